// round 2
// baseline (speedup 1.0000x reference)
#include <cuda_runtime.h>
#include <cuda_bf16.h>
#include <math.h>

// Problem constants
#define BB   2048
#define DD   256
#define HH   266
#define HP   272      // padded scratch stride for H
#define SS   50
#define EPSBN 1e-5f
#define SIGMA_C 0.3f

// ---------------- device scratch (no allocation allowed) ----------------
__device__ float g_X[BB * DD];       // current state x
__device__ float g_Y1[BB * HP];      // layer-1 pre-BN activations
__device__ float g_Y2[BB * HP];      // layer-2 pre-BN activations
__device__ float g_GRAD[BB * DD];    // layer-3 output (grad)
__device__ float g_Yv3[BB];          // v0 last-layer pre-BN
__device__ float g_S1[288];          // colsum  layer1
__device__ float g_Q1[288];          // colsumsq layer1
__device__ float g_S2[288];
__device__ float g_Q2[288];
__device__ float g_SC[4];            // v0 last layer (1 col)
__device__ float g_QC[4];

// ---------------- kernels ----------------

__global__ void init_zero_kernel(float* s1, float* q1, float* s2, float* q2,
                                 float* sc, float* qc) {
    int t = threadIdx.x;
    for (int j = t; j < 288; j += 256) { s1[j] = 0.f; q1[j] = 0.f; s2[j] = 0.f; q2[j] = 0.f; }
    if (t < 4) { sc[t] = 0.f; qc[t] = 0.f; }
}

// C[B x N] = act(A)[B x K] @ W[K x N] + bias ; optional BN+ReLU applied to A on load,
// optional column sum/sumsq accumulation of C.
template<bool BN_IN, bool STATS>
__global__ __launch_bounds__(256)
void gemm_bn(const float* __restrict__ A, int lda, int K,
             const float* __restrict__ W, int ldw, int N,
             const float* __restrict__ bias,
             const float* __restrict__ bng, const float* __restrict__ bnb,
             const float* __restrict__ ssum, const float* __restrict__ ssq,
             float* __restrict__ C, int ldc,
             float* __restrict__ osum, float* __restrict__ osq,
             float invB)
{
    __shared__ float As[16][64];
    __shared__ float Ws[16][64];
    __shared__ float scK[288];
    __shared__ float shK[288];

    const int tid = threadIdx.x;
    const int tr = tid >> 4;       // 0..15 row group
    const int tc = tid & 15;       // 0..15 col group
    const int rowBase = blockIdx.y * 64;
    const int colBase = blockIdx.x * 64;

    if (BN_IN) {
        for (int k = tid; k < K; k += 256) {
            float mu  = ssum[k] * invB;
            float var = ssq[k] * invB - mu * mu;
            float rstd = rsqrtf(var + EPSBN);
            float sc = bng[k] * rstd;
            scK[k] = sc;
            shK[k] = bnb[k] - mu * sc;
        }
        __syncthreads();
    }

    float acc[4][4] = {};
    const int nkt = (K + 15) >> 4;
    for (int kt = 0; kt < nkt; kt++) {
        int k0 = kt << 4;
        #pragma unroll
        for (int t = 0; t < 4; t++) {
            int idx = tid + t * 256;
            int wk = idx >> 6, wn = idx & 63;
            int gk = k0 + wk, gn = colBase + wn;
            Ws[wk][wn] = (gk < K && gn < N) ? W[(size_t)gk * ldw + gn] : 0.f;
        }
        #pragma unroll
        for (int t = 0; t < 4; t++) {
            int idx = tid + t * 256;
            int ak = idx >> 6, ar = idx & 63;
            int gk = k0 + ak;
            float v = 0.f;
            if (gk < K) {
                v = A[(size_t)(rowBase + ar) * lda + gk];
                if (BN_IN) v = fmaxf(fmaf(v, scK[gk], shK[gk]), 0.f);
            }
            As[ak][ar] = v;
        }
        __syncthreads();
        #pragma unroll
        for (int k = 0; k < 16; k++) {
            float ra[4], rb[4];
            #pragma unroll
            for (int m = 0; m < 4; m++) ra[m] = As[k][tr * 4 + m];
            #pragma unroll
            for (int n = 0; n < 4; n++) rb[n] = Ws[k][tc * 4 + n];
            #pragma unroll
            for (int m = 0; m < 4; m++)
                #pragma unroll
                for (int n = 0; n < 4; n++)
                    acc[m][n] = fmaf(ra[m], rb[n], acc[m][n]);
        }
        __syncthreads();
    }

    // epilogue: bias add, store, per-column partial stats
    float colS[4] = {}, colQ[4] = {};
    #pragma unroll
    for (int n = 0; n < 4; n++) {
        int gn = colBase + tc * 4 + n;
        if (gn < N) {
            float bv = bias[gn];
            #pragma unroll
            for (int m = 0; m < 4; m++) {
                float v = acc[m][n] + bv;
                C[(size_t)(rowBase + tr * 4 + m) * ldc + gn] = v;
                colS[n] += v;
                colQ[n] += v * v;
            }
        }
    }

    if (STATS) {
        // reduce 16 row groups -> 1 per column, then one atomic per column
        #pragma unroll
        for (int n = 0; n < 4; n++) As[tr][tc * 4 + n] = colS[n];
        __syncthreads();
        if (tid < 64) {
            float s = 0.f;
            #pragma unroll
            for (int j = 0; j < 16; j++) s += As[j][tid];
            int gn = colBase + tid;
            if (gn < N) atomicAdd(&osum[gn], s);
        }
        __syncthreads();
        #pragma unroll
        for (int n = 0; n < 4; n++) As[tr][tc * 4 + n] = colQ[n];
        __syncthreads();
        if (tid < 64) {
            float s = 0.f;
            #pragma unroll
            for (int j = 0; j < 16; j++) s += As[j][tid];
            int gn = colBase + tid;
            if (gn < N) atomicAdd(&osq[gn], s);
        }
    }
}

// Finalize v0 network, initialize state x, zero step stats.
__global__ __launch_bounds__(256)
void v0_final_kernel(const float* __restrict__ x_in, float* __restrict__ X,
                     const float* __restrict__ Yv3,
                     const float* __restrict__ sc, const float* __restrict__ qc,
                     const float* __restrict__ gv3, const float* __restrict__ bev3,
                     float* __restrict__ V,
                     float* z1, float* z2, float* z3, float* z4)
{
    int r = blockIdx.x, d = threadIdx.x;
    X[(size_t)r * DD + d] = x_in[(size_t)r * DD + d];
    if (d == 0) {
        float invB = 1.f / (float)BB;
        float mu  = sc[0] * invB;
        float var = qc[0] * invB - mu * mu;
        float rstd = rsqrtf(var + EPSBN);
        V[r] = fmaxf(gv3[0] * (Yv3[r] - mu) * rstd + bev3[0], 0.f);
    }
    if (r < 4) {
        float* arr = (r == 0) ? z1 : (r == 1) ? z2 : (r == 2) ? z3 : z4;
        for (int j = d; j < 288; j += 256) arr[j] = 0.f;
    }
}

__inline__ __device__ float warp_sum(float v) {
    #pragma unroll
    for (int o = 16; o > 0; o >>= 1) v += __shfl_down_sync(0xffffffffu, v, o);
    return v;
}

// Per-step state/value update + stats re-zero for next step.
__global__ __launch_bounds__(256)
void update_kernel(int i, float* __restrict__ X, const float* __restrict__ GRAD,
                   const float* __restrict__ law, const float* __restrict__ dW,
                   const float* __restrict__ tg, float* __restrict__ V,
                   float* z1, float* z2, float* z3, float* z4)
{
    int r = blockIdx.x, d = threadIdx.x;
    float h = tg[i + 1] - tg[i];
    float c = SIGMA_C * sqrtf(h);

    size_t idx = (size_t)r * DD + d;
    float xv = X[idx];
    float gr = GRAD[idx];
    float lw = law[(size_t)i * DD + d];
    float nz = c * dW[((size_t)i * BB + r) * DD + d];
    float dx = xv - lw;

    X[idx] = xv - gr * h + nz;

    float p1 = dx * dx;
    float p2 = gr * gr;
    float p3 = gr * nz;

    __shared__ float s1s[8], s2s[8], s3s[8];
    float w1 = warp_sum(p1), w2 = warp_sum(p2), w3 = warp_sum(p3);
    int lane = d & 31, wid = d >> 5;
    if (lane == 0) { s1s[wid] = w1; s2s[wid] = w2; s3s[wid] = w3; }
    __syncthreads();
    if (d == 0) {
        float s1 = 0.f, s2 = 0.f, s3 = 0.f;
        #pragma unroll
        for (int j = 0; j < 8; j++) { s1 += s1s[j]; s2 += s2s[j]; s3 += s3s[j]; }
        float f = 0.5f * s1 + 0.5f * s2;   // KAPPA = 1
        V[r] += -f * h + s3;
    }
    if (r < 4) {
        float* arr = (r == 0) ? z1 : (r == 1) ? z2 : (r == 2) ? z3 : z4;
        for (int j = d; j < 288; j += 256) arr[j] = 0.f;
    }
}

// ---------------- host launcher ----------------
extern "C" void kernel_launch(void* const* d_in, const int* in_sizes, int n_in,
                              void* d_out, int out_size)
{
    const float* x    = (const float*)d_in[0];
    const float* dW   = (const float*)d_in[1];
    const float* law  = (const float*)d_in[2];
    const float* tg   = (const float*)d_in[3];
    const float* W1   = (const float*)d_in[4];
    const float* b1   = (const float*)d_in[5];
    const float* g1   = (const float*)d_in[6];
    const float* be1  = (const float*)d_in[7];
    const float* W2   = (const float*)d_in[8];
    const float* b2   = (const float*)d_in[9];
    const float* g2   = (const float*)d_in[10];
    const float* be2  = (const float*)d_in[11];
    const float* W3   = (const float*)d_in[12];
    const float* b3   = (const float*)d_in[13];
    const float* Wv1  = (const float*)d_in[14];
    const float* bv1  = (const float*)d_in[15];
    const float* gv1  = (const float*)d_in[16];
    const float* bev1 = (const float*)d_in[17];
    const float* Wv2  = (const float*)d_in[18];
    const float* bv2  = (const float*)d_in[19];
    const float* gv2  = (const float*)d_in[20];
    const float* bev2 = (const float*)d_in[21];
    const float* Wv3  = (const float*)d_in[22];
    const float* bv3  = (const float*)d_in[23];
    const float* gv3  = (const float*)d_in[24];
    const float* bev3 = (const float*)d_in[25];

    float* V = (float*)d_out;

    float *X, *Y1, *Y2, *GRAD, *Yv3, *S1, *Q1, *S2, *Q2, *SC, *QC;
    cudaGetSymbolAddress((void**)&X,    g_X);
    cudaGetSymbolAddress((void**)&Y1,   g_Y1);
    cudaGetSymbolAddress((void**)&Y2,   g_Y2);
    cudaGetSymbolAddress((void**)&GRAD, g_GRAD);
    cudaGetSymbolAddress((void**)&Yv3,  g_Yv3);
    cudaGetSymbolAddress((void**)&S1,   g_S1);
    cudaGetSymbolAddress((void**)&Q1,   g_Q1);
    cudaGetSymbolAddress((void**)&S2,   g_S2);
    cudaGetSymbolAddress((void**)&Q2,   g_Q2);
    cudaGetSymbolAddress((void**)&SC,   g_SC);
    cudaGetSymbolAddress((void**)&QC,   g_QC);

    const float invB = 1.f / (float)BB;
    dim3 blk(256);
    dim3 gH((HH + 63) / 64, BB / 64);   // N = 266 -> 5 x 32
    dim3 gD((DD + 63) / 64, BB / 64);   // N = 256 -> 4 x 32
    dim3 g1c(1, BB / 64);               // N = 1   -> 1 x 32

    init_zero_kernel<<<1, 256>>>(S1, Q1, S2, Q2, SC, QC);

    // v0 network: x -> H -> H -> 1 (all Linear+BN+ReLU)
    gemm_bn<false, true><<<gH, blk>>>(x, DD, DD, Wv1, HH, HH, bv1,
                                      nullptr, nullptr, nullptr, nullptr,
                                      Y1, HP, S1, Q1, invB);
    gemm_bn<true, true><<<gH, blk>>>(Y1, HP, HH, Wv2, HH, HH, bv2,
                                     gv1, bev1, S1, Q1,
                                     Y2, HP, S2, Q2, invB);
    gemm_bn<true, true><<<g1c, blk>>>(Y2, HP, HH, Wv3, 1, 1, bv3,
                                      gv2, bev2, S2, Q2,
                                      Yv3, 1, SC, QC, invB);
    v0_final_kernel<<<BB, 256>>>(x, X, Yv3, SC, QC, gv3, bev3, V, S1, Q1, S2, Q2);

    for (int i = 0; i < SS; i++) {
        const float* w1i = W1 + (size_t)i * DD * HH;
        const float* w2i = W2 + (size_t)i * HH * HH;
        const float* w3i = W3 + (size_t)i * HH * DD;
        gemm_bn<false, true><<<gH, blk>>>(X, DD, DD, w1i, HH, HH, b1 + (size_t)i * HH,
                                          nullptr, nullptr, nullptr, nullptr,
                                          Y1, HP, S1, Q1, invB);
        gemm_bn<true, true><<<gH, blk>>>(Y1, HP, HH, w2i, HH, HH, b2 + (size_t)i * HH,
                                         g1 + (size_t)i * HH, be1 + (size_t)i * HH, S1, Q1,
                                         Y2, HP, S2, Q2, invB);
        gemm_bn<true, false><<<gD, blk>>>(Y2, HP, HH, w3i, DD, DD, b3 + (size_t)i * DD,
                                          g2 + (size_t)i * HH, be2 + (size_t)i * HH, S2, Q2,
                                          GRAD, DD, nullptr, nullptr, invB);
        update_kernel<<<BB, 256>>>(i, X, GRAD, law, dW, tg, V, S1, Q1, S2, Q2);
    }
    (void)in_sizes; (void)n_in; (void)out_size;
}

// round 3
// speedup vs baseline: 1.0975x; 1.0975x over previous
#include <cuda_runtime.h>
#include <cuda_bf16.h>
#include <math.h>

// Problem constants
#define BB   2048
#define DD   256
#define HH   266
#define HP   272      // padded scratch stride for H
#define SS   50
#define EPSBN 1e-5f
#define SIGMA_C 0.3f
#define KT   24       // K-tile

// ---------------- device scratch (no allocation allowed) ----------------
__device__ float g_X[BB * DD + 64];  // current state x (padded for float4 reads)
__device__ float g_Y1[BB * HP];      // layer-1 pre-BN activations
__device__ float g_Y2[BB * HP];      // layer-2 pre-BN activations
__device__ float g_GRAD[BB * DD];    // layer-3 output (grad)
__device__ float g_Yv3[BB];          // v0 last-layer pre-BN
__device__ float g_S1[288];
__device__ float g_Q1[288];
__device__ float g_S2[288];
__device__ float g_Q2[288];
__device__ float g_SC[4];
__device__ float g_QC[4];

// packed fp32x2 FMA: d = a*b + d  (2 MACs / instruction, full fp32)
__device__ __forceinline__ void ffma2(unsigned long long& d,
                                      unsigned long long a,
                                      unsigned long long b) {
    asm("fma.rn.f32x2 %0, %1, %2, %0;" : "+l"(d) : "l"(a), "l"(b));
}
__device__ __forceinline__ float f2lo(unsigned long long u) {
    return __uint_as_float((unsigned int)(u & 0xffffffffull));
}
__device__ __forceinline__ float f2hi(unsigned long long u) {
    return __uint_as_float((unsigned int)(u >> 32));
}

// ---------------- kernels ----------------

__global__ void init_zero_kernel(float* s1, float* q1, float* s2, float* q2,
                                 float* sc, float* qc) {
    int t = threadIdx.x;
    for (int j = t; j < 288; j += 256) { s1[j] = 0.f; q1[j] = 0.f; s2[j] = 0.f; q2[j] = 0.f; }
    if (t < 4) { sc[t] = 0.f; qc[t] = 0.f; }
}

// C[B x N] = act(A)[B x K] @ W[K x N] + bias ; optional BN+ReLU applied to A on load,
// optional column sum/sumsq accumulation of C.
// 1-D grid: bx -> colblock = bx>>5 (thin edge block last), rowblock = bx&31.
template<bool BN_IN, bool STATS>
__global__ __launch_bounds__(256, 1)
void gemm_bn(const float* __restrict__ A, int lda, int K,
             const float* __restrict__ W, int ldw, int N,
             const float* __restrict__ bias,
             const float* __restrict__ bng, const float* __restrict__ bnb,
             const float* __restrict__ ssum, const float* __restrict__ ssq,
             float* __restrict__ C, int ldc,
             float* __restrict__ osum, float* __restrict__ osq,
             float invB)
{
    __shared__ float As2[2][KT][128];   // A tile, transposed + duplicated: [k][2r],[k][2r+1]
    __shared__ float Ws4[2][KT][64];    // W tile
    __shared__ float scK[288];
    __shared__ float shK[288];

    const int tid = threadIdx.x;
    const int tr = tid >> 4;       // 0..15 row group (4 rows)
    const int tc = tid & 15;       // 0..15 col group (4 cols)
    const int rowBase = (blockIdx.x & 31) * 64;
    const int colBase = (blockIdx.x >> 5) * 64;

    if (BN_IN) {
        for (int k = tid; k < 288; k += 256) {
            if (k < K) {
                float mu  = ssum[k] * invB;
                float var = ssq[k] * invB - mu * mu;
                float rstd = rsqrtf(var + EPSBN);
                float sc = bng[k] * rstd;
                scK[k] = sc;
                shK[k] = bnb[k] - mu * sc;
            } else { scK[k] = 0.f; shK[k] = 0.f; }
        }
    }

    // register-staged loaders (each thread: up to 2 float4 of A, 2 float4 of W)
    float4 aR[2]; int aRow[2], aK[2];
    float4 wR[2]; int wK[2], wN4[2];
    const int nkt = (K + KT - 1) / KT;

    auto ldA = [&](int kbase) {
        #pragma unroll
        for (int s = 0; s < 2; s++) {
            int idx = tid + s * 256;
            if (idx < 384) {
                int kq = idx >> 6, r = idx & 63;
                int gk = kbase + kq * 4;
                aK[s] = gk; aRow[s] = r;
                float4 v = make_float4(0.f, 0.f, 0.f, 0.f);
                if (gk < K) {
                    v = *(const float4*)(A + (size_t)(rowBase + r) * lda + gk);
                    if (gk + 1 >= K) v.y = 0.f;
                    if (gk + 2 >= K) v.z = 0.f;
                    if (gk + 3 >= K) v.w = 0.f;
                }
                aR[s] = v;
            }
        }
    };
    auto stA = [&](int buf) {
        #pragma unroll
        for (int s = 0; s < 2; s++) {
            int idx = tid + s * 256;
            if (idx < 384) {
                float4 v = aR[s];
                int gk = aK[s];
                if (BN_IN) {
                    v.x = fmaxf(fmaf(v.x, scK[gk],     shK[gk]),     0.f);
                    v.y = fmaxf(fmaf(v.y, scK[gk + 1], shK[gk + 1]), 0.f);
                    v.z = fmaxf(fmaf(v.z, scK[gk + 2], shK[gk + 2]), 0.f);
                    v.w = fmaxf(fmaf(v.w, scK[gk + 3], shK[gk + 3]), 0.f);
                }
                int k0 = gk % KT;  // = gk - kbase
                int r2 = aRow[s] * 2;
                *(float2*)&As2[buf][k0    ][r2] = make_float2(v.x, v.x);
                *(float2*)&As2[buf][k0 + 1][r2] = make_float2(v.y, v.y);
                *(float2*)&As2[buf][k0 + 2][r2] = make_float2(v.z, v.z);
                *(float2*)&As2[buf][k0 + 3][r2] = make_float2(v.w, v.w);
            }
        }
    };
    auto ldW = [&](int kbase) {
        #pragma unroll
        for (int s = 0; s < 2; s++) {
            int idx = tid + s * 256;
            if (idx < 384) {
                int krow = idx >> 4;
                int n4 = (idx & 15) << 2;
                int gk = kbase + krow, gn = colBase + n4;
                wK[s] = krow; wN4[s] = n4;
                float4 w = make_float4(0.f, 0.f, 0.f, 0.f);
                if (gk < K) {
                    const float* wr = W + (size_t)gk * ldw + gn;
                    if (gn     < N) w.x = wr[0];
                    if (gn + 1 < N) w.y = wr[1];
                    if (gn + 2 < N) w.z = wr[2];
                    if (gn + 3 < N) w.w = wr[3];
                }
                wR[s] = w;
            }
        }
    };
    auto stW = [&](int buf) {
        #pragma unroll
        for (int s = 0; s < 2; s++) {
            int idx = tid + s * 256;
            if (idx < 384) *(float4*)&Ws4[buf][wK[s]][wN4[s]] = wR[s];
        }
    };

    unsigned long long acc[4][2] = {};
    auto comp = [&](int buf) {
        #pragma unroll 8
        for (int k = 0; k < KT; k++) {
            const ulonglong2* aP = (const ulonglong2*)&As2[buf][k][tr * 8];
            ulonglong2 a01 = aP[0];   // {a0,a0},{a1,a1}
            ulonglong2 a23 = aP[1];   // {a2,a2},{a3,a3}
            ulonglong2 b = *(const ulonglong2*)&Ws4[buf][k][tc * 4]; // {b0,b1},{b2,b3}
            ffma2(acc[0][0], a01.x, b.x); ffma2(acc[0][1], a01.x, b.y);
            ffma2(acc[1][0], a01.y, b.x); ffma2(acc[1][1], a01.y, b.y);
            ffma2(acc[2][0], a23.x, b.x); ffma2(acc[2][1], a23.x, b.y);
            ffma2(acc[3][0], a23.y, b.x); ffma2(acc[3][1], a23.y, b.y);
        }
    };

    // prologue
    ldA(0); ldW(0);
    if (BN_IN) __syncthreads();   // scK/shK ready before BN-applying stores
    stA(0); stW(0);
    __syncthreads();

    for (int kt = 0; kt < nkt; kt++) {
        int buf = kt & 1;
        if (kt + 1 < nkt) { ldA((kt + 1) * KT); ldW((kt + 1) * KT); }
        comp(buf);
        if (kt + 1 < nkt) { stA(buf ^ 1); stW(buf ^ 1); }
        __syncthreads();
    }

    // epilogue: bias add, store, per-column partial stats
    float vals[4][4];
    #pragma unroll
    for (int m = 0; m < 4; m++) {
        vals[m][0] = f2lo(acc[m][0]); vals[m][1] = f2hi(acc[m][0]);
        vals[m][2] = f2lo(acc[m][1]); vals[m][3] = f2hi(acc[m][1]);
    }
    float colS[4] = {}, colQ[4] = {};
    #pragma unroll
    for (int n = 0; n < 4; n++) {
        int gn = colBase + tc * 4 + n;
        if (gn < N) {
            float bv = bias[gn];
            #pragma unroll
            for (int m = 0; m < 4; m++) {
                float v = vals[m][n] + bv;
                C[(size_t)(rowBase + tr * 4 + m) * ldc + gn] = v;
                colS[n] += v;
                colQ[n] += v * v;
            }
        }
    }

    if (STATS) {
        float (*red)[64] = (float (*)[64])As2;   // reuse smem (post final barrier)
        #pragma unroll
        for (int n = 0; n < 4; n++) red[tr][tc * 4 + n] = colS[n];
        __syncthreads();
        if (tid < 64) {
            float s = 0.f;
            #pragma unroll
            for (int j = 0; j < 16; j++) s += red[j][tid];
            int gn = colBase + tid;
            if (gn < N) atomicAdd(&osum[gn], s);
        }
        __syncthreads();
        #pragma unroll
        for (int n = 0; n < 4; n++) red[tr][tc * 4 + n] = colQ[n];
        __syncthreads();
        if (tid < 64) {
            float s = 0.f;
            #pragma unroll
            for (int j = 0; j < 16; j++) s += red[j][tid];
            int gn = colBase + tid;
            if (gn < N) atomicAdd(&osq[gn], s);
        }
    }
}

// Finalize v0 network, initialize state x, zero step stats.
__global__ __launch_bounds__(256)
void v0_final_kernel(const float* __restrict__ x_in, float* __restrict__ X,
                     const float* __restrict__ Yv3,
                     const float* __restrict__ sc, const float* __restrict__ qc,
                     const float* __restrict__ gv3, const float* __restrict__ bev3,
                     float* __restrict__ V,
                     float* z1, float* z2, float* z3, float* z4)
{
    int r = blockIdx.x, d = threadIdx.x;
    X[(size_t)r * DD + d] = x_in[(size_t)r * DD + d];
    if (d == 0) {
        float invB = 1.f / (float)BB;
        float mu  = sc[0] * invB;
        float var = qc[0] * invB - mu * mu;
        float rstd = rsqrtf(var + EPSBN);
        V[r] = fmaxf(gv3[0] * (Yv3[r] - mu) * rstd + bev3[0], 0.f);
    }
    if (r < 4) {
        float* arr = (r == 0) ? z1 : (r == 1) ? z2 : (r == 2) ? z3 : z4;
        for (int j = d; j < 288; j += 256) arr[j] = 0.f;
    }
}

__inline__ __device__ float warp_sum(float v) {
    #pragma unroll
    for (int o = 16; o > 0; o >>= 1) v += __shfl_down_sync(0xffffffffu, v, o);
    return v;
}

// Per-step state/value update + stats re-zero for next step.
__global__ __launch_bounds__(256)
void update_kernel(int i, float* __restrict__ X, const float* __restrict__ GRAD,
                   const float* __restrict__ law, const float* __restrict__ dW,
                   const float* __restrict__ tg, float* __restrict__ V,
                   float* z1, float* z2, float* z3, float* z4)
{
    int r = blockIdx.x, d = threadIdx.x;
    float h = tg[i + 1] - tg[i];
    float c = SIGMA_C * sqrtf(h);

    size_t idx = (size_t)r * DD + d;
    float xv = X[idx];
    float gr = GRAD[idx];
    float lw = law[(size_t)i * DD + d];
    float nz = c * dW[((size_t)i * BB + r) * DD + d];
    float dx = xv - lw;

    X[idx] = xv - gr * h + nz;

    float p1 = dx * dx;
    float p2 = gr * gr;
    float p3 = gr * nz;

    __shared__ float s1s[8], s2s[8], s3s[8];
    float w1 = warp_sum(p1), w2 = warp_sum(p2), w3 = warp_sum(p3);
    int lane = d & 31, wid = d >> 5;
    if (lane == 0) { s1s[wid] = w1; s2s[wid] = w2; s3s[wid] = w3; }
    __syncthreads();
    if (d == 0) {
        float s1 = 0.f, s2 = 0.f, s3 = 0.f;
        #pragma unroll
        for (int j = 0; j < 8; j++) { s1 += s1s[j]; s2 += s2s[j]; s3 += s3s[j]; }
        float f = 0.5f * s1 + 0.5f * s2;   // KAPPA = 1
        V[r] += -f * h + s3;
    }
    if (r < 4) {
        float* arr = (r == 0) ? z1 : (r == 1) ? z2 : (r == 2) ? z3 : z4;
        for (int j = d; j < 288; j += 256) arr[j] = 0.f;
    }
}

// ---------------- host launcher ----------------
extern "C" void kernel_launch(void* const* d_in, const int* in_sizes, int n_in,
                              void* d_out, int out_size)
{
    const float* x    = (const float*)d_in[0];
    const float* dW   = (const float*)d_in[1];
    const float* law  = (const float*)d_in[2];
    const float* tg   = (const float*)d_in[3];
    const float* W1   = (const float*)d_in[4];
    const float* b1   = (const float*)d_in[5];
    const float* g1   = (const float*)d_in[6];
    const float* be1  = (const float*)d_in[7];
    const float* W2   = (const float*)d_in[8];
    const float* b2   = (const float*)d_in[9];
    const float* g2   = (const float*)d_in[10];
    const float* be2  = (const float*)d_in[11];
    const float* W3   = (const float*)d_in[12];
    const float* b3   = (const float*)d_in[13];
    const float* Wv1  = (const float*)d_in[14];
    const float* bv1  = (const float*)d_in[15];
    const float* gv1  = (const float*)d_in[16];
    const float* bev1 = (const float*)d_in[17];
    const float* Wv2  = (const float*)d_in[18];
    const float* bv2  = (const float*)d_in[19];
    const float* gv2  = (const float*)d_in[20];
    const float* bev2 = (const float*)d_in[21];
    const float* Wv3  = (const float*)d_in[22];
    const float* bv3  = (const float*)d_in[23];
    const float* gv3  = (const float*)d_in[24];
    const float* bev3 = (const float*)d_in[25];

    float* V = (float*)d_out;

    float *X, *Y1, *Y2, *GRAD, *Yv3, *S1, *Q1, *S2, *Q2, *SC, *QC;
    cudaGetSymbolAddress((void**)&X,    g_X);
    cudaGetSymbolAddress((void**)&Y1,   g_Y1);
    cudaGetSymbolAddress((void**)&Y2,   g_Y2);
    cudaGetSymbolAddress((void**)&GRAD, g_GRAD);
    cudaGetSymbolAddress((void**)&Yv3,  g_Yv3);
    cudaGetSymbolAddress((void**)&S1,   g_S1);
    cudaGetSymbolAddress((void**)&Q1,   g_Q1);
    cudaGetSymbolAddress((void**)&S2,   g_S2);
    cudaGetSymbolAddress((void**)&Q2,   g_Q2);
    cudaGetSymbolAddress((void**)&SC,   g_SC);
    cudaGetSymbolAddress((void**)&QC,   g_QC);

    const float invB = 1.f / (float)BB;
    dim3 blk(256);
    dim3 gH(5 * 32);   // N=266: 4 full col-blocks + thin block last; 32 row-blocks
    dim3 gD(4 * 32);   // N=256: exactly 128 CTAs = one wave
    dim3 g1c(1 * 32);  // N=1

    init_zero_kernel<<<1, 256>>>(S1, Q1, S2, Q2, SC, QC);

    // v0 network: x -> H -> H -> 1 (all Linear+BN+ReLU)
    gemm_bn<false, true><<<gH, blk>>>(x, DD, DD, Wv1, HH, HH, bv1,
                                      nullptr, nullptr, nullptr, nullptr,
                                      Y1, HP, S1, Q1, invB);
    gemm_bn<true, true><<<gH, blk>>>(Y1, HP, HH, Wv2, HH, HH, bv2,
                                     gv1, bev1, S1, Q1,
                                     Y2, HP, S2, Q2, invB);
    gemm_bn<true, true><<<g1c, blk>>>(Y2, HP, HH, Wv3, 1, 1, bv3,
                                      gv2, bev2, S2, Q2,
                                      Yv3, 1, SC, QC, invB);
    v0_final_kernel<<<BB, 256>>>(x, X, Yv3, SC, QC, gv3, bev3, V, S1, Q1, S2, Q2);

    for (int i = 0; i < SS; i++) {
        const float* w1i = W1 + (size_t)i * DD * HH;
        const float* w2i = W2 + (size_t)i * HH * HH;
        const float* w3i = W3 + (size_t)i * HH * DD;
        gemm_bn<false, true><<<gH, blk>>>(X, DD, DD, w1i, HH, HH, b1 + (size_t)i * HH,
                                          nullptr, nullptr, nullptr, nullptr,
                                          Y1, HP, S1, Q1, invB);
        gemm_bn<true, true><<<gH, blk>>>(Y1, HP, HH, w2i, HH, HH, b2 + (size_t)i * HH,
                                         g1 + (size_t)i * HH, be1 + (size_t)i * HH, S1, Q1,
                                         Y2, HP, S2, Q2, invB);
        gemm_bn<true, false><<<gD, blk>>>(Y2, HP, HH, w3i, DD, DD, b3 + (size_t)i * DD,
                                          g2 + (size_t)i * HH, be2 + (size_t)i * HH, S2, Q2,
                                          GRAD, DD, nullptr, nullptr, invB);
        update_kernel<<<BB, 256>>>(i, X, GRAD, law, dW, tg, V, S1, Q1, S2, Q2);
    }
    (void)in_sizes; (void)n_in; (void)out_size;
}

// round 4
// speedup vs baseline: 1.4704x; 1.3398x over previous
#include <cuda_runtime.h>
#include <math.h>

#define NCTA 148
#define BB   2048
#define DD   256
#define HH   266
#define HP   272
#define SS   50
#define EPSBN 1e-5f
#define SIGMA_C 0.3f
#define KT   24

// ---------------- device scratch ----------------
__device__ float g_X[BB * DD];
__device__ float g_Y1[BB * HP];
__device__ float g_Y2[BB * HP];
__device__ float g_Yv3[BB];
__device__ float g_S1[288], g_Q1[288], g_S2[288], g_Q2[288];
__device__ float g_SC[4], g_QC[4];
__device__ unsigned g_barctr;
__device__ unsigned g_done;

// packed fp32x2 FMA
__device__ __forceinline__ void ffma2(unsigned long long& d,
                                      unsigned long long a,
                                      unsigned long long b) {
    asm("fma.rn.f32x2 %0, %1, %2, %0;" : "+l"(d) : "l"(a), "l"(b));
}
__device__ __forceinline__ unsigned long long pack2(float x, float y) {
    unsigned long long r;
    asm("mov.b64 %0, {%1, %2};" : "=l"(r) : "f"(x), "f"(y));
    return r;
}
__device__ __forceinline__ float f2lo(unsigned long long u) {
    return __uint_as_float((unsigned int)(u & 0xffffffffull));
}
__device__ __forceinline__ float f2hi(unsigned long long u) {
    return __uint_as_float((unsigned int)(u >> 32));
}

struct SMT {
    float As2[2][KT][128];   // full: A duplicated {a,a}; thin: plain A[ k ][128]
    float Ws4[2][KT][64];    // full: W tile;            thin: W[KT][16] overlay
    float scK[288];
    float shK[288];
};

// ---------------- grid barrier ----------------
__device__ __forceinline__ void gridbar(unsigned& cnt) {
    __syncthreads();
    if (threadIdx.x == 0) {
        __threadfence();
        atomicAdd(&g_barctr, 1u);
        unsigned target = (++cnt) * NCTA;
        while (*(volatile unsigned*)&g_barctr < target) __nanosleep(64);
        __threadfence();   // CCTL.IVALL: invalidate L1 so fresh data is read
    }
    __syncthreads();
}

// ---------------- full 64x64 GEMM phase ----------------
// C[64x64] = act(A)[64xK] @ W[KxN-slice] + bias (optionally BN+ReLU on A load)
// F1:   (colBase==0) accumulate sum_k (A - law)^2 per row -> V -= 0.5*h*sum
// XUPD: epilogue computes grad, updates X in place, accumulates
//       V += -0.5*h*sum(grad^2) + sum(grad*noise)
template<bool BN_IN, bool STATS, bool F1, bool XUPD, bool WRC>
__device__ void gemm_full(SMT& sm, int rowBase, int colBase,
    const float* __restrict__ A, int lda, int K,
    const float* __restrict__ W, int ldw, int N,
    const float* __restrict__ bias,
    const float* __restrict__ bng, const float* __restrict__ bnb,
    const float* __restrict__ ssum, const float* __restrict__ ssq,
    float* __restrict__ C, int ldc,
    float* __restrict__ osum, float* __restrict__ osq,
    const float* __restrict__ law, float hstep, float cstep,
    float* __restrict__ V, float* __restrict__ X, const float* __restrict__ dWi)
{
    const int tid = threadIdx.x;
    const int tr = tid >> 4;
    const int tc = tid & 15;
    const float invB = 1.f / (float)BB;

    if (BN_IN) {
        for (int k = tid; k < 288; k += 256) {
            if (k < K) {
                float mu  = ssum[k] * invB;
                float var = ssq[k] * invB - mu * mu;
                float rstd = rsqrtf(var + EPSBN);
                float sc = bng[k] * rstd;
                sm.scK[k] = sc;
                sm.shK[k] = bnb[k] - mu * sc;
            } else { sm.scK[k] = 0.f; sm.shK[k] = 0.f; }
        }
    }

    float4 aR[2]; int aK[2];
    float4 wR[2]; int wK[2], wN4[2];
    const int aRow = tid & 63;
    float facc = 0.f;
    const int nkt = (K + KT - 1) / KT;

    auto ldA = [&](int kbase) {
        #pragma unroll
        for (int s = 0; s < 2; s++) {
            int idx = tid + s * 256;
            if (idx < 384) {
                int kq = idx >> 6;
                int gk = kbase + kq * 4;
                aK[s] = gk;
                float4 v = make_float4(0.f, 0.f, 0.f, 0.f);
                if (gk < K) {
                    v = *(const float4*)(A + (size_t)(rowBase + aRow) * lda + gk);
                    if (gk + 1 >= K) v.y = 0.f;
                    if (gk + 2 >= K) v.z = 0.f;
                    if (gk + 3 >= K) v.w = 0.f;
                    if (F1 && colBase == 0) {
                        float d0 = v.x - law[gk]; facc += d0 * d0;
                        if (gk + 1 < K) { float d = v.y - law[gk + 1]; facc += d * d; }
                        if (gk + 2 < K) { float d = v.z - law[gk + 2]; facc += d * d; }
                        if (gk + 3 < K) { float d = v.w - law[gk + 3]; facc += d * d; }
                    }
                }
                aR[s] = v;
            }
        }
    };
    auto stA = [&](int buf) {
        #pragma unroll
        for (int s = 0; s < 2; s++) {
            int idx = tid + s * 256;
            if (idx < 384) {
                int kq = idx >> 6;
                float4 v = aR[s];
                int gk = aK[s];
                if (BN_IN) {
                    v.x = fmaxf(fmaf(v.x, sm.scK[gk],     sm.shK[gk]),     0.f);
                    v.y = fmaxf(fmaf(v.y, sm.scK[gk + 1], sm.shK[gk + 1]), 0.f);
                    v.z = fmaxf(fmaf(v.z, sm.scK[gk + 2], sm.shK[gk + 2]), 0.f);
                    v.w = fmaxf(fmaf(v.w, sm.scK[gk + 3], sm.shK[gk + 3]), 0.f);
                }
                int k0 = kq * 4;
                int r2 = aRow * 2;
                *(float2*)&sm.As2[buf][k0    ][r2] = make_float2(v.x, v.x);
                *(float2*)&sm.As2[buf][k0 + 1][r2] = make_float2(v.y, v.y);
                *(float2*)&sm.As2[buf][k0 + 2][r2] = make_float2(v.z, v.z);
                *(float2*)&sm.As2[buf][k0 + 3][r2] = make_float2(v.w, v.w);
            }
        }
    };
    auto ldW = [&](int kbase) {
        #pragma unroll
        for (int s = 0; s < 2; s++) {
            int idx = tid + s * 256;
            if (idx < 384) {
                int krow = idx >> 4;
                int n4 = (idx & 15) << 2;
                int gk = kbase + krow, gn = colBase + n4;
                wK[s] = krow; wN4[s] = n4;
                float4 w = make_float4(0.f, 0.f, 0.f, 0.f);
                if (gk < K) {
                    const float* wr = W + (size_t)gk * ldw + gn;
                    if (gn     < N) w.x = wr[0];
                    if (gn + 1 < N) w.y = wr[1];
                    if (gn + 2 < N) w.z = wr[2];
                    if (gn + 3 < N) w.w = wr[3];
                }
                wR[s] = w;
            }
        }
    };
    auto stW = [&](int buf) {
        #pragma unroll
        for (int s = 0; s < 2; s++) {
            int idx = tid + s * 256;
            if (idx < 384) *(float4*)&sm.Ws4[buf][wK[s]][wN4[s]] = wR[s];
        }
    };

    unsigned long long acc[4][2] = {};
    auto comp = [&](int buf) {
        #pragma unroll 8
        for (int k = 0; k < KT; k++) {
            const ulonglong2* aP = (const ulonglong2*)&sm.As2[buf][k][tr * 8];
            ulonglong2 a01 = aP[0];
            ulonglong2 a23 = aP[1];
            ulonglong2 b = *(const ulonglong2*)&sm.Ws4[buf][k][tc * 4];
            ffma2(acc[0][0], a01.x, b.x); ffma2(acc[0][1], a01.x, b.y);
            ffma2(acc[1][0], a01.y, b.x); ffma2(acc[1][1], a01.y, b.y);
            ffma2(acc[2][0], a23.x, b.x); ffma2(acc[2][1], a23.x, b.y);
            ffma2(acc[3][0], a23.y, b.x); ffma2(acc[3][1], a23.y, b.y);
        }
    };

    ldA(0); ldW(0);
    if (BN_IN) __syncthreads();
    stA(0); stW(0);
    __syncthreads();
    for (int kt = 0; kt < nkt; kt++) {
        int buf = kt & 1;
        if (kt + 1 < nkt) { ldA((kt + 1) * KT); ldW((kt + 1) * KT); }
        comp(buf);
        if (kt + 1 < nkt) { stA(buf ^ 1); stW(buf ^ 1); }
        __syncthreads();
    }

    float vals[4][4];
    #pragma unroll
    for (int m = 0; m < 4; m++) {
        vals[m][0] = f2lo(acc[m][0]); vals[m][1] = f2hi(acc[m][0]);
        vals[m][2] = f2lo(acc[m][1]); vals[m][3] = f2hi(acc[m][1]);
    }

    float (*red)[64] = (float (*)[64])sm.As2;

    if (WRC) {
        float colS[4] = {}, colQ[4] = {};
        #pragma unroll
        for (int n = 0; n < 4; n++) {
            int gn = colBase + tc * 4 + n;
            if (gn < N) {
                float bv = bias[gn];
                #pragma unroll
                for (int m = 0; m < 4; m++) {
                    float v = vals[m][n] + bv;
                    C[(size_t)(rowBase + tr * 4 + m) * ldc + gn] = v;
                    colS[n] += v;
                    colQ[n] += v * v;
                }
            }
        }
        if (STATS) {
            #pragma unroll
            for (int n = 0; n < 4; n++) red[tr][tc * 4 + n] = colS[n];
            __syncthreads();
            if (tid < 64) {
                float s = 0.f;
                #pragma unroll
                for (int j = 0; j < 16; j++) s += red[j][tid];
                int gn = colBase + tid;
                if (gn < N) atomicAdd(&osum[gn], s);
            }
            __syncthreads();
            #pragma unroll
            for (int n = 0; n < 4; n++) red[tr][tc * 4 + n] = colQ[n];
            __syncthreads();
            if (tid < 64) {
                float s = 0.f;
                #pragma unroll
                for (int j = 0; j < 16; j++) s += red[j][tid];
                int gn = colBase + tid;
                if (gn < N) atomicAdd(&osq[gn], s);
            }
        }
    }

    if (XUPD) {
        float4 bj = *(const float4*)(bias + colBase + tc * 4);
        float p2[4], p3[4];
        #pragma unroll
        for (int m = 0; m < 4; m++) {
            int r = rowBase + tr * 4 + m;
            size_t off = (size_t)r * DD + colBase + tc * 4;
            float4 dw = *(const float4*)(dWi + off);
            float4 xv = *(const float4*)(X + off);
            float q0 = vals[m][0] + bj.x, q1 = vals[m][1] + bj.y;
            float q2 = vals[m][2] + bj.z, q3 = vals[m][3] + bj.w;
            float n0 = cstep * dw.x, n1 = cstep * dw.y;
            float n2 = cstep * dw.z, n3 = cstep * dw.w;
            float4 xo;
            xo.x = xv.x - q0 * hstep + n0;
            xo.y = xv.y - q1 * hstep + n1;
            xo.z = xv.z - q2 * hstep + n2;
            xo.w = xv.w - q3 * hstep + n3;
            *(float4*)(X + off) = xo;
            p2[m] = q0 * q0 + q1 * q1 + q2 * q2 + q3 * q3;
            p3[m] = q0 * n0 + q1 * n1 + q2 * n2 + q3 * n3;
        }
        __syncthreads();
        #pragma unroll
        for (int m = 0; m < 4; m++) red[tc][tr * 4 + m] = p2[m];
        __syncthreads();
        float s2 = 0.f;
        if (tid < 64) {
            #pragma unroll
            for (int j = 0; j < 16; j++) s2 += red[j][tid];
        }
        __syncthreads();
        #pragma unroll
        for (int m = 0; m < 4; m++) red[tc][tr * 4 + m] = p3[m];
        __syncthreads();
        if (tid < 64) {
            float s3 = 0.f;
            #pragma unroll
            for (int j = 0; j < 16; j++) s3 += red[j][tid];
            atomicAdd(&V[rowBase + tid], -0.5f * hstep * s2 + s3);
        }
    }

    if (F1) {
        if (colBase == 0) {
            __syncthreads();
            red[tid >> 6][aRow] = facc;
            __syncthreads();
            if (tid < 64) {
                float s = red[0][tid] + red[1][tid] + red[2][tid] + red[3][tid];
                atomicAdd(&V[rowBase + tid], -0.5f * hstep * s);
            }
        }
    }
}

// ---------------- thin 128x16 GEMM phase (H remainder cols 256..265) ----------
template<bool BN_IN>
__device__ void gemm_thin(SMT& sm, int rowBase, int colBase,
    const float* __restrict__ A, int lda, int K,
    const float* __restrict__ W, int ldw, int N,
    const float* __restrict__ bias,
    const float* __restrict__ bng, const float* __restrict__ bnb,
    const float* __restrict__ ssum, const float* __restrict__ ssq,
    float* __restrict__ C, int ldc,
    float* __restrict__ osum, float* __restrict__ osq)
{
    const int tid = threadIdx.x;
    const int tr = tid >> 3;   // 0..31 -> 4 rows each
    const int tc = tid & 7;    // 0..7  -> 2 cols each
    const float invB = 1.f / (float)BB;
    float (*tA)[KT][128] = (float (*)[KT][128])sm.As2;
    float (*tW)[KT][16]  = (float (*)[KT][16]) sm.Ws4;

    if (BN_IN) {
        for (int k = tid; k < 288; k += 256) {
            if (k < K) {
                float mu  = ssum[k] * invB;
                float var = ssq[k] * invB - mu * mu;
                float rstd = rsqrtf(var + EPSBN);
                float sc = bng[k] * rstd;
                sm.scK[k] = sc;
                sm.shK[k] = bnb[k] - mu * sc;
            } else { sm.scK[k] = 0.f; sm.shK[k] = 0.f; }
        }
    }

    float4 aR[3]; int aK[3];
    float wRv[4];
    const int nkt = (K + KT - 1) / KT;

    auto ldA = [&](int kbase) {
        #pragma unroll
        for (int s = 0; s < 3; s++) {
            int idx = tid + s * 256;
            int r = idx & 127, kq = idx >> 7;
            int gk = kbase + kq * 4;
            aK[s] = gk;
            float4 v = make_float4(0.f, 0.f, 0.f, 0.f);
            if (gk < K) {
                v = *(const float4*)(A + (size_t)(rowBase + r) * lda + gk);
                if (gk + 1 >= K) v.y = 0.f;
                if (gk + 2 >= K) v.z = 0.f;
                if (gk + 3 >= K) v.w = 0.f;
            }
            aR[s] = v;
        }
    };
    auto stA = [&](int buf) {
        #pragma unroll
        for (int s = 0; s < 3; s++) {
            int idx = tid + s * 256;
            int r = idx & 127, kq = idx >> 7;
            float4 v = aR[s];
            int gk = aK[s];
            if (BN_IN) {
                v.x = fmaxf(fmaf(v.x, sm.scK[gk],     sm.shK[gk]),     0.f);
                v.y = fmaxf(fmaf(v.y, sm.scK[gk + 1], sm.shK[gk + 1]), 0.f);
                v.z = fmaxf(fmaf(v.z, sm.scK[gk + 2], sm.shK[gk + 2]), 0.f);
                v.w = fmaxf(fmaf(v.w, sm.scK[gk + 3], sm.shK[gk + 3]), 0.f);
            }
            int k0 = kq * 4;
            tA[buf][k0    ][r] = v.x;
            tA[buf][k0 + 1][r] = v.y;
            tA[buf][k0 + 2][r] = v.z;
            tA[buf][k0 + 3][r] = v.w;
        }
    };
    auto ldW = [&](int kbase) {
        if (tid < 96) {
            int kk = tid >> 2, n4 = (tid & 3) * 4;
            int gk = kbase + kk;
            #pragma unroll
            for (int j = 0; j < 4; j++) {
                int gn = colBase + n4 + j;
                wRv[j] = (gk < K && gn < N) ? W[(size_t)gk * ldw + gn] : 0.f;
            }
        }
    };
    auto stW = [&](int buf) {
        if (tid < 96) {
            int kk = tid >> 2, n4 = (tid & 3) * 4;
            #pragma unroll
            for (int j = 0; j < 4; j++) tW[buf][kk][n4 + j] = wRv[j];
        }
    };

    unsigned long long acc[4] = {};
    auto comp = [&](int buf) {
        #pragma unroll 8
        for (int k = 0; k < KT; k++) {
            float4 a = *(const float4*)&tA[buf][k][tr * 4];
            unsigned long long b = *(const unsigned long long*)&tW[buf][k][tc * 2];
            ffma2(acc[0], pack2(a.x, a.x), b);
            ffma2(acc[1], pack2(a.y, a.y), b);
            ffma2(acc[2], pack2(a.z, a.z), b);
            ffma2(acc[3], pack2(a.w, a.w), b);
        }
    };

    ldA(0); ldW(0);
    if (BN_IN) __syncthreads();
    stA(0); stW(0);
    __syncthreads();
    for (int kt = 0; kt < nkt; kt++) {
        int buf = kt & 1;
        if (kt + 1 < nkt) { ldA((kt + 1) * KT); ldW((kt + 1) * KT); }
        comp(buf);
        if (kt + 1 < nkt) { stA(buf ^ 1); stW(buf ^ 1); }
        __syncthreads();
    }

    int gn0 = colBase + tc * 2, gn1 = gn0 + 1;
    float b0 = (gn0 < N) ? bias[gn0] : 0.f;
    float b1 = (gn1 < N) ? bias[gn1] : 0.f;
    float cS[2] = {}, cQ[2] = {};
    #pragma unroll
    for (int m = 0; m < 4; m++) {
        int r = rowBase + tr * 4 + m;
        float v0 = f2lo(acc[m]) + b0;
        float v1 = f2hi(acc[m]) + b1;
        if (gn0 < N) { C[(size_t)r * ldc + gn0] = v0; cS[0] += v0; cQ[0] += v0 * v0; }
        if (gn1 < N) { C[(size_t)r * ldc + gn1] = v1; cS[1] += v1; cQ[1] += v1 * v1; }
    }
    float (*rt)[16] = (float (*)[16])sm.As2;
    __syncthreads();
    rt[tr][tc * 2] = cS[0]; rt[tr][tc * 2 + 1] = cS[1];
    __syncthreads();
    float sS = 0.f;
    if (tid < 16) { for (int j = 0; j < 32; j++) sS += rt[j][tid]; }
    __syncthreads();
    rt[tr][tc * 2] = cQ[0]; rt[tr][tc * 2 + 1] = cQ[1];
    __syncthreads();
    if (tid < 16) {
        float sQ = 0.f;
        for (int j = 0; j < 32; j++) sQ += rt[j][tid];
        int gn = colBase + tid;
        if (gn < N) { atomicAdd(&osum[gn], sS); atomicAdd(&osq[gn], sQ); }
    }
}

// ---------------- single persistent kernel ----------------
__global__ __launch_bounds__(256)
void mega_kernel(const float* __restrict__ x, const float* __restrict__ dW,
                 const float* __restrict__ law, const float* __restrict__ tg,
                 const float* __restrict__ W1, const float* __restrict__ b1,
                 const float* __restrict__ g1, const float* __restrict__ be1,
                 const float* __restrict__ W2, const float* __restrict__ b2,
                 const float* __restrict__ g2, const float* __restrict__ be2,
                 const float* __restrict__ W3, const float* __restrict__ b3,
                 const float* __restrict__ Wv1, const float* __restrict__ bv1,
                 const float* __restrict__ gv1, const float* __restrict__ bev1,
                 const float* __restrict__ Wv2, const float* __restrict__ bv2,
                 const float* __restrict__ gv2, const float* __restrict__ bev2,
                 const float* __restrict__ Wv3, const float* __restrict__ bv3,
                 const float* __restrict__ gv3, const float* __restrict__ bev3,
                 float* __restrict__ V)
{
    __shared__ SMT sm;
    const int cta = blockIdx.x;
    const int tid = threadIdx.x;
    unsigned bar = 0;

    // phase 0: zero stats, copy X = x
    if (cta == 0) for (int j = tid; j < 288; j += 256) { g_S1[j] = 0.f; g_Q1[j] = 0.f; }
    if (cta == 1) for (int j = tid; j < 288; j += 256) { g_S2[j] = 0.f; g_Q2[j] = 0.f; }
    if (cta == 2 && tid < 4) { g_SC[tid] = 0.f; g_QC[tid] = 0.f; }
    {
        const float4* xs = (const float4*)x;
        float4* xd = (float4*)g_X;
        for (int idx = cta * 256 + tid; idx < BB * DD / 4; idx += NCTA * 256) xd[idx] = xs[idx];
    }
    gridbar(bar);

    // v0 layer 1
    if (cta < 128)
        gemm_full<false, true, false, false, true>(sm, (cta & 31) * 64, (cta >> 5) * 64,
            g_X, DD, DD, Wv1, HH, HH, bv1, nullptr, nullptr, nullptr, nullptr,
            g_Y1, HP, g_S1, g_Q1, nullptr, 0.f, 0.f, nullptr, nullptr, nullptr);
    else if (cta < 144)
        gemm_thin<false>(sm, (cta - 128) * 128, 256, g_X, DD, DD, Wv1, HH, HH, bv1,
            nullptr, nullptr, nullptr, nullptr, g_Y1, HP, g_S1, g_Q1);
    gridbar(bar);

    // v0 layer 2
    if (cta < 128)
        gemm_full<true, true, false, false, true>(sm, (cta & 31) * 64, (cta >> 5) * 64,
            g_Y1, HP, HH, Wv2, HH, HH, bv2, gv1, bev1, g_S1, g_Q1,
            g_Y2, HP, g_S2, g_Q2, nullptr, 0.f, 0.f, nullptr, nullptr, nullptr);
    else if (cta < 144)
        gemm_thin<true>(sm, (cta - 128) * 128, 256, g_Y1, HP, HH, Wv2, HH, HH, bv2,
            gv1, bev1, g_S1, g_Q1, g_Y2, HP, g_S2, g_Q2);
    gridbar(bar);

    // v0 layer 3 (N=1)
    if (cta < 32)
        gemm_full<true, true, false, false, true>(sm, cta * 64, 0,
            g_Y2, HP, HH, Wv3, 1, 1, bv3, gv2, bev2, g_S2, g_Q2,
            g_Yv3, 1, g_SC, g_QC, nullptr, 0.f, 0.f, nullptr, nullptr, nullptr);
    gridbar(bar);

    // v0 finalize + re-zero stats for step 0
    {
        int r = cta * 256 + tid;
        if (r < BB) {
            float invB = 1.f / (float)BB;
            float mu  = g_SC[0] * invB;
            float var = g_QC[0] * invB - mu * mu;
            float rstd = rsqrtf(var + EPSBN);
            V[r] = fmaxf(gv3[0] * (g_Yv3[r] - mu) * rstd + bev3[0], 0.f);
        }
        if (cta == 8) for (int j = tid; j < 288; j += 256) { g_S1[j] = 0.f; g_Q1[j] = 0.f; }
        if (cta == 9) for (int j = tid; j < 288; j += 256) { g_S2[j] = 0.f; g_Q2[j] = 0.f; }
    }
    gridbar(bar);

    #pragma unroll 1
    for (int i = 0; i < SS; i++) {
        float h  = tg[i + 1] - tg[i];
        float cs = SIGMA_C * sqrtf(h);
        const float* w1i = W1 + (size_t)i * DD * HH;
        const float* w2i = W2 + (size_t)i * HH * HH;
        const float* w3i = W3 + (size_t)i * HH * DD;

        // layer 1: X -> Y1, stats S1/Q1, F1 term into V
        if (cta < 128)
            gemm_full<false, true, true, false, true>(sm, (cta & 31) * 64, (cta >> 5) * 64,
                g_X, DD, DD, w1i, HH, HH, b1 + (size_t)i * HH,
                nullptr, nullptr, nullptr, nullptr,
                g_Y1, HP, g_S1, g_Q1,
                law + (size_t)i * DD, h, cs, V, nullptr, nullptr);
        else if (cta < 144)
            gemm_thin<false>(sm, (cta - 128) * 128, 256, g_X, DD, DD, w1i, HH, HH,
                b1 + (size_t)i * HH, nullptr, nullptr, nullptr, nullptr,
                g_Y1, HP, g_S1, g_Q1);
        else if (cta == 147)
            for (int j = tid; j < 288; j += 256) { g_S2[j] = 0.f; g_Q2[j] = 0.f; }
        gridbar(bar);

        // layer 2: BN(Y1) -> Y2, stats S2/Q2
        if (cta < 128)
            gemm_full<true, true, false, false, true>(sm, (cta & 31) * 64, (cta >> 5) * 64,
                g_Y1, HP, HH, w2i, HH, HH, b2 + (size_t)i * HH,
                g1 + (size_t)i * HH, be1 + (size_t)i * HH, g_S1, g_Q1,
                g_Y2, HP, g_S2, g_Q2, nullptr, 0.f, 0.f, nullptr, nullptr, nullptr);
        else if (cta < 144)
            gemm_thin<true>(sm, (cta - 128) * 128, 256, g_Y1, HP, HH, w2i, HH, HH,
                b2 + (size_t)i * HH, g1 + (size_t)i * HH, be1 + (size_t)i * HH,
                g_S1, g_Q1, g_Y2, HP, g_S2, g_Q2);
        gridbar(bar);

        // layer 3: BN(Y2) -> grad; fused SDE update of X and V
        if (cta < 128)
            gemm_full<true, false, false, true, false>(sm, (cta & 31) * 64, (cta >> 5) * 64,
                g_Y2, HP, HH, w3i, DD, DD, b3 + (size_t)i * DD,
                g2 + (size_t)i * HH, be2 + (size_t)i * HH, g_S2, g_Q2,
                nullptr, 0, nullptr, nullptr,
                nullptr, h, cs, V, g_X, dW + (size_t)i * BB * DD);
        else if (cta == 128)
            for (int j = tid; j < 288; j += 256) { g_S1[j] = 0.f; g_Q1[j] = 0.f; }
        gridbar(bar);
    }

    // reset barrier state for next launch (handshake so nobody is still spinning)
    if (tid == 0) {
        __threadfence();
        atomicAdd(&g_done, 1u);
        if (cta == 0) {
            while (*(volatile unsigned*)&g_done < NCTA) __nanosleep(64);
            g_barctr = 0u;
            __threadfence();
            g_done = 0u;
        }
    }
}

// ---------------- host launcher ----------------
extern "C" void kernel_launch(void* const* d_in, const int* in_sizes, int n_in,
                              void* d_out, int out_size)
{
    const float* x    = (const float*)d_in[0];
    const float* dW   = (const float*)d_in[1];
    const float* law  = (const float*)d_in[2];
    const float* tg   = (const float*)d_in[3];
    const float* W1   = (const float*)d_in[4];
    const float* b1   = (const float*)d_in[5];
    const float* g1   = (const float*)d_in[6];
    const float* be1  = (const float*)d_in[7];
    const float* W2   = (const float*)d_in[8];
    const float* b2   = (const float*)d_in[9];
    const float* g2   = (const float*)d_in[10];
    const float* be2  = (const float*)d_in[11];
    const float* W3   = (const float*)d_in[12];
    const float* b3   = (const float*)d_in[13];
    const float* Wv1  = (const float*)d_in[14];
    const float* bv1  = (const float*)d_in[15];
    const float* gv1  = (const float*)d_in[16];
    const float* bev1 = (const float*)d_in[17];
    const float* Wv2  = (const float*)d_in[18];
    const float* bv2  = (const float*)d_in[19];
    const float* gv2  = (const float*)d_in[20];
    const float* bev2 = (const float*)d_in[21];
    const float* Wv3  = (const float*)d_in[22];
    const float* bv3  = (const float*)d_in[23];
    const float* gv3  = (const float*)d_in[24];
    const float* bev3 = (const float*)d_in[25];
    float* V = (float*)d_out;

    mega_kernel<<<NCTA, 256>>>(x, dW, law, tg,
                               W1, b1, g1, be1, W2, b2, g2, be2, W3, b3,
                               Wv1, bv1, gv1, bev1, Wv2, bv2, gv2, bev2,
                               Wv3, bv3, gv3, bev3, V);
    (void)in_sizes; (void)n_in; (void)out_size;
}

// round 6
// speedup vs baseline: 1.5532x; 1.0563x over previous
#include <cuda_runtime.h>
#include <math.h>

#define NCTA 148
#define NT   512
#define BB   2048
#define DD   256
#define HH   266
#define HP   272
#define SS   50
#define EPSBN 1e-5f
#define SIGMA_C 0.3f
#define KT   24

// ---------------- device scratch ----------------
__device__ float g_X[BB * DD];
__device__ float g_Y1[BB * HP];
__device__ float g_Y2[BB * HP];
__device__ float g_Yv3[BB];
__device__ float g_S1[288], g_Q1[288], g_S2[288], g_Q2[288];
__device__ float g_SC[4], g_QC[4];
__device__ unsigned g_barctr;
__device__ unsigned g_done;

// packed fp32x2 FMA
__device__ __forceinline__ void ffma2(unsigned long long& d,
                                      unsigned long long a,
                                      unsigned long long b) {
    asm("fma.rn.f32x2 %0, %1, %2, %0;" : "+l"(d) : "l"(a), "l"(b));
}
__device__ __forceinline__ unsigned long long pack2(float x, float y) {
    unsigned long long r;
    asm("mov.b64 %0, {%1, %2};" : "=l"(r) : "f"(x), "f"(y));
    return r;
}
__device__ __forceinline__ float f2lo(unsigned long long u) {
    return __uint_as_float((unsigned int)(u & 0xffffffffull));
}
__device__ __forceinline__ float f2hi(unsigned long long u) {
    return __uint_as_float((unsigned int)(u >> 32));
}

struct SMT {
    float As2[2][KT][128];   // full: A duplicated {a,a}; thin: A[k][128] overlay
    float Ws4[2][KT][64];    // full: W tile;             thin: W[KT][16] overlay
    float scK[288];
    float shK[288];
};

// ---------------- grid barrier (volatile poll, no sleep) ----------------
__device__ __forceinline__ void gridbar(unsigned& cnt) {
    __syncthreads();
    if (threadIdx.x == 0) {
        __threadfence();
        atomicAdd(&g_barctr, 1u);
        unsigned target = (++cnt) * NCTA;
        while (*(volatile unsigned*)&g_barctr < target) { }
        __threadfence();   // invalidate L1 so fresh data is read
    }
    __syncthreads();
}

// ---------------- full 64x64 GEMM phase (512 threads) ----------------
// thread map: tr = tid>>5 (row group of 4), tcg = tid&31 (col pair)
template<bool BN_IN, bool STATS, bool F1, bool XUPD, bool WRC>
__device__ void gemm_full(SMT& sm, int rowBase, int colBase,
    const float* __restrict__ A, int lda, int K,
    const float* __restrict__ W, int ldw, int N,
    const float* __restrict__ bias,
    const float* __restrict__ bng, const float* __restrict__ bnb,
    const float* __restrict__ ssum, const float* __restrict__ ssq,
    float* __restrict__ C, int ldc,
    float* __restrict__ osum, float* __restrict__ osq,
    const float* __restrict__ law, float hstep, float cstep,
    float* __restrict__ V, float* __restrict__ X, const float* __restrict__ dWi)
{
    const int tid = threadIdx.x;
    const int tr  = tid >> 5;
    const int tcg = tid & 31;
    const float invB = 1.f / (float)BB;

    if (BN_IN) {
        for (int k = tid; k < 288; k += NT) {
            if (k < K) {
                float mu  = ssum[k] * invB;
                float var = ssq[k] * invB - mu * mu;
                float rstd = rsqrtf(var + EPSBN);
                float sc = bng[k] * rstd;
                sm.scK[k] = sc;
                sm.shK[k] = bnb[k] - mu * sc;
            } else { sm.scK[k] = 0.f; sm.shK[k] = 0.f; }
        }
    }

    // loader jobs: one per thread (tid < 384)
    const int aRow = tid & 63;       // A: row
    const int aKq  = tid >> 6;       // A: k-quad (0..5 valid)
    const int wKrow = tid >> 4;      // W: k row (0..23 valid)
    const int wN4   = (tid & 15) << 2;
    float4 aR; int aK = 0;
    float4 wR;
    float facc = 0.f;
    const int nkt = (K + KT - 1) / KT;

    auto ldA = [&](int kbase) {
        if (tid < 384) {
            int gk = kbase + aKq * 4;
            aK = gk;
            float4 v = make_float4(0.f, 0.f, 0.f, 0.f);
            if (gk < K) {
                v = *(const float4*)(A + (size_t)(rowBase + aRow) * lda + gk);
                if (gk + 1 >= K) v.y = 0.f;
                if (gk + 2 >= K) v.z = 0.f;
                if (gk + 3 >= K) v.w = 0.f;
                if (F1 && colBase == 0) {
                    float d0 = v.x - law[gk]; facc += d0 * d0;
                    if (gk + 1 < K) { float d = v.y - law[gk + 1]; facc += d * d; }
                    if (gk + 2 < K) { float d = v.z - law[gk + 2]; facc += d * d; }
                    if (gk + 3 < K) { float d = v.w - law[gk + 3]; facc += d * d; }
                }
            }
            aR = v;
        }
    };
    auto stA = [&](int buf) {
        if (tid < 384) {
            float4 v = aR;
            int gk = aK;
            if (BN_IN) {
                v.x = fmaxf(fmaf(v.x, sm.scK[gk],     sm.shK[gk]),     0.f);
                v.y = fmaxf(fmaf(v.y, sm.scK[gk + 1], sm.shK[gk + 1]), 0.f);
                v.z = fmaxf(fmaf(v.z, sm.scK[gk + 2], sm.shK[gk + 2]), 0.f);
                v.w = fmaxf(fmaf(v.w, sm.scK[gk + 3], sm.shK[gk + 3]), 0.f);
            }
            int k0 = aKq * 4;
            int r2 = aRow * 2;
            *(float2*)&sm.As2[buf][k0    ][r2] = make_float2(v.x, v.x);
            *(float2*)&sm.As2[buf][k0 + 1][r2] = make_float2(v.y, v.y);
            *(float2*)&sm.As2[buf][k0 + 2][r2] = make_float2(v.z, v.z);
            *(float2*)&sm.As2[buf][k0 + 3][r2] = make_float2(v.w, v.w);
        }
    };
    auto ldW = [&](int kbase) {
        if (tid < 384) {
            int gk = kbase + wKrow, gn = colBase + wN4;
            float4 w = make_float4(0.f, 0.f, 0.f, 0.f);
            if (gk < K) {
                const float* wr = W + (size_t)gk * ldw + gn;
                if (gn     < N) w.x = wr[0];
                if (gn + 1 < N) w.y = wr[1];
                if (gn + 2 < N) w.z = wr[2];
                if (gn + 3 < N) w.w = wr[3];
            }
            wR = w;
        }
    };
    auto stW = [&](int buf) {
        if (tid < 384) *(float4*)&sm.Ws4[buf][wKrow][wN4] = wR;
    };

    unsigned long long acc[4] = {};   // acc[m] = {col0,col1} for row m
    auto comp = [&](int buf) {
        #pragma unroll 8
        for (int k = 0; k < KT; k++) {
            const ulonglong2* aP = (const ulonglong2*)&sm.As2[buf][k][tr * 8];
            ulonglong2 a01 = aP[0];
            ulonglong2 a23 = aP[1];
            unsigned long long b = *(const unsigned long long*)&sm.Ws4[buf][k][tcg * 2];
            ffma2(acc[0], a01.x, b);
            ffma2(acc[1], a01.y, b);
            ffma2(acc[2], a23.x, b);
            ffma2(acc[3], a23.y, b);
        }
    };

    ldA(0); ldW(0);
    if (BN_IN) __syncthreads();
    stA(0); stW(0);
    __syncthreads();
    for (int kt = 0; kt < nkt; kt++) {
        int buf = kt & 1;
        if (kt + 1 < nkt) { ldA((kt + 1) * KT); ldW((kt + 1) * KT); }
        comp(buf);
        if (kt + 1 < nkt) { stA(buf ^ 1); stW(buf ^ 1); }
        __syncthreads();
    }

    float vals[4][2];
    #pragma unroll
    for (int m = 0; m < 4; m++) { vals[m][0] = f2lo(acc[m]); vals[m][1] = f2hi(acc[m]); }

    float (*red)[64] = (float (*)[64])sm.As2;

    if (WRC) {
        float colS[2] = {}, colQ[2] = {};
        #pragma unroll
        for (int n = 0; n < 2; n++) {
            int gn = colBase + tcg * 2 + n;
            if (gn < N) {
                float bv = bias[gn];
                #pragma unroll
                for (int m = 0; m < 4; m++) {
                    float v = vals[m][n] + bv;
                    C[(size_t)(rowBase + tr * 4 + m) * ldc + gn] = v;
                    colS[n] += v;
                    colQ[n] += v * v;
                }
            }
        }
        if (STATS) {
            red[tr][tcg * 2] = colS[0]; red[tr][tcg * 2 + 1] = colS[1];
            __syncthreads();
            if (tid < 64) {
                float s = 0.f;
                #pragma unroll
                for (int j = 0; j < 16; j++) s += red[j][tid];
                int gn = colBase + tid;
                if (gn < N) atomicAdd(&osum[gn], s);
            }
            __syncthreads();
            red[tr][tcg * 2] = colQ[0]; red[tr][tcg * 2 + 1] = colQ[1];
            __syncthreads();
            if (tid < 64) {
                float s = 0.f;
                #pragma unroll
                for (int j = 0; j < 16; j++) s += red[j][tid];
                int gn = colBase + tid;
                if (gn < N) atomicAdd(&osq[gn], s);
            }
        }
    }

    if (XUPD) {
        float2 bj = *(const float2*)(bias + colBase + tcg * 2);
        float p2[4], p3[4];
        #pragma unroll
        for (int m = 0; m < 4; m++) {
            int r = rowBase + tr * 4 + m;
            size_t off = (size_t)r * DD + colBase + tcg * 2;
            float2 dw = *(const float2*)(dWi + off);
            float2 xv = *(const float2*)(X + off);
            float q0 = vals[m][0] + bj.x, q1 = vals[m][1] + bj.y;
            float n0 = cstep * dw.x,      n1 = cstep * dw.y;
            float2 xo;
            xo.x = xv.x - q0 * hstep + n0;
            xo.y = xv.y - q1 * hstep + n1;
            *(float2*)(X + off) = xo;
            p2[m] = q0 * q0 + q1 * q1;
            p3[m] = q0 * n0 + q1 * n1;
        }
        __syncthreads();
        #pragma unroll
        for (int m = 0; m < 4; m++) red[tcg][tr * 4 + m] = p2[m];
        __syncthreads();
        float s2 = 0.f;
        if (tid < 64) {
            #pragma unroll
            for (int j = 0; j < 32; j++) s2 += red[j][tid];
        }
        __syncthreads();
        #pragma unroll
        for (int m = 0; m < 4; m++) red[tcg][tr * 4 + m] = p3[m];
        __syncthreads();
        if (tid < 64) {
            float s3 = 0.f;
            #pragma unroll
            for (int j = 0; j < 32; j++) s3 += red[j][tid];
            atomicAdd(&V[rowBase + tid], -0.5f * hstep * s2 + s3);
        }
    }

    if (F1) {
        if (colBase == 0) {
            __syncthreads();
            if (tid < 384) red[aKq][aRow] = facc;
            __syncthreads();
            if (tid < 64) {
                float s = 0.f;
                #pragma unroll
                for (int j = 0; j < 6; j++) s += red[j][tid];
                atomicAdd(&V[rowBase + tid], -0.5f * hstep * s);
            }
        }
    }
}

// ---------------- thin 128x16 GEMM phase (512 threads) ----------------
// thread map: tr = tid & 127 (row), tcq = tid >> 7 (col quad)
template<bool BN_IN>
__device__ void gemm_thin(SMT& sm, int rowBase, int colBase,
    const float* __restrict__ A, int lda, int K,
    const float* __restrict__ W, int ldw, int N,
    const float* __restrict__ bias,
    const float* __restrict__ bng, const float* __restrict__ bnb,
    const float* __restrict__ ssum, const float* __restrict__ ssq,
    float* __restrict__ C, int ldc,
    float* __restrict__ osum, float* __restrict__ osq)
{
    const int tid = threadIdx.x;
    const int tr  = tid & 127;
    const int tcq = tid >> 7;
    const float invB = 1.f / (float)BB;
    float (*tA)[KT][128] = (float (*)[KT][128])sm.As2;
    float (*tW)[KT][16]  = (float (*)[KT][16]) sm.Ws4;

    if (BN_IN) {
        for (int k = tid; k < 288; k += NT) {
            if (k < K) {
                float mu  = ssum[k] * invB;
                float var = ssq[k] * invB - mu * mu;
                float rstd = rsqrtf(var + EPSBN);
                float sc = bng[k] * rstd;
                sm.scK[k] = sc;
                sm.shK[k] = bnb[k] - mu * sc;
            } else { sm.scK[k] = 0.f; sm.shK[k] = 0.f; }
        }
    }

    float4 aR[2]; int aK[2];
    float wRv[4];
    const int nkt = (K + KT - 1) / KT;

    auto ldA = [&](int kbase) {
        #pragma unroll
        for (int s = 0; s < 2; s++) {
            int idx = tid + s * NT;
            if (idx < 768) {
                int r = idx & 127, kq = idx >> 7;
                int gk = kbase + kq * 4;
                aK[s] = gk;
                float4 v = make_float4(0.f, 0.f, 0.f, 0.f);
                if (gk < K) {
                    v = *(const float4*)(A + (size_t)(rowBase + r) * lda + gk);
                    if (gk + 1 >= K) v.y = 0.f;
                    if (gk + 2 >= K) v.z = 0.f;
                    if (gk + 3 >= K) v.w = 0.f;
                }
                aR[s] = v;
            }
        }
    };
    auto stA = [&](int buf) {
        #pragma unroll
        for (int s = 0; s < 2; s++) {
            int idx = tid + s * NT;
            if (idx < 768) {
                int r = idx & 127, kq = idx >> 7;
                float4 v = aR[s];
                int gk = aK[s];
                if (BN_IN) {
                    v.x = fmaxf(fmaf(v.x, sm.scK[gk],     sm.shK[gk]),     0.f);
                    v.y = fmaxf(fmaf(v.y, sm.scK[gk + 1], sm.shK[gk + 1]), 0.f);
                    v.z = fmaxf(fmaf(v.z, sm.scK[gk + 2], sm.shK[gk + 2]), 0.f);
                    v.w = fmaxf(fmaf(v.w, sm.scK[gk + 3], sm.shK[gk + 3]), 0.f);
                }
                int k0 = kq * 4;
                tA[buf][k0    ][r] = v.x;
                tA[buf][k0 + 1][r] = v.y;
                tA[buf][k0 + 2][r] = v.z;
                tA[buf][k0 + 3][r] = v.w;
            }
        }
    };
    auto ldW = [&](int kbase) {
        if (tid < 96) {
            int kk = tid >> 2, n4 = (tid & 3) * 4;
            int gk = kbase + kk;
            #pragma unroll
            for (int j = 0; j < 4; j++) {
                int gn = colBase + n4 + j;
                wRv[j] = (gk < K && gn < N) ? W[(size_t)gk * ldw + gn] : 0.f;
            }
        }
    };
    auto stW = [&](int buf) {
        if (tid < 96) {
            int kk = tid >> 2, n4 = (tid & 3) * 4;
            #pragma unroll
            for (int j = 0; j < 4; j++) tW[buf][kk][n4 + j] = wRv[j];
        }
    };

    unsigned long long acc[2] = {};   // 4 cols for this thread's row
    auto comp = [&](int buf) {
        #pragma unroll 8
        for (int k = 0; k < KT; k++) {
            float a = tA[buf][k][tr];
            ulonglong2 b = *(const ulonglong2*)&tW[buf][k][tcq * 4];
            unsigned long long aa = pack2(a, a);
            ffma2(acc[0], aa, b.x);
            ffma2(acc[1], aa, b.y);
        }
    };

    ldA(0); ldW(0);
    if (BN_IN) __syncthreads();
    stA(0); stW(0);
    __syncthreads();
    for (int kt = 0; kt < nkt; kt++) {
        int buf = kt & 1;
        if (kt + 1 < nkt) { ldA((kt + 1) * KT); ldW((kt + 1) * KT); }
        comp(buf);
        if (kt + 1 < nkt) { stA(buf ^ 1); stW(buf ^ 1); }
        __syncthreads();
    }

    float v[4];
    v[0] = f2lo(acc[0]); v[1] = f2hi(acc[0]);
    v[2] = f2lo(acc[1]); v[3] = f2hi(acc[1]);
    #pragma unroll
    for (int j = 0; j < 4; j++) {
        int gn = colBase + tcq * 4 + j;
        if (gn < N) {
            v[j] += bias[gn];
            C[(size_t)(rowBase + tr) * ldc + gn] = v[j];
        } else v[j] = 0.f;
    }
    float (*rt)[16] = (float (*)[16])sm.As2;   // 128 x 16 values
    __syncthreads();
    #pragma unroll
    for (int j = 0; j < 4; j++) rt[tr][tcq * 4 + j] = v[j];
    __syncthreads();
    if (tid < 16) {
        float s = 0.f, q = 0.f;
        for (int j = 0; j < 128; j++) { float t = rt[j][tid]; s += t; q += t * t; }
        int gn = colBase + tid;
        if (gn < N) { atomicAdd(&osum[gn], s); atomicAdd(&osq[gn], q); }
    }
}

// ---------------- single persistent kernel ----------------
__global__ __launch_bounds__(NT, 1)
void mega_kernel(const float* __restrict__ x, const float* __restrict__ dW,
                 const float* __restrict__ law, const float* __restrict__ tg,
                 const float* __restrict__ W1, const float* __restrict__ b1,
                 const float* __restrict__ g1, const float* __restrict__ be1,
                 const float* __restrict__ W2, const float* __restrict__ b2,
                 const float* __restrict__ g2, const float* __restrict__ be2,
                 const float* __restrict__ W3, const float* __restrict__ b3,
                 const float* __restrict__ Wv1, const float* __restrict__ bv1,
                 const float* __restrict__ gv1, const float* __restrict__ bev1,
                 const float* __restrict__ Wv2, const float* __restrict__ bv2,
                 const float* __restrict__ gv2, const float* __restrict__ bev2,
                 const float* __restrict__ Wv3, const float* __restrict__ bv3,
                 const float* __restrict__ gv3, const float* __restrict__ bev3,
                 float* __restrict__ V)
{
    __shared__ SMT sm;
    const int cta = blockIdx.x;
    const int tid = threadIdx.x;
    unsigned bar = 0;
    const int myRow = (cta & 31) * 64;
    const int myCol = (cta >> 5) * 64;

    // phase 0: zero stats, copy X = x
    if (cta == 0) for (int j = tid; j < 288; j += NT) { g_S1[j] = 0.f; g_Q1[j] = 0.f; }
    if (cta == 1) for (int j = tid; j < 288; j += NT) { g_S2[j] = 0.f; g_Q2[j] = 0.f; }
    if (cta == 2 && tid < 4) { g_SC[tid] = 0.f; g_QC[tid] = 0.f; }
    {
        const float4* xs = (const float4*)x;
        float4* xd = (float4*)g_X;
        for (int idx = cta * NT + tid; idx < BB * DD / 4; idx += NCTA * NT) xd[idx] = xs[idx];
    }
    gridbar(bar);

    // v0 layer 1
    if (cta < 128)
        gemm_full<false, true, false, false, true>(sm, myRow, myCol,
            g_X, DD, DD, Wv1, HH, HH, bv1, nullptr, nullptr, nullptr, nullptr,
            g_Y1, HP, g_S1, g_Q1, nullptr, 0.f, 0.f, nullptr, nullptr, nullptr);
    else if (cta < 144)
        gemm_thin<false>(sm, (cta - 128) * 128, 256, g_X, DD, DD, Wv1, HH, HH, bv1,
            nullptr, nullptr, nullptr, nullptr, g_Y1, HP, g_S1, g_Q1);
    gridbar(bar);

    // v0 layer 2
    if (cta < 128)
        gemm_full<true, true, false, false, true>(sm, myRow, myCol,
            g_Y1, HP, HH, Wv2, HH, HH, bv2, gv1, bev1, g_S1, g_Q1,
            g_Y2, HP, g_S2, g_Q2, nullptr, 0.f, 0.f, nullptr, nullptr, nullptr);
    else if (cta < 144)
        gemm_thin<true>(sm, (cta - 128) * 128, 256, g_Y1, HP, HH, Wv2, HH, HH, bv2,
            gv1, bev1, g_S1, g_Q1, g_Y2, HP, g_S2, g_Q2);
    gridbar(bar);

    // v0 layer 3 (N=1)
    if (cta < 32)
        gemm_full<true, true, false, false, true>(sm, cta * 64, 0,
            g_Y2, HP, HH, Wv3, 1, 1, bv3, gv2, bev2, g_S2, g_Q2,
            g_Yv3, 1, g_SC, g_QC, nullptr, 0.f, 0.f, nullptr, nullptr, nullptr);
    gridbar(bar);

    // v0 finalize + re-zero stats for step 0
    {
        int r = cta * NT + tid;
        if (r < BB) {
            float invB = 1.f / (float)BB;
            float mu  = g_SC[0] * invB;
            float var = g_QC[0] * invB - mu * mu;
            float rstd = rsqrtf(var + EPSBN);
            V[r] = fmaxf(gv3[0] * (g_Yv3[r] - mu) * rstd + bev3[0], 0.f);
        }
        if (cta == 8) for (int j = tid; j < 288; j += NT) { g_S1[j] = 0.f; g_Q1[j] = 0.f; }
        if (cta == 9) for (int j = tid; j < 288; j += NT) { g_S2[j] = 0.f; g_Q2[j] = 0.f; }
    }
    gridbar(bar);

    #pragma unroll 1
    for (int i = 0; i < SS; i++) {
        float h  = tg[i + 1] - tg[i];
        float cs = SIGMA_C * sqrtf(h);
        const float* w1i = W1 + (size_t)i * DD * HH;
        const float* w2i = W2 + (size_t)i * HH * HH;
        const float* w3i = W3 + (size_t)i * HH * DD;

        // layer 1: X -> Y1, stats S1/Q1, F1 term into V
        if (cta < 128)
            gemm_full<false, true, true, false, true>(sm, myRow, myCol,
                g_X, DD, DD, w1i, HH, HH, b1 + (size_t)i * HH,
                nullptr, nullptr, nullptr, nullptr,
                g_Y1, HP, g_S1, g_Q1,
                law + (size_t)i * DD, h, cs, V, nullptr, nullptr);
        else if (cta < 144)
            gemm_thin<false>(sm, (cta - 128) * 128, 256, g_X, DD, DD, w1i, HH, HH,
                b1 + (size_t)i * HH, nullptr, nullptr, nullptr, nullptr,
                g_Y1, HP, g_S1, g_Q1);
        else if (cta == 147)
            for (int j = tid; j < 288; j += NT) { g_S2[j] = 0.f; g_Q2[j] = 0.f; }
        gridbar(bar);

        // layer 2: BN(Y1) -> Y2, stats S2/Q2
        if (cta < 128)
            gemm_full<true, true, false, false, true>(sm, myRow, myCol,
                g_Y1, HP, HH, w2i, HH, HH, b2 + (size_t)i * HH,
                g1 + (size_t)i * HH, be1 + (size_t)i * HH, g_S1, g_Q1,
                g_Y2, HP, g_S2, g_Q2, nullptr, 0.f, 0.f, nullptr, nullptr, nullptr);
        else if (cta < 144)
            gemm_thin<true>(sm, (cta - 128) * 128, 256, g_Y1, HP, HH, w2i, HH, HH,
                b2 + (size_t)i * HH, g1 + (size_t)i * HH, be1 + (size_t)i * HH,
                g_S1, g_Q1, g_Y2, HP, g_S2, g_Q2);
        gridbar(bar);

        // layer 3: BN(Y2) -> grad; fused SDE update of X and V
        if (cta < 128)
            gemm_full<true, false, false, true, false>(sm, myRow, myCol,
                g_Y2, HP, HH, w3i, DD, DD, b3 + (size_t)i * DD,
                g2 + (size_t)i * HH, be2 + (size_t)i * HH, g_S2, g_Q2,
                nullptr, 0, nullptr, nullptr,
                nullptr, h, cs, V, g_X, dW + (size_t)i * BB * DD);
        else if (cta == 128)
            for (int j = tid; j < 288; j += NT) { g_S1[j] = 0.f; g_Q1[j] = 0.f; }
        gridbar(bar);
    }

    // reset barrier state for next launch (handshake so nobody is still spinning)
    if (tid == 0) {
        __threadfence();
        atomicAdd(&g_done, 1u);
        if (cta == 0) {
            while (*(volatile unsigned*)&g_done < NCTA) { }
            g_barctr = 0u;
            __threadfence();
            g_done = 0u;
        }
    }
}

// ---------------- host launcher ----------------
extern "C" void kernel_launch(void* const* d_in, const int* in_sizes, int n_in,
                              void* d_out, int out_size)
{
    const float* x    = (const float*)d_in[0];
    const float* dW   = (const float*)d_in[1];
    const float* law  = (const float*)d_in[2];
    const float* tg   = (const float*)d_in[3];
    const float* W1   = (const float*)d_in[4];
    const float* b1   = (const float*)d_in[5];
    const float* g1   = (const float*)d_in[6];
    const float* be1  = (const float*)d_in[7];
    const float* W2   = (const float*)d_in[8];
    const float* b2   = (const float*)d_in[9];
    const float* g2   = (const float*)d_in[10];
    const float* be2  = (const float*)d_in[11];
    const float* W3   = (const float*)d_in[12];
    const float* b3   = (const float*)d_in[13];
    const float* Wv1  = (const float*)d_in[14];
    const float* bv1  = (const float*)d_in[15];
    const float* gv1  = (const float*)d_in[16];
    const float* bev1 = (const float*)d_in[17];
    const float* Wv2  = (const float*)d_in[18];
    const float* bv2  = (const float*)d_in[19];
    const float* gv2  = (const float*)d_in[20];
    const float* bev2 = (const float*)d_in[21];
    const float* Wv3  = (const float*)d_in[22];
    const float* bv3  = (const float*)d_in[23];
    const float* gv3  = (const float*)d_in[24];
    const float* bev3 = (const float*)d_in[25];
    float* V = (float*)d_out;

    mega_kernel<<<NCTA, NT>>>(x, dW, law, tg,
                              W1, b1, g1, be1, W2, b2, g2, be2, W3, b3,
                              Wv1, bv1, gv1, bev1, Wv2, bv2, gv2, bev2,
                              Wv3, bv3, gv3, bev3, V);
    (void)in_sizes; (void)n_in; (void)out_size;
}

// round 7
// speedup vs baseline: 1.5655x; 1.0079x over previous
#include <cuda_runtime.h>
#include <math.h>

#define NCTA 148
#define NT   512
#define BB   2048
#define DD   256
#define HH   266
#define HP   272
#define SS   50
#define EPSBN 1e-5f
#define SIGMA_C 0.3f
#define KT   24

// ---------------- device scratch ----------------
__device__ float g_X[BB * DD];
__device__ float g_Y1[BB * HP];
__device__ float g_Y2[BB * HP];
__device__ float g_Yv3[BB];
__device__ float g_S1[288], g_Q1[288], g_S2[288], g_Q2[288];
__device__ float g_SC[4], g_QC[4];
__device__ unsigned g_barctr;
__device__ unsigned g_done;

// packed fp32x2 FMA
__device__ __forceinline__ void ffma2(unsigned long long& d,
                                      unsigned long long a,
                                      unsigned long long b) {
    asm("fma.rn.f32x2 %0, %1, %2, %0;" : "+l"(d) : "l"(a), "l"(b));
}
__device__ __forceinline__ unsigned long long pack2(float x, float y) {
    unsigned long long r;
    asm("mov.b64 %0, {%1, %2};" : "=l"(r) : "f"(x), "f"(y));
    return r;
}
__device__ __forceinline__ float f2lo(unsigned long long u) {
    return __uint_as_float((unsigned int)(u & 0xffffffffull));
}
__device__ __forceinline__ float f2hi(unsigned long long u) {
    return __uint_as_float((unsigned int)(u >> 32));
}

struct SMT {
    float As2[2][KT][128];   // full: A duplicated {a,a}; thin: A[k][128] overlay
    float Ws4[2][KT][64];    // full: W tile;             thin: W[KT][16] overlay
    float scK[288];
    float shK[288];
};

// ---------------- grid barrier (volatile poll, no sleep) ----------------
__device__ __forceinline__ void gridbar(unsigned& cnt) {
    __syncthreads();
    if (threadIdx.x == 0) {
        __threadfence();
        atomicAdd(&g_barctr, 1u);
        unsigned target = (++cnt) * NCTA;
        while (*(volatile unsigned*)&g_barctr < target) { }
        __threadfence();   // invalidate L1 so fresh data is read
    }
    __syncthreads();
}

// ---------------- full 64x64 GEMM phase (512 threads) ----------------
// thread map: tr = tid>>5 (row group of 4), tcg = tid&31 (col pair)
template<bool BN_IN, bool STATS, bool F1, bool XUPD, bool WRC>
__device__ void gemm_full(SMT& sm, int rowBase, int colBase,
    const float* __restrict__ A, int lda, int K,
    const float* __restrict__ W, int ldw, int N,
    const float* __restrict__ bias,
    const float* __restrict__ bng, const float* __restrict__ bnb,
    const float* __restrict__ ssum, const float* __restrict__ ssq,
    float* __restrict__ C, int ldc,
    float* __restrict__ osum, float* __restrict__ osq,
    const float* __restrict__ law, float hstep, float cstep,
    float* __restrict__ V, float* __restrict__ X, const float* __restrict__ dWi)
{
    const int tid = threadIdx.x;
    const int tr  = tid >> 5;
    const int tcg = tid & 31;
    const float invB = 1.f / (float)BB;

    if (BN_IN) {
        for (int k = tid; k < 288; k += NT) {
            if (k < K) {
                float mu  = ssum[k] * invB;
                float var = ssq[k] * invB - mu * mu;
                float rstd = rsqrtf(var + EPSBN);
                float sc = bng[k] * rstd;
                sm.scK[k] = sc;
                sm.shK[k] = bnb[k] - mu * sc;
            } else { sm.scK[k] = 0.f; sm.shK[k] = 0.f; }
        }
    }

    // loader jobs: one per thread (tid < 384)
    const int aRow = tid & 63;       // A: row
    const int aKq  = tid >> 6;       // A: k-quad (0..5 valid)
    const int wKrow = tid >> 4;      // W: k row (0..23 valid)
    const int wN4   = (tid & 15) << 2;
    float4 aR; int aK = 0;
    float4 wR;
    float facc = 0.f;
    const int nkt = (K + KT - 1) / KT;

    auto ldA = [&](int kbase) {
        if (tid < 384) {
            int gk = kbase + aKq * 4;
            aK = gk;
            float4 v = make_float4(0.f, 0.f, 0.f, 0.f);
            if (gk < K) {
                v = *(const float4*)(A + (size_t)(rowBase + aRow) * lda + gk);
                if (gk + 1 >= K) v.y = 0.f;
                if (gk + 2 >= K) v.z = 0.f;
                if (gk + 3 >= K) v.w = 0.f;
                if (F1 && colBase == 0) {
                    float d0 = v.x - law[gk]; facc += d0 * d0;
                    if (gk + 1 < K) { float d = v.y - law[gk + 1]; facc += d * d; }
                    if (gk + 2 < K) { float d = v.z - law[gk + 2]; facc += d * d; }
                    if (gk + 3 < K) { float d = v.w - law[gk + 3]; facc += d * d; }
                }
            }
            aR = v;
        }
    };
    auto stA = [&](int buf) {
        if (tid < 384) {
            float4 v = aR;
            int gk = aK;
            if (BN_IN) {
                v.x = fmaxf(fmaf(v.x, sm.scK[gk],     sm.shK[gk]),     0.f);
                v.y = fmaxf(fmaf(v.y, sm.scK[gk + 1], sm.shK[gk + 1]), 0.f);
                v.z = fmaxf(fmaf(v.z, sm.scK[gk + 2], sm.shK[gk + 2]), 0.f);
                v.w = fmaxf(fmaf(v.w, sm.scK[gk + 3], sm.shK[gk + 3]), 0.f);
            }
            int k0 = aKq * 4;
            int r2 = aRow * 2;
            *(float2*)&sm.As2[buf][k0    ][r2] = make_float2(v.x, v.x);
            *(float2*)&sm.As2[buf][k0 + 1][r2] = make_float2(v.y, v.y);
            *(float2*)&sm.As2[buf][k0 + 2][r2] = make_float2(v.z, v.z);
            *(float2*)&sm.As2[buf][k0 + 3][r2] = make_float2(v.w, v.w);
        }
    };
    auto ldW = [&](int kbase) {
        if (tid < 384) {
            int gk = kbase + wKrow, gn = colBase + wN4;
            float4 w = make_float4(0.f, 0.f, 0.f, 0.f);
            if (gk < K) {
                const float* wr = W + (size_t)gk * ldw + gn;
                if (gn     < N) w.x = wr[0];
                if (gn + 1 < N) w.y = wr[1];
                if (gn + 2 < N) w.z = wr[2];
                if (gn + 3 < N) w.w = wr[3];
            }
            wR = w;
        }
    };
    auto stW = [&](int buf) {
        if (tid < 384) *(float4*)&sm.Ws4[buf][wKrow][wN4] = wR;
    };

    unsigned long long acc[4] = {};   // acc[m] = {col0,col1} for row m
    auto comp = [&](int buf) {
        #pragma unroll 8
        for (int k = 0; k < KT; k++) {
            const ulonglong2* aP = (const ulonglong2*)&sm.As2[buf][k][tr * 8];
            ulonglong2 a01 = aP[0];
            ulonglong2 a23 = aP[1];
            unsigned long long b = *(const unsigned long long*)&sm.Ws4[buf][k][tcg * 2];
            ffma2(acc[0], a01.x, b);
            ffma2(acc[1], a01.y, b);
            ffma2(acc[2], a23.x, b);
            ffma2(acc[3], a23.y, b);
        }
    };

    ldA(0); ldW(0);
    if (BN_IN) __syncthreads();
    stA(0); stW(0);
    __syncthreads();
    for (int kt = 0; kt < nkt; kt++) {
        int buf = kt & 1;
        if (kt + 1 < nkt) { ldA((kt + 1) * KT); ldW((kt + 1) * KT); }
        comp(buf);
        if (kt + 1 < nkt) { stA(buf ^ 1); stW(buf ^ 1); }
        __syncthreads();
    }

    float vals[4][2];
    #pragma unroll
    for (int m = 0; m < 4; m++) { vals[m][0] = f2lo(acc[m]); vals[m][1] = f2hi(acc[m]); }

    float (*red)[64] = (float (*)[64])sm.As2;

    if (WRC) {
        float colS[2] = {}, colQ[2] = {};
        #pragma unroll
        for (int n = 0; n < 2; n++) {
            int gn = colBase + tcg * 2 + n;
            if (gn < N) {
                float bv = bias[gn];
                #pragma unroll
                for (int m = 0; m < 4; m++) {
                    float v = vals[m][n] + bv;
                    C[(size_t)(rowBase + tr * 4 + m) * ldc + gn] = v;
                    colS[n] += v;
                    colQ[n] += v * v;
                }
            }
        }
        if (STATS) {
            red[tr][tcg * 2] = colS[0]; red[tr][tcg * 2 + 1] = colS[1];
            __syncthreads();
            if (tid < 64) {
                float s = 0.f;
                #pragma unroll
                for (int j = 0; j < 16; j++) s += red[j][tid];
                int gn = colBase + tid;
                if (gn < N) atomicAdd(&osum[gn], s);
            }
            __syncthreads();
            red[tr][tcg * 2] = colQ[0]; red[tr][tcg * 2 + 1] = colQ[1];
            __syncthreads();
            if (tid < 64) {
                float s = 0.f;
                #pragma unroll
                for (int j = 0; j < 16; j++) s += red[j][tid];
                int gn = colBase + tid;
                if (gn < N) atomicAdd(&osq[gn], s);
            }
        }
    }

    if (XUPD) {
        float2 bj = *(const float2*)(bias + colBase + tcg * 2);
        float p2[4], p3[4];
        #pragma unroll
        for (int m = 0; m < 4; m++) {
            int r = rowBase + tr * 4 + m;
            size_t off = (size_t)r * DD + colBase + tcg * 2;
            float2 dw = *(const float2*)(dWi + off);
            float2 xv = *(const float2*)(X + off);
            float q0 = vals[m][0] + bj.x, q1 = vals[m][1] + bj.y;
            float n0 = cstep * dw.x,      n1 = cstep * dw.y;
            float2 xo;
            xo.x = xv.x - q0 * hstep + n0;
            xo.y = xv.y - q1 * hstep + n1;
            *(float2*)(X + off) = xo;
            p2[m] = q0 * q0 + q1 * q1;
            p3[m] = q0 * n0 + q1 * n1;
        }
        __syncthreads();
        #pragma unroll
        for (int m = 0; m < 4; m++) red[tcg][tr * 4 + m] = p2[m];
        __syncthreads();
        float s2 = 0.f;
        if (tid < 64) {
            #pragma unroll
            for (int j = 0; j < 32; j++) s2 += red[j][tid];
        }
        __syncthreads();
        #pragma unroll
        for (int m = 0; m < 4; m++) red[tcg][tr * 4 + m] = p3[m];
        __syncthreads();
        if (tid < 64) {
            float s3 = 0.f;
            #pragma unroll
            for (int j = 0; j < 32; j++) s3 += red[j][tid];
            atomicAdd(&V[rowBase + tid], -0.5f * hstep * s2 + s3);
        }
    }

    if (F1) {
        if (colBase == 0) {
            __syncthreads();
            if (tid < 384) red[aKq][aRow] = facc;
            __syncthreads();
            if (tid < 64) {
                float s = 0.f;
                #pragma unroll
                for (int j = 0; j < 6; j++) s += red[j][tid];
                atomicAdd(&V[rowBase + tid], -0.5f * hstep * s);
            }
        }
    }
}

// ---------------- thin 128x16 GEMM phase (512 threads) ----------------
// thread map: tr = tid & 127 (row), tcq = tid >> 7 (col quad)
template<bool BN_IN>
__device__ void gemm_thin(SMT& sm, int rowBase, int colBase,
    const float* __restrict__ A, int lda, int K,
    const float* __restrict__ W, int ldw, int N,
    const float* __restrict__ bias,
    const float* __restrict__ bng, const float* __restrict__ bnb,
    const float* __restrict__ ssum, const float* __restrict__ ssq,
    float* __restrict__ C, int ldc,
    float* __restrict__ osum, float* __restrict__ osq)
{
    const int tid = threadIdx.x;
    const int tr  = tid & 127;
    const int tcq = tid >> 7;
    const float invB = 1.f / (float)BB;
    float (*tA)[KT][128] = (float (*)[KT][128])sm.As2;
    float (*tW)[KT][16]  = (float (*)[KT][16]) sm.Ws4;

    if (BN_IN) {
        for (int k = tid; k < 288; k += NT) {
            if (k < K) {
                float mu  = ssum[k] * invB;
                float var = ssq[k] * invB - mu * mu;
                float rstd = rsqrtf(var + EPSBN);
                float sc = bng[k] * rstd;
                sm.scK[k] = sc;
                sm.shK[k] = bnb[k] - mu * sc;
            } else { sm.scK[k] = 0.f; sm.shK[k] = 0.f; }
        }
    }

    float4 aR[2]; int aK[2];
    float wRv[4];
    const int nkt = (K + KT - 1) / KT;

    auto ldA = [&](int kbase) {
        #pragma unroll
        for (int s = 0; s < 2; s++) {
            int idx = tid + s * NT;
            if (idx < 768) {
                int r = idx & 127, kq = idx >> 7;
                int gk = kbase + kq * 4;
                aK[s] = gk;
                float4 v = make_float4(0.f, 0.f, 0.f, 0.f);
                if (gk < K) {
                    v = *(const float4*)(A + (size_t)(rowBase + r) * lda + gk);
                    if (gk + 1 >= K) v.y = 0.f;
                    if (gk + 2 >= K) v.z = 0.f;
                    if (gk + 3 >= K) v.w = 0.f;
                }
                aR[s] = v;
            }
        }
    };
    auto stA = [&](int buf) {
        #pragma unroll
        for (int s = 0; s < 2; s++) {
            int idx = tid + s * NT;
            if (idx < 768) {
                int r = idx & 127, kq = idx >> 7;
                float4 v = aR[s];
                int gk = aK[s];
                if (BN_IN) {
                    v.x = fmaxf(fmaf(v.x, sm.scK[gk],     sm.shK[gk]),     0.f);
                    v.y = fmaxf(fmaf(v.y, sm.scK[gk + 1], sm.shK[gk + 1]), 0.f);
                    v.z = fmaxf(fmaf(v.z, sm.scK[gk + 2], sm.shK[gk + 2]), 0.f);
                    v.w = fmaxf(fmaf(v.w, sm.scK[gk + 3], sm.shK[gk + 3]), 0.f);
                }
                int k0 = kq * 4;
                tA[buf][k0    ][r] = v.x;
                tA[buf][k0 + 1][r] = v.y;
                tA[buf][k0 + 2][r] = v.z;
                tA[buf][k0 + 3][r] = v.w;
            }
        }
    };
    auto ldW = [&](int kbase) {
        if (tid < 96) {
            int kk = tid >> 2, n4 = (tid & 3) * 4;
            int gk = kbase + kk;
            #pragma unroll
            for (int j = 0; j < 4; j++) {
                int gn = colBase + n4 + j;
                wRv[j] = (gk < K && gn < N) ? W[(size_t)gk * ldw + gn] : 0.f;
            }
        }
    };
    auto stW = [&](int buf) {
        if (tid < 96) {
            int kk = tid >> 2, n4 = (tid & 3) * 4;
            #pragma unroll
            for (int j = 0; j < 4; j++) tW[buf][kk][n4 + j] = wRv[j];
        }
    };

    unsigned long long acc[2] = {};   // 4 cols for this thread's row
    auto comp = [&](int buf) {
        #pragma unroll 8
        for (int k = 0; k < KT; k++) {
            float a = tA[buf][k][tr];
            ulonglong2 b = *(const ulonglong2*)&tW[buf][k][tcq * 4];
            unsigned long long aa = pack2(a, a);
            ffma2(acc[0], aa, b.x);
            ffma2(acc[1], aa, b.y);
        }
    };

    ldA(0); ldW(0);
    if (BN_IN) __syncthreads();
    stA(0); stW(0);
    __syncthreads();
    for (int kt = 0; kt < nkt; kt++) {
        int buf = kt & 1;
        if (kt + 1 < nkt) { ldA((kt + 1) * KT); ldW((kt + 1) * KT); }
        comp(buf);
        if (kt + 1 < nkt) { stA(buf ^ 1); stW(buf ^ 1); }
        __syncthreads();
    }

    float v[4];
    v[0] = f2lo(acc[0]); v[1] = f2hi(acc[0]);
    v[2] = f2lo(acc[1]); v[3] = f2hi(acc[1]);
    #pragma unroll
    for (int j = 0; j < 4; j++) {
        int gn = colBase + tcq * 4 + j;
        if (gn < N) {
            v[j] += bias[gn];
            C[(size_t)(rowBase + tr) * ldc + gn] = v[j];
        } else v[j] = 0.f;
    }
    float (*rt)[16] = (float (*)[16])sm.As2;   // 128 x 16 values
    __syncthreads();
    #pragma unroll
    for (int j = 0; j < 4; j++) rt[tr][tcq * 4 + j] = v[j];
    __syncthreads();
    if (tid < 16) {
        float s = 0.f, q = 0.f;
        for (int j = 0; j < 128; j++) { float t = rt[j][tid]; s += t; q += t * t; }
        int gn = colBase + tid;
        if (gn < N) { atomicAdd(&osum[gn], s); atomicAdd(&osq[gn], q); }
    }
}

// ---------------- single persistent kernel ----------------
__global__ __launch_bounds__(NT, 1)
void mega_kernel(const float* __restrict__ x, const float* __restrict__ dW,
                 const float* __restrict__ law, const float* __restrict__ tg,
                 const float* __restrict__ W1, const float* __restrict__ b1,
                 const float* __restrict__ g1, const float* __restrict__ be1,
                 const float* __restrict__ W2, const float* __restrict__ b2,
                 const float* __restrict__ g2, const float* __restrict__ be2,
                 const float* __restrict__ W3, const float* __restrict__ b3,
                 const float* __restrict__ Wv1, const float* __restrict__ bv1,
                 const float* __restrict__ gv1, const float* __restrict__ bev1,
                 const float* __restrict__ Wv2, const float* __restrict__ bv2,
                 const float* __restrict__ gv2, const float* __restrict__ bev2,
                 const float* __restrict__ Wv3, const float* __restrict__ bv3,
                 const float* __restrict__ gv3, const float* __restrict__ bev3,
                 float* __restrict__ V)
{
    __shared__ SMT sm;
    const int cta = blockIdx.x;
    const int tid = threadIdx.x;
    unsigned bar = 0;
    const int myRow = (cta & 31) * 64;
    const int myCol = (cta >> 5) * 64;

    // phase 0: zero stats, copy X = x
    if (cta == 0) for (int j = tid; j < 288; j += NT) { g_S1[j] = 0.f; g_Q1[j] = 0.f; }
    if (cta == 1) for (int j = tid; j < 288; j += NT) { g_S2[j] = 0.f; g_Q2[j] = 0.f; }
    if (cta == 2 && tid < 4) { g_SC[tid] = 0.f; g_QC[tid] = 0.f; }
    {
        const float4* xs = (const float4*)x;
        float4* xd = (float4*)g_X;
        for (int idx = cta * NT + tid; idx < BB * DD / 4; idx += NCTA * NT) xd[idx] = xs[idx];
    }
    gridbar(bar);

    // v0 layer 1
    if (cta < 128)
        gemm_full<false, true, false, false, true>(sm, myRow, myCol,
            g_X, DD, DD, Wv1, HH, HH, bv1, nullptr, nullptr, nullptr, nullptr,
            g_Y1, HP, g_S1, g_Q1, nullptr, 0.f, 0.f, nullptr, nullptr, nullptr);
    else if (cta < 144)
        gemm_thin<false>(sm, (cta - 128) * 128, 256, g_X, DD, DD, Wv1, HH, HH, bv1,
            nullptr, nullptr, nullptr, nullptr, g_Y1, HP, g_S1, g_Q1);
    gridbar(bar);

    // v0 layer 2
    if (cta < 128)
        gemm_full<true, true, false, false, true>(sm, myRow, myCol,
            g_Y1, HP, HH, Wv2, HH, HH, bv2, gv1, bev1, g_S1, g_Q1,
            g_Y2, HP, g_S2, g_Q2, nullptr, 0.f, 0.f, nullptr, nullptr, nullptr);
    else if (cta < 144)
        gemm_thin<true>(sm, (cta - 128) * 128, 256, g_Y1, HP, HH, Wv2, HH, HH, bv2,
            gv1, bev1, g_S1, g_Q1, g_Y2, HP, g_S2, g_Q2);
    gridbar(bar);

    // v0 layer 3 (N=1)
    if (cta < 32)
        gemm_full<true, true, false, false, true>(sm, cta * 64, 0,
            g_Y2, HP, HH, Wv3, 1, 1, bv3, gv2, bev2, g_S2, g_Q2,
            g_Yv3, 1, g_SC, g_QC, nullptr, 0.f, 0.f, nullptr, nullptr, nullptr);
    gridbar(bar);

    // v0 finalize + re-zero stats for step 0
    {
        int r = cta * NT + tid;
        if (r < BB) {
            float invB = 1.f / (float)BB;
            float mu  = g_SC[0] * invB;
            float var = g_QC[0] * invB - mu * mu;
            float rstd = rsqrtf(var + EPSBN);
            V[r] = fmaxf(gv3[0] * (g_Yv3[r] - mu) * rstd + bev3[0], 0.f);
        }
        if (cta == 8) for (int j = tid; j < 288; j += NT) { g_S1[j] = 0.f; g_Q1[j] = 0.f; }
        if (cta == 9) for (int j = tid; j < 288; j += NT) { g_S2[j] = 0.f; g_Q2[j] = 0.f; }
    }
    gridbar(bar);

    #pragma unroll 1
    for (int i = 0; i < SS; i++) {
        float h  = tg[i + 1] - tg[i];
        float cs = SIGMA_C * sqrtf(h);
        const float* w1i = W1 + (size_t)i * DD * HH;
        const float* w2i = W2 + (size_t)i * HH * HH;
        const float* w3i = W3 + (size_t)i * HH * DD;

        // layer 1: X -> Y1, stats S1/Q1, F1 term into V
        if (cta < 128)
            gemm_full<false, true, true, false, true>(sm, myRow, myCol,
                g_X, DD, DD, w1i, HH, HH, b1 + (size_t)i * HH,
                nullptr, nullptr, nullptr, nullptr,
                g_Y1, HP, g_S1, g_Q1,
                law + (size_t)i * DD, h, cs, V, nullptr, nullptr);
        else if (cta < 144)
            gemm_thin<false>(sm, (cta - 128) * 128, 256, g_X, DD, DD, w1i, HH, HH,
                b1 + (size_t)i * HH, nullptr, nullptr, nullptr, nullptr,
                g_Y1, HP, g_S1, g_Q1);
        else if (cta == 147)
            for (int j = tid; j < 288; j += NT) { g_S2[j] = 0.f; g_Q2[j] = 0.f; }
        gridbar(bar);

        // layer 2: BN(Y1) -> Y2, stats S2/Q2
        if (cta < 128)
            gemm_full<true, true, false, false, true>(sm, myRow, myCol,
                g_Y1, HP, HH, w2i, HH, HH, b2 + (size_t)i * HH,
                g1 + (size_t)i * HH, be1 + (size_t)i * HH, g_S1, g_Q1,
                g_Y2, HP, g_S2, g_Q2, nullptr, 0.f, 0.f, nullptr, nullptr, nullptr);
        else if (cta < 144)
            gemm_thin<true>(sm, (cta - 128) * 128, 256, g_Y1, HP, HH, w2i, HH, HH,
                b2 + (size_t)i * HH, g1 + (size_t)i * HH, be1 + (size_t)i * HH,
                g_S1, g_Q1, g_Y2, HP, g_S2, g_Q2);
        gridbar(bar);

        // layer 3: BN(Y2) -> grad; fused SDE update of X and V
        if (cta < 128)
            gemm_full<true, false, false, true, false>(sm, myRow, myCol,
                g_Y2, HP, HH, w3i, DD, DD, b3 + (size_t)i * DD,
                g2 + (size_t)i * HH, be2 + (size_t)i * HH, g_S2, g_Q2,
                nullptr, 0, nullptr, nullptr,
                nullptr, h, cs, V, g_X, dW + (size_t)i * BB * DD);
        else if (cta == 128)
            for (int j = tid; j < 288; j += NT) { g_S1[j] = 0.f; g_Q1[j] = 0.f; }
        gridbar(bar);
    }

    // reset barrier state for next launch (handshake so nobody is still spinning)
    if (tid == 0) {
        __threadfence();
        atomicAdd(&g_done, 1u);
        if (cta == 0) {
            while (*(volatile unsigned*)&g_done < NCTA) { }
            g_barctr = 0u;
            __threadfence();
            g_done = 0u;
        }
    }
}

// ---------------- host launcher ----------------
extern "C" void kernel_launch(void* const* d_in, const int* in_sizes, int n_in,
                              void* d_out, int out_size)
{
    const float* x    = (const float*)d_in[0];
    const float* dW   = (const float*)d_in[1];
    const float* law  = (const float*)d_in[2];
    const float* tg   = (const float*)d_in[3];
    const float* W1   = (const float*)d_in[4];
    const float* b1   = (const float*)d_in[5];
    const float* g1   = (const float*)d_in[6];
    const float* be1  = (const float*)d_in[7];
    const float* W2   = (const float*)d_in[8];
    const float* b2   = (const float*)d_in[9];
    const float* g2   = (const float*)d_in[10];
    const float* be2  = (const float*)d_in[11];
    const float* W3   = (const float*)d_in[12];
    const float* b3   = (const float*)d_in[13];
    const float* Wv1  = (const float*)d_in[14];
    const float* bv1  = (const float*)d_in[15];
    const float* gv1  = (const float*)d_in[16];
    const float* bev1 = (const float*)d_in[17];
    const float* Wv2  = (const float*)d_in[18];
    const float* bv2  = (const float*)d_in[19];
    const float* gv2  = (const float*)d_in[20];
    const float* bev2 = (const float*)d_in[21];
    const float* Wv3  = (const float*)d_in[22];
    const float* bv3  = (const float*)d_in[23];
    const float* gv3  = (const float*)d_in[24];
    const float* bev3 = (const float*)d_in[25];
    float* V = (float*)d_out;

    mega_kernel<<<NCTA, NT>>>(x, dW, law, tg,
                              W1, b1, g1, be1, W2, b2, g2, be2, W3, b3,
                              Wv1, bv1, gv1, bev1, Wv2, bv2, gv2, bev2,
                              Wv3, bv3, gv3, bev3, V);
    (void)in_sizes; (void)n_in; (void)out_size;
}

// round 9
// speedup vs baseline: 1.9464x; 1.2434x over previous
#include <cuda_runtime.h>
#include <cuda_bf16.h>
#include <math.h>
#include <stdint.h>

#define NCTA 148
#define NT   512
#define BB   2048
#define DD   256
#define HH   266
#define HP   272
#define SS   50
#define EPSBN 1e-5f
#define SIGMA_C 0.3f
#define KC   64

// smem byte offsets (half tiles padded to 72 halfs/row; Cs stride 68 floats)
#define OF_AH 0
#define OF_AL 18432
#define OF_BH 36864
#define OF_BL 46080
#define OF_CS 55296
#define OF_SC 90112
#define OF_SH 91200
#define SMEM_DYN 92288

// ---------------- device scratch ----------------
__device__ float g_X[BB * DD];
__device__ float g_Y1[BB * HP];
__device__ float g_Y2[BB * HP];
__device__ float g_Yv3[BB];
__device__ __nv_bfloat16 g_Wt1hi[SS * HH * DD], g_Wt1lo[SS * HH * DD];
__device__ __nv_bfloat16 g_Wt2hi[SS * HH * HP], g_Wt2lo[SS * HH * HP];
__device__ __nv_bfloat16 g_Wt3hi[SS * DD * HP], g_Wt3lo[SS * DD * HP];
__device__ __nv_bfloat16 g_Wv1hi[HH * DD], g_Wv1lo[HH * DD];
__device__ __nv_bfloat16 g_Wv2hi[HH * HP], g_Wv2lo[HH * HP];
__device__ __nv_bfloat16 g_Wv3hi[HP],      g_Wv3lo[HP];
__device__ float g_S1[HP], g_Q1[HP], g_S2[HP], g_Q2[HP], g_SC[1], g_QC[1];
__device__ unsigned g_barctr, g_done;

// ---------------- PTX helpers ----------------
__device__ __forceinline__ uint32_t smem_u32(const void* p) {
    uint32_t a;
    asm("{ .reg .u64 t; cvta.to.shared.u64 t, %1; cvt.u32.u64 %0, t; }" : "=r"(a) : "l"(p));
    return a;
}
#define LDSM4(r, addr) \
    asm volatile("ldmatrix.sync.aligned.m8n8.x4.shared.b16 {%0,%1,%2,%3}, [%4];" \
        : "=r"((r)[0]), "=r"((r)[1]), "=r"((r)[2]), "=r"((r)[3]) : "r"(addr))
#define MMA16816(c, a, b0_, b1_) \
    asm volatile("mma.sync.aligned.m16n8k16.row.col.f32.bf16.bf16.f32 " \
        "{%0,%1,%2,%3}, {%4,%5,%6,%7}, {%8,%9}, {%0,%1,%2,%3};" \
        : "+f"((c)[0]), "+f"((c)[1]), "+f"((c)[2]), "+f"((c)[3]) \
        : "r"((a)[0]), "r"((a)[1]), "r"((a)[2]), "r"((a)[3]), "r"(b0_), "r"(b1_))

__device__ __forceinline__ void gridbar(unsigned& cnt) {
    __syncthreads();
    if (threadIdx.x == 0) {
        __threadfence();
        atomicAdd(&g_barctr, 1u);
        unsigned target = (++cnt) * NCTA;
        while (*(volatile unsigned*)&g_barctr < target) { }
        __threadfence();
    }
    __syncthreads();
}

// ---------------- transpose + split ----------------
__device__ void tsplit(const float* __restrict__ src, int K, int N,
                       __nv_bfloat16* __restrict__ dh, __nv_bfloat16* __restrict__ dl,
                       int ldT, float (*ts)[33]) {
    int ktiles = (ldT + 31) >> 5, ntiles = (N + 31) >> 5;
    for (int t = 0; t < ktiles * ntiles; t++) {
        int kt = t / ntiles, nt = t - kt * ntiles;
        int k0 = kt << 5, n0 = nt << 5;
        __syncthreads();
        #pragma unroll
        for (int s2 = 0; s2 < 2; s2++) {
            int idx = s2 * NT + threadIdx.x;
            int r = idx >> 5, c = idx & 31;
            int k = k0 + r, n = n0 + c;
            ts[r][c] = (k < K && n < N) ? src[(size_t)k * N + n] : 0.f;
        }
        __syncthreads();
        #pragma unroll
        for (int s2 = 0; s2 < 2; s2++) {
            int idx = s2 * NT + threadIdx.x;
            int rr = idx >> 5, cc = idx & 31;
            int n = n0 + rr, k = k0 + cc;
            if (n < N && k < ldT) {
                float v = ts[cc][rr];
                __nv_bfloat16 hb = __float2bfloat16(v);
                dh[(size_t)n * ldT + k] = hb;
                dl[(size_t)n * ldT + k] = __float2bfloat16(v - __bfloat162float(hb));
            }
        }
    }
}

// ---------------- HMMA GEMM phase (128x64 tile, 16 warps) ----------------
// MODE 0: C fp32 + column stats. MODE 1: fused SDE X/V update. MODE 2: N=1 v0 head.
template<int MODE, bool BN>
__device__ __noinline__ void mma_gemm(char* alp, uint32_t sbase,
    int rowBase, int cb,
    const float* __restrict__ A, int ldA, int K, int Ksteps,
    const __nv_bfloat16* __restrict__ Bh, const __nv_bfloat16* __restrict__ Bl, int Nout,
    const float* __restrict__ bias,
    const float* __restrict__ bng, const float* __restrict__ bnb,
    const float* __restrict__ ssum, const float* __restrict__ ssq,
    float* __restrict__ C, int ldc, float* osum, float* osq,
    float hstep, float cstep, float* __restrict__ V,
    float* __restrict__ X, const float* __restrict__ dWi, const float* __restrict__ lawi)
{
    const int tid = threadIdx.x;
    const int lane = tid & 31;
    const int warp = tid >> 5;
    const int mr = warp & 7;    // row block: rows mr*16..+15
    const int nc = warp >> 3;   // col half:  cols nc*32..+31
    float* scK = (float*)(alp + OF_SC);
    float* shK = (float*)(alp + OF_SH);

    if (BN) {
        const float invB = 1.f / (float)BB;
        for (int k = tid; k < HP; k += NT) {
            if (k < K) {
                float mu  = ssum[k] * invB;
                float var = ssq[k] * invB - mu * mu;
                float rstd = rsqrtf(var + EPSBN);
                float sc = bng[k] * rstd;
                scK[k] = sc; shK[k] = bnb[k] - mu * sc;
            } else { scK[k] = 0.f; shK[k] = 0.f; }
        }
        __syncthreads();
    }

    float acc[4][4] = {};
    const int nch = (Ksteps + KC - 1) / KC;
    for (int ch = 0; ch < nch; ch++) {
        const int k0 = ch * KC;
        // ---- load A chunk: 128 rows x KC, fp32 -> BN/ReLU -> bf16 hi/lo ----
        #pragma unroll
        for (int it = 0; it < 2; it++) {
            int idx = it * NT + tid;
            int row = idx >> 3, kg = idx & 7;
            int gk = k0 + kg * 8;
            union { __nv_bfloat16 h[8]; uint4 u; } th, tl;
            if (gk < Ksteps) {
                const float* ap = A + (size_t)(rowBase + row) * ldA + gk;
                float4 v0 = *(const float4*)ap;
                float4 v1 = *(const float4*)(ap + 4);
                float vv[8] = {v0.x, v0.y, v0.z, v0.w, v1.x, v1.y, v1.z, v1.w};
                #pragma unroll
                for (int e = 0; e < 8; e++) {
                    float v = vv[e];
                    if (BN) v = fmaxf(fmaf(v, scK[gk + e], shK[gk + e]), 0.f);
                    __nv_bfloat16 hb = __float2bfloat16(v);
                    th.h[e] = hb;
                    tl.h[e] = __float2bfloat16(v - __bfloat162float(hb));
                }
            } else { th.u = make_uint4(0, 0, 0, 0); tl.u = th.u; }
            uint32_t off = (uint32_t)(row * 72 + kg * 8) * 2u;
            *(uint4*)(alp + OF_AH + off) = th.u;
            *(uint4*)(alp + OF_AL + off) = tl.u;
        }
        // ---- load B chunk: 64 n-rows x KC (pre-split bf16, K-major) ----
        {
            int row = tid >> 3, kg = tid & 7;
            int gk = k0 + kg * 8;
            int n = cb + row;
            uint4 uh = make_uint4(0, 0, 0, 0), ul = uh;
            if (gk < Ksteps && n < Nout) {
                uh = *(const uint4*)(Bh + (size_t)n * Ksteps + gk);
                ul = *(const uint4*)(Bl + (size_t)n * Ksteps + gk);
            }
            uint32_t off = (uint32_t)(row * 72 + kg * 8) * 2u;
            *(uint4*)(alp + OF_BH + off) = uh;
            *(uint4*)(alp + OF_BL + off) = ul;
        }
        __syncthreads();

        int ns = (Ksteps - k0) >> 4; if (ns > KC / 16) ns = KC / 16;
        for (int kk = 0; kk < ns; kk++) {
            const int k16 = kk * 16;
            uint32_t ah[4], al[4], bh[2][4], bl[2][4];
            {
                uint32_t ao = sbase + OF_AH +
                    2u * (uint32_t)((mr * 16 + (lane & 15)) * 72 + k16 + ((lane >> 4) << 3));
                LDSM4(ah, ao);
                LDSM4(al, ao + (OF_AL - OF_AH));
            }
            #pragma unroll
            for (int nh = 0; nh < 2; nh++) {
                uint32_t bo = sbase + OF_BH +
                    2u * (uint32_t)((nc * 32 + nh * 16 + ((lane >> 3) & 1) * 8 + (lane & 7)) * 72
                                    + k16 + ((lane >> 4) << 3));
                LDSM4(bh[nh], bo);
                LDSM4(bl[nh], bo + (OF_BL - OF_BH));
            }
            #pragma unroll
            for (int t = 0; t < 4; t++) {
                uint32_t b0h = bh[t >> 1][t & 1], b1h = bh[t >> 1][(t & 1) + 2];
                uint32_t b0l = bl[t >> 1][t & 1], b1l = bl[t >> 1][(t & 1) + 2];
                MMA16816(acc[t], ah, b0h, b1h);
                MMA16816(acc[t], al, b0h, b1h);
                MMA16816(acc[t], ah, b0l, b1l);
            }
        }
        __syncthreads();
    }

    // ---- store fragments to Cs [128][68] ----
    float* Cs = (float*)(alp + OF_CS);
    {
        int r0 = mr * 16 + (lane >> 2);
        #pragma unroll
        for (int t = 0; t < 4; t++) {
            int cl = nc * 32 + t * 8 + (lane & 3) * 2;
            Cs[r0 * 68 + cl]           = acc[t][0];
            Cs[r0 * 68 + cl + 1]       = acc[t][1];
            Cs[(r0 + 8) * 68 + cl]     = acc[t][2];
            Cs[(r0 + 8) * 68 + cl + 1] = acc[t][3];
        }
    }
    __syncthreads();

    if (MODE == 0) {
        // bias + write C (coalesced), re-store biased values
        for (int idx = tid; idx < 128 * 64; idx += NT) {
            int row = idx >> 6, col = idx & 63;
            int gn = cb + col;
            float v = 0.f;
            if (gn < Nout) {
                v = Cs[row * 68 + col] + bias[gn];
                C[(size_t)(rowBase + row) * ldc + gn] = v;
            }
            Cs[row * 68 + col] = v;
        }
        __syncthreads();
        // column stats: 64 cols x 8 segments of 16 rows
        float* red2 = (float*)(alp + OF_AH);
        {
            int col = tid & 63, seg = tid >> 6;
            float s = 0.f, q = 0.f;
            #pragma unroll
            for (int r16 = 0; r16 < 16; r16++) {
                float v = Cs[(seg * 16 + r16) * 68 + col];
                s += v; q += v * v;
            }
            red2[seg * 64 + col] = s;
            red2[512 + seg * 64 + col] = q;
        }
        __syncthreads();
        if (tid < 64) {
            float s = 0.f, q = 0.f;
            #pragma unroll
            for (int g = 0; g < 8; g++) { s += red2[g * 64 + tid]; q += red2[512 + g * 64 + tid]; }
            int gn = cb + tid;
            if (gn < Nout) { atomicAdd(&osum[gn], s); atomicAdd(&osq[gn], q); }
        }
        __syncthreads();
    } else if (MODE == 1) {
        // fused SDE: row = tid>>2 (128 rows), each thread 16 cols
        int row = tid >> 2, quad = tid & 3;
        size_t rbo = (size_t)(rowBase + row) * DD + cb + quad * 16;
        float p1 = 0.f, p2 = 0.f, p3 = 0.f;
        #pragma unroll
        for (int j4 = 0; j4 < 4; j4++) {
            int cl = quad * 16 + j4 * 4;
            int gc = cb + cl;
            float4 bj = *(const float4*)(bias + gc);
            float4 xv = *(const float4*)(X + rbo + j4 * 4);
            float4 dv = *(const float4*)(dWi + rbo + j4 * 4);
            float4 lw = *(const float4*)(lawi + gc);
            float q0 = Cs[row * 68 + cl]     + bj.x;
            float q1 = Cs[row * 68 + cl + 1] + bj.y;
            float q2 = Cs[row * 68 + cl + 2] + bj.z;
            float q3 = Cs[row * 68 + cl + 3] + bj.w;
            float n0 = cstep * dv.x, n1 = cstep * dv.y;
            float n2 = cstep * dv.z, n3 = cstep * dv.w;
            float d0 = xv.x - lw.x, d1 = xv.y - lw.y;
            float d2 = xv.z - lw.z, d3 = xv.w - lw.w;
            p1 += d0 * d0 + d1 * d1 + d2 * d2 + d3 * d3;
            p2 += q0 * q0 + q1 * q1 + q2 * q2 + q3 * q3;
            p3 += q0 * n0 + q1 * n1 + q2 * n2 + q3 * n3;
            float4 xo;
            xo.x = xv.x - q0 * hstep + n0;
            xo.y = xv.y - q1 * hstep + n1;
            xo.z = xv.z - q2 * hstep + n2;
            xo.w = xv.w - q3 * hstep + n3;
            *(float4*)(X + rbo + j4 * 4) = xo;
        }
        float t = -0.5f * hstep * (p1 + p2) + p3;
        t += __shfl_down_sync(0xffffffffu, t, 1);
        t += __shfl_down_sync(0xffffffffu, t, 2);
        if ((lane & 3) == 0) atomicAdd(&V[rowBase + row], t);
        __syncthreads();
    } else {   // MODE 2: N=1
        if (tid < 128) {
            float v = Cs[tid * 68] + bias[0];
            g_Yv3[rowBase + tid] = v;
            float s = v, q = v * v;
            #pragma unroll
            for (int o = 16; o > 0; o >>= 1) {
                s += __shfl_down_sync(0xffffffffu, s, o);
                q += __shfl_down_sync(0xffffffffu, q, o);
            }
            if ((tid & 31) == 0) { atomicAdd(&g_SC[0], s); atomicAdd(&g_QC[0], q); }
        }
        __syncthreads();
    }
}

// ---------------- single persistent kernel ----------------
extern "C" __global__ void __launch_bounds__(NT, 1)
mega_kernel(const float* __restrict__ x, const float* __restrict__ dW,
            const float* __restrict__ law, const float* __restrict__ tg,
            const float* __restrict__ W1, const float* __restrict__ b1,
            const float* __restrict__ g1, const float* __restrict__ be1,
            const float* __restrict__ W2, const float* __restrict__ b2,
            const float* __restrict__ g2, const float* __restrict__ be2,
            const float* __restrict__ W3, const float* __restrict__ b3,
            const float* __restrict__ Wv1, const float* __restrict__ bv1,
            const float* __restrict__ gv1, const float* __restrict__ bev1,
            const float* __restrict__ Wv2, const float* __restrict__ bv2,
            const float* __restrict__ gv2, const float* __restrict__ bev2,
            const float* __restrict__ Wv3, const float* __restrict__ bv3,
            const float* __restrict__ gv3, const float* __restrict__ bev3,
            float* __restrict__ V)
{
    extern __shared__ char dsm[];
    const int cta = blockIdx.x;
    const int tid = threadIdx.x;
    char* alp = dsm;
    uint32_t sbase = smem_u32(dsm);
    unsigned bar = 0;
    const int rb = (cta & 15) * 128;
    const int cb = (cta >> 4) * 64;

    // ---- P0: stats zero, X copy, weight transpose+split ----
    if (cta == 0) {
        for (int j = tid; j < HP; j += NT) { g_S1[j] = 0.f; g_Q1[j] = 0.f; g_S2[j] = 0.f; g_Q2[j] = 0.f; }
        if (tid == 0) { g_SC[0] = 0.f; g_QC[0] = 0.f; }
    }
    {
        const float4* xs = (const float4*)x;
        float4* xd = (float4*)g_X;
        for (int idx = cta * NT + tid; idx < BB * DD / 4; idx += NCTA * NT) xd[idx] = xs[idx];
    }
    {
        float (*ts)[33] = (float (*)[33])alp;
        for (int m = cta; m < 153; m += NCTA) {
            if (m < 50)
                tsplit(W1 + (size_t)m * DD * HH, DD, HH,
                       g_Wt1hi + (size_t)m * HH * DD, g_Wt1lo + (size_t)m * HH * DD, DD, ts);
            else if (m < 100)
                tsplit(W2 + (size_t)(m - 50) * HH * HH, HH, HH,
                       g_Wt2hi + (size_t)(m - 50) * HH * HP, g_Wt2lo + (size_t)(m - 50) * HH * HP, HP, ts);
            else if (m < 150)
                tsplit(W3 + (size_t)(m - 100) * HH * DD, HH, DD,
                       g_Wt3hi + (size_t)(m - 100) * DD * HP, g_Wt3lo + (size_t)(m - 100) * DD * HP, HP, ts);
            else if (m == 150) tsplit(Wv1, DD, HH, g_Wv1hi, g_Wv1lo, DD, ts);
            else if (m == 151) tsplit(Wv2, HH, HH, g_Wv2hi, g_Wv2lo, HP, ts);
            else               tsplit(Wv3, HH, 1,  g_Wv3hi, g_Wv3lo, HP, ts);
        }
    }
    gridbar(bar);

    // ---- v0 L1 ----
    if (cta < 80)
        mma_gemm<0, false>(alp, sbase, rb, cb,
            g_X, DD, 256, 256, g_Wv1hi, g_Wv1lo, HH, bv1,
            0, 0, 0, 0, g_Y1, HP, g_S1, g_Q1, 0, 0, 0, 0, 0, 0);
    gridbar(bar);
    // ---- v0 L2 ----
    if (cta < 80)
        mma_gemm<0, true>(alp, sbase, rb, cb,
            g_Y1, HP, 266, 272, g_Wv2hi, g_Wv2lo, HH, bv2,
            gv1, bev1, g_S1, g_Q1, g_Y2, HP, g_S2, g_Q2, 0, 0, 0, 0, 0, 0);
    gridbar(bar);
    // ---- v0 L3 (N=1) ----
    if (cta < 16)
        mma_gemm<2, true>(alp, sbase, cta * 128, 0,
            g_Y2, HP, 266, 272, g_Wv3hi, g_Wv3lo, 1, bv3,
            gv2, bev2, g_S2, g_Q2, 0, 0, 0, 0, 0, 0, 0, 0, 0, 0);
    else if (cta == 100)
        for (int j = tid; j < HP; j += NT) { g_S1[j] = 0.f; g_Q1[j] = 0.f; }
    gridbar(bar);
    // ---- v0 finalize ----
    {
        int r = cta * NT + tid;
        if (r < BB) {
            float invB = 1.f / (float)BB;
            float mu  = g_SC[0] * invB;
            float var = g_QC[0] * invB - mu * mu;
            float rstd = rsqrtf(var + EPSBN);
            V[r] = fmaxf(gv3[0] * (g_Yv3[r] - mu) * rstd + bev3[0], 0.f);
        }
        if (cta == 8)
            for (int j = tid; j < HP; j += NT) { g_S2[j] = 0.f; g_Q2[j] = 0.f; }
    }
    gridbar(bar);

    #pragma unroll 1
    for (int i = 0; i < SS; i++) {
        float h  = tg[i + 1] - tg[i];
        float cs = SIGMA_C * sqrtf(h);
        // ---- L1: X -> Y1 + S1/Q1 ----
        if (cta < 80)
            mma_gemm<0, false>(alp, sbase, rb, cb,
                g_X, DD, 256, 256,
                g_Wt1hi + (size_t)i * HH * DD, g_Wt1lo + (size_t)i * HH * DD, HH,
                b1 + (size_t)i * HH, 0, 0, 0, 0,
                g_Y1, HP, g_S1, g_Q1, 0, 0, 0, 0, 0, 0);
        else if (cta == 147)
            for (int j = tid; j < HP; j += NT) { g_S2[j] = 0.f; g_Q2[j] = 0.f; }
        gridbar(bar);
        // ---- L2: BN(Y1) -> Y2 + S2/Q2 ----
        if (cta < 80)
            mma_gemm<0, true>(alp, sbase, rb, cb,
                g_Y1, HP, 266, 272,
                g_Wt2hi + (size_t)i * HH * HP, g_Wt2lo + (size_t)i * HH * HP, HH,
                b2 + (size_t)i * HH, g1 + (size_t)i * HH, be1 + (size_t)i * HH, g_S1, g_Q1,
                g_Y2, HP, g_S2, g_Q2, 0, 0, 0, 0, 0, 0);
        gridbar(bar);
        // ---- L3: BN(Y2) -> grad; fused SDE update ----
        if (cta < 64)
            mma_gemm<1, true>(alp, sbase, rb, cb,
                g_Y2, HP, 266, 272,
                g_Wt3hi + (size_t)i * DD * HP, g_Wt3lo + (size_t)i * DD * HP, DD,
                b3 + (size_t)i * DD, g2 + (size_t)i * HH, be2 + (size_t)i * HH, g_S2, g_Q2,
                0, 0, 0, 0, h, cs, V, g_X, dW + (size_t)i * BB * DD, law + (size_t)i * DD);
        else if (cta == 100)
            for (int j = tid; j < HP; j += NT) { g_S1[j] = 0.f; g_Q1[j] = 0.f; }
        gridbar(bar);
    }

    if (tid == 0) {
        __threadfence();
        atomicAdd(&g_done, 1u);
        if (cta == 0) {
            while (*(volatile unsigned*)&g_done < NCTA) { }
            g_barctr = 0u;
            __threadfence();
            g_done = 0u;
        }
    }
}

// ---------------- host launcher ----------------
extern "C" void kernel_launch(void* const* d_in, const int* in_sizes, int n_in,
                              void* d_out, int out_size)
{
    cudaFuncSetAttribute((const void*)mega_kernel,
                         cudaFuncAttributeMaxDynamicSharedMemorySize, SMEM_DYN);
    mega_kernel<<<NCTA, NT, SMEM_DYN>>>(
        (const float*)d_in[0], (const float*)d_in[1], (const float*)d_in[2], (const float*)d_in[3],
        (const float*)d_in[4],  (const float*)d_in[5],  (const float*)d_in[6],  (const float*)d_in[7],
        (const float*)d_in[8],  (const float*)d_in[9],  (const float*)d_in[10], (const float*)d_in[11],
        (const float*)d_in[12], (const float*)d_in[13],
        (const float*)d_in[14], (const float*)d_in[15], (const float*)d_in[16], (const float*)d_in[17],
        (const float*)d_in[18], (const float*)d_in[19], (const float*)d_in[20], (const float*)d_in[21],
        (const float*)d_in[22], (const float*)d_in[23], (const float*)d_in[24], (const float*)d_in[25],
        (float*)d_out);
    (void)in_sizes; (void)n_in; (void)out_size;
}

// round 10
// speedup vs baseline: 2.1585x; 1.1090x over previous
#include <cuda_runtime.h>
#include <cuda_bf16.h>
#include <math.h>
#include <stdint.h>

#define NCTA 148
#define NT   512
#define BB   2048
#define DD   256
#define HH   266
#define HP   272
#define SS   50
#define EPSBN 1e-5f
#define SIGMA_C 0.3f
#define KC   64

// smem layout (bytes): A: 2 bufs x (hi 18432 + lo 18432); B: 2 bufs x (hi 9216 + lo 9216)
#define ABUF(b)  ((b) * 36864)
#define ALO      18432
#define BBUF(b)  (73728 + (b) * 18432)
#define BLO      9216
#define OF_SC    110592
#define OF_SH    111744
#define OF_CS    0            // epilogue scratch aliases A buffers (post-sync)
#define SMEM_DYN 112896

// ---------------- device scratch ----------------
__device__ float g_X[BB * DD];
__device__ float g_Y1[BB * HP];
__device__ float g_Y2[BB * HP];
__device__ float g_Yv3[BB];
__device__ __nv_bfloat16 g_Wt1hi[SS * HH * DD], g_Wt1lo[SS * HH * DD];
__device__ __nv_bfloat16 g_Wt2hi[SS * HH * HP], g_Wt2lo[SS * HH * HP];
__device__ __nv_bfloat16 g_Wt3hi[SS * DD * HP], g_Wt3lo[SS * DD * HP];
__device__ __nv_bfloat16 g_Wv1hi[HH * DD], g_Wv1lo[HH * DD];
__device__ __nv_bfloat16 g_Wv2hi[HH * HP], g_Wv2lo[HH * HP];
__device__ __nv_bfloat16 g_Wv3hi[HP],      g_Wv3lo[HP];
__device__ float g_S1[HP], g_Q1[HP], g_S2[HP], g_Q2[HP], g_SC[1], g_QC[1];
__device__ unsigned g_barctr, g_done;

// ---------------- PTX helpers ----------------
__device__ __forceinline__ uint32_t smem_u32(const void* p) {
    uint32_t a;
    asm("{ .reg .u64 t; cvta.to.shared.u64 t, %1; cvt.u32.u64 %0, t; }" : "=r"(a) : "l"(p));
    return a;
}
#define LDSM4(r, addr) \
    asm volatile("ldmatrix.sync.aligned.m8n8.x4.shared.b16 {%0,%1,%2,%3}, [%4];" \
        : "=r"((r)[0]), "=r"((r)[1]), "=r"((r)[2]), "=r"((r)[3]) : "r"(addr))
#define MMA16816(c, a, b0_, b1_) \
    asm volatile("mma.sync.aligned.m16n8k16.row.col.f32.bf16.bf16.f32 " \
        "{%0,%1,%2,%3}, {%4,%5,%6,%7}, {%8,%9}, {%0,%1,%2,%3};" \
        : "+f"((c)[0]), "+f"((c)[1]), "+f"((c)[2]), "+f"((c)[3]) \
        : "r"((a)[0]), "r"((a)[1]), "r"((a)[2]), "r"((a)[3]), "r"(b0_), "r"(b1_))
#define CP16(dst, src) \
    asm volatile("cp.async.ca.shared.global [%0], [%1], 16;" :: "r"(dst), "l"(src) : "memory")
#define CP_COMMIT() asm volatile("cp.async.commit_group;" ::: "memory")
#define CP_WAIT0()  asm volatile("cp.async.wait_group 0;" ::: "memory")

__device__ __forceinline__ void gridbar(unsigned& cnt) {
    __syncthreads();
    if (threadIdx.x == 0) {
        __threadfence();
        atomicAdd(&g_barctr, 1u);
        unsigned target = (++cnt) * NCTA;
        while (*(volatile unsigned*)&g_barctr < target) { }
        __threadfence();
    }
    __syncthreads();
}

// ---------------- transpose + split ----------------
__device__ void tsplit(const float* __restrict__ src, int K, int N,
                       __nv_bfloat16* __restrict__ dh, __nv_bfloat16* __restrict__ dl,
                       int ldT, float (*ts)[33]) {
    int ktiles = (ldT + 31) >> 5, ntiles = (N + 31) >> 5;
    for (int t = 0; t < ktiles * ntiles; t++) {
        int kt = t / ntiles, nt = t - kt * ntiles;
        int k0 = kt << 5, n0 = nt << 5;
        __syncthreads();
        #pragma unroll
        for (int s2 = 0; s2 < 2; s2++) {
            int idx = s2 * NT + threadIdx.x;
            int r = idx >> 5, c = idx & 31;
            int k = k0 + r, n = n0 + c;
            ts[r][c] = (k < K && n < N) ? src[(size_t)k * N + n] : 0.f;
        }
        __syncthreads();
        #pragma unroll
        for (int s2 = 0; s2 < 2; s2++) {
            int idx = s2 * NT + threadIdx.x;
            int rr = idx >> 5, cc = idx & 31;
            int n = n0 + rr, k = k0 + cc;
            if (n < N && k < ldT) {
                float v = ts[cc][rr];
                __nv_bfloat16 hb = __float2bfloat16(v);
                dh[(size_t)n * ldT + k] = hb;
                dl[(size_t)n * ldT + k] = __float2bfloat16(v - __bfloat162float(hb));
            }
        }
    }
}

// ---------------- HMMA GEMM phase (128x64 tile, 16 warps, pipelined) --------
// MODE 0: C fp32 + column stats. MODE 1: fused SDE X/V update. MODE 2: N=1 v0 head.
template<int MODE, bool BN>
__device__ __noinline__ void mma_gemm(char* alp, uint32_t sbase,
    int rowBase, int cb,
    const float* __restrict__ A, int ldA, int K, int Ksteps,
    const __nv_bfloat16* __restrict__ Bh, const __nv_bfloat16* __restrict__ Bl, int Nout,
    const float* __restrict__ bias,
    const float* __restrict__ bng, const float* __restrict__ bnb,
    const float* __restrict__ ssum, const float* __restrict__ ssq,
    float* __restrict__ C, int ldc, float* osum, float* osq,
    float hstep, float cstep, float* __restrict__ V,
    float* __restrict__ X, const float* __restrict__ dWi, const float* __restrict__ lawi)
{
    const int tid = threadIdx.x;
    const int lane = tid & 31;
    const int warp = tid >> 5;
    const int mr = warp & 7;
    const int nc = warp >> 3;
    float* scK = (float*)(alp + OF_SC);
    float* shK = (float*)(alp + OF_SH);

    if (BN) {
        const float invB = 1.f / (float)BB;
        for (int k = tid; k < HP; k += NT) {
            if (k < K) {
                float mu  = ssum[k] * invB;
                float var = ssq[k] * invB - mu * mu;
                float rstd = rsqrtf(var + EPSBN);
                float sc = bng[k] * rstd;
                scK[k] = sc; shK[k] = bnb[k] - mu * sc;
            } else { scK[k] = 0.f; shK[k] = 0.f; }
        }
        __syncthreads();
    }

    const int nch = (Ksteps + KC - 1) / KC;
    float fa[16];   // staged A: 2 jobs x 8 floats

    auto ldAreg = [&](int ch) {
        const int k0 = ch * KC;
        #pragma unroll
        for (int it = 0; it < 2; it++) {
            int idx = it * NT + tid;
            int row = idx >> 3, kg = idx & 7;
            int gk = k0 + kg * 8;
            if (gk < Ksteps) {   // Ksteps % 8 == 0 -> all-or-nothing
                const float* ap = A + (size_t)(rowBase + row) * ldA + gk;
                float4 v0 = *(const float4*)ap;
                float4 v1 = *(const float4*)(ap + 4);
                fa[it*8+0] = v0.x; fa[it*8+1] = v0.y; fa[it*8+2] = v0.z; fa[it*8+3] = v0.w;
                fa[it*8+4] = v1.x; fa[it*8+5] = v1.y; fa[it*8+6] = v1.z; fa[it*8+7] = v1.w;
            } else {
                #pragma unroll
                for (int e = 0; e < 8; e++) fa[it*8+e] = 0.f;
            }
        }
    };
    auto stA = [&](int ch, int buf) {
        const int k0 = ch * KC;
        #pragma unroll
        for (int it = 0; it < 2; it++) {
            int idx = it * NT + tid;
            int row = idx >> 3, kg = idx & 7;
            int gk = k0 + kg * 8;
            union { __nv_bfloat16 h[8]; uint4 u; } th, tl;
            if (gk < Ksteps) {
                #pragma unroll
                for (int e = 0; e < 8; e++) {
                    float v = fa[it*8+e];
                    if (BN) v = fmaxf(fmaf(v, scK[gk + e], shK[gk + e]), 0.f);
                    __nv_bfloat16 hb = __float2bfloat16(v);
                    th.h[e] = hb;
                    tl.h[e] = __float2bfloat16(v - __bfloat162float(hb));
                }
            } else { th.u = make_uint4(0, 0, 0, 0); tl.u = th.u; }
            uint32_t off = (uint32_t)(row * 72 + kg * 8) * 2u;
            *(uint4*)(alp + ABUF(buf) + off) = th.u;
            *(uint4*)(alp + ABUF(buf) + ALO + off) = tl.u;
        }
    };
    auto cpB = [&](int ch, int buf) {
        const int k0 = ch * KC;
        int row = tid >> 3, kg = tid & 7;
        int gk = k0 + kg * 8;
        int n = cb + row;
        uint32_t off = (uint32_t)(row * 72 + kg * 8) * 2u;
        uint32_t d0 = sbase + BBUF(buf) + off;
        uint32_t d1 = d0 + BLO;
        if (gk < Ksteps && n < Nout) {
            CP16(d0, Bh + (size_t)n * Ksteps + gk);
            CP16(d1, Bl + (size_t)n * Ksteps + gk);
        } else {
            uint4 z = make_uint4(0, 0, 0, 0);
            *(uint4*)(alp + BBUF(buf) + off) = z;
            *(uint4*)(alp + BBUF(buf) + BLO + off) = z;
        }
    };

    float acc[4][4] = {};

    // prologue: stage chunk 0
    ldAreg(0);
    cpB(0, 0); CP_COMMIT();
    stA(0, 0);
    CP_WAIT0();
    __syncthreads();

    for (int ch = 0; ch < nch; ch++) {
        const int buf = ch & 1;
        const bool more = (ch + 1 < nch);
        if (more) { ldAreg(ch + 1); cpB(ch + 1, buf ^ 1); CP_COMMIT(); }

        int ns = (Ksteps - ch * KC) >> 4; if (ns > KC / 16) ns = KC / 16;
        for (int kk = 0; kk < ns; kk++) {
            const int k16 = kk * 16;
            uint32_t ah[4], al[4], bh[2][4], bl[2][4];
            {
                uint32_t ao = sbase + ABUF(buf) +
                    2u * (uint32_t)((mr * 16 + (lane & 15)) * 72 + k16 + ((lane >> 4) << 3));
                LDSM4(ah, ao);
                LDSM4(al, ao + ALO);
            }
            #pragma unroll
            for (int nh = 0; nh < 2; nh++) {
                uint32_t bo = sbase + BBUF(buf) +
                    2u * (uint32_t)((nc * 32 + nh * 16 + ((lane >> 3) & 1) * 8 + (lane & 7)) * 72
                                    + k16 + ((lane >> 4) << 3));
                LDSM4(bh[nh], bo);
                LDSM4(bl[nh], bo + BLO);
            }
            #pragma unroll
            for (int t = 0; t < 4; t++) {
                uint32_t b0h = bh[t >> 1][t & 1], b1h = bh[t >> 1][(t & 1) + 2];
                uint32_t b0l = bl[t >> 1][t & 1], b1l = bl[t >> 1][(t & 1) + 2];
                MMA16816(acc[t], ah, b0h, b1h);
                MMA16816(acc[t], al, b0h, b1h);
                MMA16816(acc[t], ah, b0l, b1l);
            }
        }

        if (more) stA(ch + 1, buf ^ 1);
        CP_WAIT0();
        __syncthreads();
    }

    // ---- epilogue: fragments -> Cs (aliases A buffers, all mma done) ----
    float* Cs = (float*)(alp + OF_CS);
    {
        int r0 = mr * 16 + (lane >> 2);
        #pragma unroll
        for (int t = 0; t < 4; t++) {
            int cl = nc * 32 + t * 8 + (lane & 3) * 2;
            Cs[r0 * 68 + cl]           = acc[t][0];
            Cs[r0 * 68 + cl + 1]       = acc[t][1];
            Cs[(r0 + 8) * 68 + cl]     = acc[t][2];
            Cs[(r0 + 8) * 68 + cl + 1] = acc[t][3];
        }
    }
    __syncthreads();

    if (MODE == 0) {
        for (int idx = tid; idx < 128 * 64; idx += NT) {
            int row = idx >> 6, col = idx & 63;
            int gn = cb + col;
            float v = 0.f;
            if (gn < Nout) {
                v = Cs[row * 68 + col] + bias[gn];
                C[(size_t)(rowBase + row) * ldc + gn] = v;
            }
            Cs[row * 68 + col] = v;
        }
        __syncthreads();
        float* red2 = (float*)(alp + 34816);
        {
            int col = tid & 63, seg = tid >> 6;
            float s = 0.f, q = 0.f;
            #pragma unroll
            for (int r16 = 0; r16 < 16; r16++) {
                float v = Cs[(seg * 16 + r16) * 68 + col];
                s += v; q += v * v;
            }
            red2[seg * 64 + col] = s;
            red2[512 + seg * 64 + col] = q;
        }
        __syncthreads();
        if (tid < 64) {
            float s = 0.f, q = 0.f;
            #pragma unroll
            for (int g = 0; g < 8; g++) { s += red2[g * 64 + tid]; q += red2[512 + g * 64 + tid]; }
            int gn = cb + tid;
            if (gn < Nout) { atomicAdd(&osum[gn], s); atomicAdd(&osq[gn], q); }
        }
        __syncthreads();
    } else if (MODE == 1) {
        int row = tid >> 2, quad = tid & 3;
        size_t rbo = (size_t)(rowBase + row) * DD + cb + quad * 16;
        float p1 = 0.f, p2 = 0.f, p3 = 0.f;
        #pragma unroll
        for (int j4 = 0; j4 < 4; j4++) {
            int cl = quad * 16 + j4 * 4;
            int gc = cb + cl;
            float4 bj = *(const float4*)(bias + gc);
            float4 xv = *(const float4*)(X + rbo + j4 * 4);
            float4 dv = *(const float4*)(dWi + rbo + j4 * 4);
            float4 lw = *(const float4*)(lawi + gc);
            float q0 = Cs[row * 68 + cl]     + bj.x;
            float q1 = Cs[row * 68 + cl + 1] + bj.y;
            float q2 = Cs[row * 68 + cl + 2] + bj.z;
            float q3 = Cs[row * 68 + cl + 3] + bj.w;
            float n0 = cstep * dv.x, n1 = cstep * dv.y;
            float n2 = cstep * dv.z, n3 = cstep * dv.w;
            float d0 = xv.x - lw.x, d1 = xv.y - lw.y;
            float d2 = xv.z - lw.z, d3 = xv.w - lw.w;
            p1 += d0 * d0 + d1 * d1 + d2 * d2 + d3 * d3;
            p2 += q0 * q0 + q1 * q1 + q2 * q2 + q3 * q3;
            p3 += q0 * n0 + q1 * n1 + q2 * n2 + q3 * n3;
            float4 xo;
            xo.x = xv.x - q0 * hstep + n0;
            xo.y = xv.y - q1 * hstep + n1;
            xo.z = xv.z - q2 * hstep + n2;
            xo.w = xv.w - q3 * hstep + n3;
            *(float4*)(X + rbo + j4 * 4) = xo;
        }
        float t = -0.5f * hstep * (p1 + p2) + p3;
        t += __shfl_down_sync(0xffffffffu, t, 1);
        t += __shfl_down_sync(0xffffffffu, t, 2);
        if ((lane & 3) == 0) atomicAdd(&V[rowBase + row], t);
        __syncthreads();
    } else {
        if (tid < 128) {
            float v = Cs[tid * 68] + bias[0];
            g_Yv3[rowBase + tid] = v;
            float s = v, q = v * v;
            #pragma unroll
            for (int o = 16; o > 0; o >>= 1) {
                s += __shfl_down_sync(0xffffffffu, s, o);
                q += __shfl_down_sync(0xffffffffu, q, o);
            }
            if ((tid & 31) == 0) { atomicAdd(&g_SC[0], s); atomicAdd(&g_QC[0], q); }
        }
        __syncthreads();
    }
}

// ---------------- single persistent kernel ----------------
extern "C" __global__ void __launch_bounds__(NT, 1)
mega_kernel(const float* __restrict__ x, const float* __restrict__ dW,
            const float* __restrict__ law, const float* __restrict__ tg,
            const float* __restrict__ W1, const float* __restrict__ b1,
            const float* __restrict__ g1, const float* __restrict__ be1,
            const float* __restrict__ W2, const float* __restrict__ b2,
            const float* __restrict__ g2, const float* __restrict__ be2,
            const float* __restrict__ W3, const float* __restrict__ b3,
            const float* __restrict__ Wv1, const float* __restrict__ bv1,
            const float* __restrict__ gv1, const float* __restrict__ bev1,
            const float* __restrict__ Wv2, const float* __restrict__ bv2,
            const float* __restrict__ gv2, const float* __restrict__ bev2,
            const float* __restrict__ Wv3, const float* __restrict__ bv3,
            const float* __restrict__ gv3, const float* __restrict__ bev3,
            float* __restrict__ V)
{
    extern __shared__ char dsm[];
    const int cta = blockIdx.x;
    const int tid = threadIdx.x;
    char* alp = dsm;
    uint32_t sbase = smem_u32(dsm);
    unsigned bar = 0;
    const int rb = (cta & 15) * 128;
    const int cb = (cta >> 4) * 64;

    if (cta == 0) {
        for (int j = tid; j < HP; j += NT) { g_S1[j] = 0.f; g_Q1[j] = 0.f; g_S2[j] = 0.f; g_Q2[j] = 0.f; }
        if (tid == 0) { g_SC[0] = 0.f; g_QC[0] = 0.f; }
    }
    {
        const float4* xs = (const float4*)x;
        float4* xd = (float4*)g_X;
        for (int idx = cta * NT + tid; idx < BB * DD / 4; idx += NCTA * NT) xd[idx] = xs[idx];
    }
    {
        float (*ts)[33] = (float (*)[33])alp;
        for (int m = cta; m < 153; m += NCTA) {
            if (m < 50)
                tsplit(W1 + (size_t)m * DD * HH, DD, HH,
                       g_Wt1hi + (size_t)m * HH * DD, g_Wt1lo + (size_t)m * HH * DD, DD, ts);
            else if (m < 100)
                tsplit(W2 + (size_t)(m - 50) * HH * HH, HH, HH,
                       g_Wt2hi + (size_t)(m - 50) * HH * HP, g_Wt2lo + (size_t)(m - 50) * HH * HP, HP, ts);
            else if (m < 150)
                tsplit(W3 + (size_t)(m - 100) * HH * DD, HH, DD,
                       g_Wt3hi + (size_t)(m - 100) * DD * HP, g_Wt3lo + (size_t)(m - 100) * DD * HP, HP, ts);
            else if (m == 150) tsplit(Wv1, DD, HH, g_Wv1hi, g_Wv1lo, DD, ts);
            else if (m == 151) tsplit(Wv2, HH, HH, g_Wv2hi, g_Wv2lo, HP, ts);
            else               tsplit(Wv3, HH, 1,  g_Wv3hi, g_Wv3lo, HP, ts);
        }
    }
    gridbar(bar);

    if (cta < 80)
        mma_gemm<0, false>(alp, sbase, rb, cb,
            g_X, DD, 256, 256, g_Wv1hi, g_Wv1lo, HH, bv1,
            0, 0, 0, 0, g_Y1, HP, g_S1, g_Q1, 0, 0, 0, 0, 0, 0);
    gridbar(bar);
    if (cta < 80)
        mma_gemm<0, true>(alp, sbase, rb, cb,
            g_Y1, HP, 266, 272, g_Wv2hi, g_Wv2lo, HH, bv2,
            gv1, bev1, g_S1, g_Q1, g_Y2, HP, g_S2, g_Q2, 0, 0, 0, 0, 0, 0);
    gridbar(bar);
    if (cta < 16)
        mma_gemm<2, true>(alp, sbase, cta * 128, 0,
            g_Y2, HP, 266, 272, g_Wv3hi, g_Wv3lo, 1, bv3,
            gv2, bev2, g_S2, g_Q2, 0, 0, 0, 0, 0, 0, 0, 0, 0, 0);
    else if (cta == 100)
        for (int j = tid; j < HP; j += NT) { g_S1[j] = 0.f; g_Q1[j] = 0.f; }
    gridbar(bar);
    {
        int r = cta * NT + tid;
        if (r < BB) {
            float invB = 1.f / (float)BB;
            float mu  = g_SC[0] * invB;
            float var = g_QC[0] * invB - mu * mu;
            float rstd = rsqrtf(var + EPSBN);
            V[r] = fmaxf(gv3[0] * (g_Yv3[r] - mu) * rstd + bev3[0], 0.f);
        }
        if (cta == 8)
            for (int j = tid; j < HP; j += NT) { g_S2[j] = 0.f; g_Q2[j] = 0.f; }
    }
    gridbar(bar);

    #pragma unroll 1
    for (int i = 0; i < SS; i++) {
        float h  = tg[i + 1] - tg[i];
        float cs = SIGMA_C * sqrtf(h);
        if (cta < 80)
            mma_gemm<0, false>(alp, sbase, rb, cb,
                g_X, DD, 256, 256,
                g_Wt1hi + (size_t)i * HH * DD, g_Wt1lo + (size_t)i * HH * DD, HH,
                b1 + (size_t)i * HH, 0, 0, 0, 0,
                g_Y1, HP, g_S1, g_Q1, 0, 0, 0, 0, 0, 0);
        else if (cta == 147)
            for (int j = tid; j < HP; j += NT) { g_S2[j] = 0.f; g_Q2[j] = 0.f; }
        gridbar(bar);
        if (cta < 80)
            mma_gemm<0, true>(alp, sbase, rb, cb,
                g_Y1, HP, 266, 272,
                g_Wt2hi + (size_t)i * HH * HP, g_Wt2lo + (size_t)i * HH * HP, HH,
                b2 + (size_t)i * HH, g1 + (size_t)i * HH, be1 + (size_t)i * HH, g_S1, g_Q1,
                g_Y2, HP, g_S2, g_Q2, 0, 0, 0, 0, 0, 0);
        gridbar(bar);
        if (cta < 64)
            mma_gemm<1, true>(alp, sbase, rb, cb,
                g_Y2, HP, 266, 272,
                g_Wt3hi + (size_t)i * DD * HP, g_Wt3lo + (size_t)i * DD * HP, DD,
                b3 + (size_t)i * DD, g2 + (size_t)i * HH, be2 + (size_t)i * HH, g_S2, g_Q2,
                0, 0, 0, 0, h, cs, V, g_X, dW + (size_t)i * BB * DD, law + (size_t)i * DD);
        else if (cta == 100)
            for (int j = tid; j < HP; j += NT) { g_S1[j] = 0.f; g_Q1[j] = 0.f; }
        gridbar(bar);
    }

    if (tid == 0) {
        __threadfence();
        atomicAdd(&g_done, 1u);
        if (cta == 0) {
            while (*(volatile unsigned*)&g_done < NCTA) { }
            g_barctr = 0u;
            __threadfence();
            g_done = 0u;
        }
    }
}

// ---------------- host launcher ----------------
extern "C" void kernel_launch(void* const* d_in, const int* in_sizes, int n_in,
                              void* d_out, int out_size)
{
    cudaFuncSetAttribute((const void*)mega_kernel,
                         cudaFuncAttributeMaxDynamicSharedMemorySize, SMEM_DYN);
    mega_kernel<<<NCTA, NT, SMEM_DYN>>>(
        (const float*)d_in[0], (const float*)d_in[1], (const float*)d_in[2], (const float*)d_in[3],
        (const float*)d_in[4],  (const float*)d_in[5],  (const float*)d_in[6],  (const float*)d_in[7],
        (const float*)d_in[8],  (const float*)d_in[9],  (const float*)d_in[10], (const float*)d_in[11],
        (const float*)d_in[12], (const float*)d_in[13],
        (const float*)d_in[14], (const float*)d_in[15], (const float*)d_in[16], (const float*)d_in[17],
        (const float*)d_in[18], (const float*)d_in[19], (const float*)d_in[20], (const float*)d_in[21],
        (const float*)d_in[22], (const float*)d_in[23], (const float*)d_in[24], (const float*)d_in[25],
        (float*)d_out);
    (void)in_sizes; (void)n_in; (void)out_size;
}

// round 11
// speedup vs baseline: 3.2867x; 1.5227x over previous
#include <cuda_runtime.h>
#include <cuda_bf16.h>
#include <math.h>
#include <stdint.h>

#define NCTA 148
#define NT   512
#define BB   2048
#define DD   256
#define HH   266
#define HP   272
#define SS   50
#define EPSBN 1e-5f
#define SIGMA_C 0.3f
#define KC   64

// smem layout (bytes)
#define ABUF(b)  ((b) * 36864)      // A: 128 rows x 72 halfs, hi+lo
#define ALO      18432
#define BBUF(b)  (73728 + (b) * 9216)   // B: 32 rows x 72 halfs, hi+lo
#define BLO      4608
#define OF_SC    92160
#define OF_SH    93312
#define SMEM_DYN 94464

// ---------------- device scratch ----------------
__device__ float g_X[BB * DD];
__device__ __nv_bfloat16 g_Xhi[BB * DD], g_Xlo[BB * DD];
__device__ float g_Y1[BB * HP];
__device__ float g_Y2[BB * HP];
__device__ float g_Yv3[BB];
__device__ __nv_bfloat16 g_Wt1hi[SS * HH * DD], g_Wt1lo[SS * HH * DD];
__device__ __nv_bfloat16 g_Wt2hi[SS * HH * HP], g_Wt2lo[SS * HH * HP];
__device__ __nv_bfloat16 g_Wt3hi[SS * DD * HP], g_Wt3lo[SS * DD * HP];
__device__ __nv_bfloat16 g_Wv1hi[HH * DD], g_Wv1lo[HH * DD];
__device__ __nv_bfloat16 g_Wv2hi[HH * HP], g_Wv2lo[HH * HP];
__device__ __nv_bfloat16 g_Wv3hi[HP],      g_Wv3lo[HP];
__device__ float g_S1[HP], g_Q1[HP], g_S2[HP], g_Q2[HP], g_SC[1], g_QC[1];
__device__ unsigned g_barctr, g_done;

// ---------------- PTX helpers ----------------
__device__ __forceinline__ uint32_t smem_u32(const void* p) {
    uint32_t a;
    asm("{ .reg .u64 t; cvta.to.shared.u64 t, %1; cvt.u32.u64 %0, t; }" : "=r"(a) : "l"(p));
    return a;
}
#define LDSM4(r, addr) \
    asm volatile("ldmatrix.sync.aligned.m8n8.x4.shared.b16 {%0,%1,%2,%3}, [%4];" \
        : "=r"((r)[0]), "=r"((r)[1]), "=r"((r)[2]), "=r"((r)[3]) : "r"(addr))
#define MMA16816(c, a, b0_, b1_) \
    asm volatile("mma.sync.aligned.m16n8k16.row.col.f32.bf16.bf16.f32 " \
        "{%0,%1,%2,%3}, {%4,%5,%6,%7}, {%8,%9}, {%0,%1,%2,%3};" \
        : "+f"((c)[0]), "+f"((c)[1]), "+f"((c)[2]), "+f"((c)[3]) \
        : "r"((a)[0]), "r"((a)[1]), "r"((a)[2]), "r"((a)[3]), "r"(b0_), "r"(b1_))
#define CP16(dst, src) \
    asm volatile("cp.async.ca.shared.global [%0], [%1], 16;" :: "r"(dst), "l"(src) : "memory")
#define CP_COMMIT() asm volatile("cp.async.commit_group;" ::: "memory")
#define CP_WAIT0()  asm volatile("cp.async.wait_group 0;" ::: "memory")

__device__ __forceinline__ void gridbar(unsigned& cnt) {
    __syncthreads();
    if (threadIdx.x == 0) {
        __threadfence();
        atomicAdd(&g_barctr, 1u);
        unsigned target = (++cnt) * NCTA;
        while (*(volatile unsigned*)&g_barctr < target) { }
        __threadfence();
    }
    __syncthreads();
}

// ---------------- transpose + split ----------------
__device__ void tsplit(const float* __restrict__ src, int K, int N,
                       __nv_bfloat16* __restrict__ dh, __nv_bfloat16* __restrict__ dl,
                       int ldT, float (*ts)[33]) {
    int ktiles = (ldT + 31) >> 5, ntiles = (N + 31) >> 5;
    for (int t = 0; t < ktiles * ntiles; t++) {
        int kt = t / ntiles, nt = t - kt * ntiles;
        int k0 = kt << 5, n0 = nt << 5;
        __syncthreads();
        #pragma unroll
        for (int s2 = 0; s2 < 2; s2++) {
            int idx = s2 * NT + threadIdx.x;
            int r = idx >> 5, c = idx & 31;
            int k = k0 + r, n = n0 + c;
            ts[r][c] = (k < K && n < N) ? src[(size_t)k * N + n] : 0.f;
        }
        __syncthreads();
        #pragma unroll
        for (int s2 = 0; s2 < 2; s2++) {
            int idx = s2 * NT + threadIdx.x;
            int rr = idx >> 5, cc = idx & 31;
            int n = n0 + rr, k = k0 + cc;
            if (n < N && k < ldT) {
                float v = ts[cc][rr];
                __nv_bfloat16 hb = __float2bfloat16(v);
                dh[(size_t)n * ldT + k] = hb;
                dl[(size_t)n * ldT + k] = __float2bfloat16(v - __bfloat162float(hb));
            }
        }
    }
}

// ---------------- HMMA GEMM phase (128x32 tile, 16 warps, pipelined) --------
// MODE 0: C fp32 + column stats. MODE 1: fused SDE X/V update + X-split. MODE 2: N=1 head.
template<int MODE, bool BN, bool ASPLIT>
__device__ __noinline__ void mma_gemm(char* alp, uint32_t sbase,
    int rowBase, int cb,
    const float* __restrict__ A, int ldA, int K, int Ksteps,
    const __nv_bfloat16* __restrict__ Ahs, const __nv_bfloat16* __restrict__ Als,
    const __nv_bfloat16* __restrict__ Bh, const __nv_bfloat16* __restrict__ Bl, int Nout,
    const float* __restrict__ bias,
    const float* __restrict__ bng, const float* __restrict__ bnb,
    const float* __restrict__ ssum, const float* __restrict__ ssq,
    float* __restrict__ C, int ldc, float* osum, float* osq,
    float hstep, float cstep, float* __restrict__ V,
    float* __restrict__ X, const float* __restrict__ dWi, const float* __restrict__ lawi)
{
    const int tid = threadIdx.x;
    const int lane = tid & 31;
    const int warp = tid >> 5;
    const int mr = warp & 7;    // rows mr*16..+15
    const int nc = warp >> 3;   // cols nc*16..+15
    float* scK = (float*)(alp + OF_SC);
    float* shK = (float*)(alp + OF_SH);

    if (BN) {
        const float invB = 1.f / (float)BB;
        for (int k = tid; k < HP; k += NT) {
            if (k < K) {
                float mu  = ssum[k] * invB;
                float var = ssq[k] * invB - mu * mu;
                float rstd = rsqrtf(var + EPSBN);
                float sc = bng[k] * rstd;
                scK[k] = sc; shK[k] = bnb[k] - mu * sc;
            } else { scK[k] = 0.f; shK[k] = 0.f; }
        }
        __syncthreads();
    }

    const int nch = (Ksteps + KC - 1) / KC;
    float fa[16];

    auto ldAreg = [&](int ch) {
        const int k0 = ch * KC;
        #pragma unroll
        for (int it = 0; it < 2; it++) {
            int idx = it * NT + tid;
            int row = idx >> 3, kg = idx & 7;
            int gk = k0 + kg * 8;
            if (gk < Ksteps) {
                const float* ap = A + (size_t)(rowBase + row) * ldA + gk;
                float4 v0 = *(const float4*)ap;
                float4 v1 = *(const float4*)(ap + 4);
                fa[it*8+0] = v0.x; fa[it*8+1] = v0.y; fa[it*8+2] = v0.z; fa[it*8+3] = v0.w;
                fa[it*8+4] = v1.x; fa[it*8+5] = v1.y; fa[it*8+6] = v1.z; fa[it*8+7] = v1.w;
            } else {
                #pragma unroll
                for (int e = 0; e < 8; e++) fa[it*8+e] = 0.f;
            }
        }
    };
    auto stA = [&](int ch, int buf) {
        const int k0 = ch * KC;
        #pragma unroll
        for (int it = 0; it < 2; it++) {
            int idx = it * NT + tid;
            int row = idx >> 3, kg = idx & 7;
            int gk = k0 + kg * 8;
            union { __nv_bfloat16 h[8]; uint4 u; } th, tl;
            if (gk < Ksteps) {
                #pragma unroll
                for (int e = 0; e < 8; e++) {
                    float v = fa[it*8+e];
                    if (BN) v = fmaxf(fmaf(v, scK[gk + e], shK[gk + e]), 0.f);
                    __nv_bfloat16 hb = __float2bfloat16(v);
                    th.h[e] = hb;
                    tl.h[e] = __float2bfloat16(v - __bfloat162float(hb));
                }
            } else { th.u = make_uint4(0, 0, 0, 0); tl.u = th.u; }
            uint32_t off = (uint32_t)(row * 72 + kg * 8) * 2u;
            *(uint4*)(alp + ABUF(buf) + off) = th.u;
            *(uint4*)(alp + ABUF(buf) + ALO + off) = tl.u;
        }
    };
    auto cpA = [&](int ch, int buf) {   // ASPLIT: bf16 A direct (K=256 exact)
        const int k0 = ch * KC;
        #pragma unroll
        for (int it = 0; it < 2; it++) {
            int idx = it * NT + tid;
            int row = idx >> 3, kg = idx & 7;
            int gk = k0 + kg * 8;
            uint32_t off = (uint32_t)(row * 72 + kg * 8) * 2u;
            uint32_t d = sbase + ABUF(buf) + off;
            const size_t go = (size_t)(rowBase + row) * ldA + gk;
            CP16(d, Ahs + go);
            CP16(d + ALO, Als + go);
        }
    };
    auto cpB = [&](int ch, int buf) {
        if (tid < 256) {
            const int k0 = ch * KC;
            int row = tid >> 3, kg = tid & 7;
            int gk = k0 + kg * 8;
            int n = cb + row;
            uint32_t off = (uint32_t)(row * 72 + kg * 8) * 2u;
            uint32_t d0 = sbase + BBUF(buf) + off;
            if (gk < Ksteps && n < Nout) {
                CP16(d0, Bh + (size_t)n * Ksteps + gk);
                CP16(d0 + BLO, Bl + (size_t)n * Ksteps + gk);
            } else {
                uint4 z = make_uint4(0, 0, 0, 0);
                *(uint4*)(alp + BBUF(buf) + off) = z;
                *(uint4*)(alp + BBUF(buf) + BLO + off) = z;
            }
        }
    };

    float acc[2][4] = {};
    uint32_t ahf[2][4], alf[2][4], bhf[2][4], blf[2][4];

    auto ldFrag = [&](int kk, int p, int buf) {
        const int k16 = kk * 16;
        uint32_t ao = sbase + ABUF(buf) +
            2u * (uint32_t)((mr * 16 + (lane & 15)) * 72 + k16 + ((lane >> 4) << 3));
        LDSM4(ahf[p], ao);
        LDSM4(alf[p], ao + ALO);
        uint32_t bo = sbase + BBUF(buf) +
            2u * (uint32_t)((nc * 16 + (lane & 7) + ((lane >> 3) & 1) * 8) * 72
                            + k16 + ((lane >> 4) << 3));
        LDSM4(bhf[p], bo);
        LDSM4(blf[p], bo + BLO);
    };

    // prologue
    if (ASPLIT) { cpA(0, 0); cpB(0, 0); CP_COMMIT(); }
    else        { ldAreg(0); cpB(0, 0); CP_COMMIT(); stA(0, 0); }
    CP_WAIT0();
    __syncthreads();

    for (int ch = 0; ch < nch; ch++) {
        const int buf = ch & 1;
        const bool more = (ch + 1 < nch);
        if (more) {
            if (ASPLIT) cpA(ch + 1, buf ^ 1);
            else        ldAreg(ch + 1);
            cpB(ch + 1, buf ^ 1); CP_COMMIT();
        }

        int ns = (Ksteps - ch * KC) >> 4; if (ns > KC / 16) ns = KC / 16;
        ldFrag(0, 0, buf);
        for (int kk = 0; kk < ns; kk++) {
            const int p = kk & 1;
            if (kk + 1 < ns) ldFrag(kk + 1, p ^ 1, buf);
            #pragma unroll
            for (int t = 0; t < 2; t++) {
                MMA16816(acc[t], ahf[p], bhf[p][t], bhf[p][t + 2]);
                MMA16816(acc[t], alf[p], bhf[p][t], bhf[p][t + 2]);
                MMA16816(acc[t], ahf[p], blf[p][t], blf[p][t + 2]);
            }
        }

        if (more && !ASPLIT) stA(ch + 1, buf ^ 1);
        CP_WAIT0();
        __syncthreads();
    }

    // ---- fragments -> Cs [128][36] (aliases A buffers) ----
    float* Cs = (float*)alp;
    {
        int r0 = mr * 16 + (lane >> 2);
        #pragma unroll
        for (int t = 0; t < 2; t++) {
            int cl = nc * 16 + t * 8 + (lane & 3) * 2;
            Cs[r0 * 36 + cl]           = acc[t][0];
            Cs[r0 * 36 + cl + 1]       = acc[t][1];
            Cs[(r0 + 8) * 36 + cl]     = acc[t][2];
            Cs[(r0 + 8) * 36 + cl + 1] = acc[t][3];
        }
    }
    __syncthreads();

    if (MODE == 0) {
        #pragma unroll
        for (int it = 0; it < 8; it++) {
            int idx = it * NT + tid;
            int row = idx >> 5, col = idx & 31;
            int gn = cb + col;
            float v = 0.f;
            if (gn < Nout) {
                v = Cs[row * 36 + col] + bias[gn];
                C[(size_t)(rowBase + row) * ldc + gn] = v;
            }
            Cs[row * 36 + col] = v;
        }
        __syncthreads();
        float* red2 = (float*)(alp + 20480);
        {
            int col = tid & 31, seg = tid >> 5;
            float s = 0.f, q = 0.f;
            #pragma unroll
            for (int r8 = 0; r8 < 8; r8++) {
                float v = Cs[(seg * 8 + r8) * 36 + col];
                s += v; q += v * v;
            }
            red2[seg * 32 + col] = s;
            red2[512 + seg * 32 + col] = q;
        }
        __syncthreads();
        if (tid < 32) {
            float s = 0.f, q = 0.f;
            #pragma unroll
            for (int g = 0; g < 16; g++) { s += red2[g * 32 + tid]; q += red2[512 + g * 32 + tid]; }
            int gn = cb + tid;
            if (gn < Nout) { atomicAdd(&osum[gn], s); atomicAdd(&osq[gn], q); }
        }
        __syncthreads();
    } else if (MODE == 1) {
        int row = tid >> 2, quad = tid & 3;
        size_t rbo = (size_t)(rowBase + row) * DD + cb + quad * 8;
        float p1 = 0.f, p2 = 0.f, p3 = 0.f;
        float xr[8];
        #pragma unroll
        for (int j4 = 0; j4 < 2; j4++) {
            int cl = quad * 8 + j4 * 4;
            int gc = cb + cl;
            float4 bj = *(const float4*)(bias + gc);
            float4 xv = *(const float4*)(X + rbo + j4 * 4);
            float4 dv = *(const float4*)(dWi + rbo + j4 * 4);
            float4 lw = *(const float4*)(lawi + gc);
            float q0 = Cs[row * 36 + cl]     + bj.x;
            float q1 = Cs[row * 36 + cl + 1] + bj.y;
            float q2 = Cs[row * 36 + cl + 2] + bj.z;
            float q3 = Cs[row * 36 + cl + 3] + bj.w;
            float n0 = cstep * dv.x, n1 = cstep * dv.y;
            float n2 = cstep * dv.z, n3 = cstep * dv.w;
            float d0 = xv.x - lw.x, d1 = xv.y - lw.y;
            float d2 = xv.z - lw.z, d3 = xv.w - lw.w;
            p1 += d0 * d0 + d1 * d1 + d2 * d2 + d3 * d3;
            p2 += q0 * q0 + q1 * q1 + q2 * q2 + q3 * q3;
            p3 += q0 * n0 + q1 * n1 + q2 * n2 + q3 * n3;
            float4 xo;
            xo.x = xv.x - q0 * hstep + n0;
            xo.y = xv.y - q1 * hstep + n1;
            xo.z = xv.z - q2 * hstep + n2;
            xo.w = xv.w - q3 * hstep + n3;
            *(float4*)(X + rbo + j4 * 4) = xo;
            xr[j4*4+0] = xo.x; xr[j4*4+1] = xo.y; xr[j4*4+2] = xo.z; xr[j4*4+3] = xo.w;
        }
        // write X split for next step's L1
        {
            union { __nv_bfloat16 h[8]; uint4 u; } th, tl;
            #pragma unroll
            for (int e = 0; e < 8; e++) {
                __nv_bfloat16 hb = __float2bfloat16(xr[e]);
                th.h[e] = hb;
                tl.h[e] = __float2bfloat16(xr[e] - __bfloat162float(hb));
            }
            *(uint4*)(g_Xhi + rbo) = th.u;
            *(uint4*)(g_Xlo + rbo) = tl.u;
        }
        float t = -0.5f * hstep * (p1 + p2) + p3;
        t += __shfl_down_sync(0xffffffffu, t, 1);
        t += __shfl_down_sync(0xffffffffu, t, 2);
        if ((lane & 3) == 0) atomicAdd(&V[rowBase + row], t);
        __syncthreads();
    } else {
        if (tid < 128) {
            float v = Cs[tid * 36] + bias[0];
            g_Yv3[rowBase + tid] = v;
            float s = v, q = v * v;
            #pragma unroll
            for (int o = 16; o > 0; o >>= 1) {
                s += __shfl_down_sync(0xffffffffu, s, o);
                q += __shfl_down_sync(0xffffffffu, q, o);
            }
            if ((tid & 31) == 0) { atomicAdd(&g_SC[0], s); atomicAdd(&g_QC[0], q); }
        }
        __syncthreads();
    }
}

// ---------------- single persistent kernel ----------------
extern "C" __global__ void __launch_bounds__(NT, 1)
mega_kernel(const float* __restrict__ x, const float* __restrict__ dW,
            const float* __restrict__ law, const float* __restrict__ tg,
            const float* __restrict__ W1, const float* __restrict__ b1,
            const float* __restrict__ g1, const float* __restrict__ be1,
            const float* __restrict__ W2, const float* __restrict__ b2,
            const float* __restrict__ g2, const float* __restrict__ be2,
            const float* __restrict__ W3, const float* __restrict__ b3,
            const float* __restrict__ Wv1, const float* __restrict__ bv1,
            const float* __restrict__ gv1, const float* __restrict__ bev1,
            const float* __restrict__ Wv2, const float* __restrict__ bv2,
            const float* __restrict__ gv2, const float* __restrict__ bev2,
            const float* __restrict__ Wv3, const float* __restrict__ bv3,
            const float* __restrict__ gv3, const float* __restrict__ bev3,
            float* __restrict__ V)
{
    extern __shared__ char dsm[];
    const int cta = blockIdx.x;
    const int tid = threadIdx.x;
    char* alp = dsm;
    uint32_t sbase = smem_u32(dsm);
    unsigned bar = 0;
    const int rb = (cta & 15) * 128;
    const int cb = (cta >> 4) * 32;

    if (cta == 0) {
        for (int j = tid; j < HP; j += NT) { g_S1[j] = 0.f; g_Q1[j] = 0.f; g_S2[j] = 0.f; g_Q2[j] = 0.f; }
        if (tid == 0) { g_SC[0] = 0.f; g_QC[0] = 0.f; }
    }
    {   // copy X and split to bf16
        for (int idx = cta * NT + tid; idx < BB * DD / 4; idx += NCTA * NT)
            ((float4*)g_X)[idx] = ((const float4*)x)[idx];
        int idx8 = cta * NT + tid;
        if (idx8 < BB * DD / 8) {
            const float* xp = x + idx8 * 8;
            union { __nv_bfloat16 h[8]; uint4 u; } th, tl;
            #pragma unroll
            for (int e = 0; e < 8; e++) {
                float v = xp[e];
                __nv_bfloat16 hb = __float2bfloat16(v);
                th.h[e] = hb;
                tl.h[e] = __float2bfloat16(v - __bfloat162float(hb));
            }
            *(uint4*)(g_Xhi + (size_t)idx8 * 8) = th.u;
            *(uint4*)(g_Xlo + (size_t)idx8 * 8) = tl.u;
        }
    }
    {
        float (*ts)[33] = (float (*)[33])alp;
        for (int m = cta; m < 153; m += NCTA) {
            if (m < 50)
                tsplit(W1 + (size_t)m * DD * HH, DD, HH,
                       g_Wt1hi + (size_t)m * HH * DD, g_Wt1lo + (size_t)m * HH * DD, DD, ts);
            else if (m < 100)
                tsplit(W2 + (size_t)(m - 50) * HH * HH, HH, HH,
                       g_Wt2hi + (size_t)(m - 50) * HH * HP, g_Wt2lo + (size_t)(m - 50) * HH * HP, HP, ts);
            else if (m < 150)
                tsplit(W3 + (size_t)(m - 100) * HH * DD, HH, DD,
                       g_Wt3hi + (size_t)(m - 100) * DD * HP, g_Wt3lo + (size_t)(m - 100) * DD * HP, HP, ts);
            else if (m == 150) tsplit(Wv1, DD, HH, g_Wv1hi, g_Wv1lo, DD, ts);
            else if (m == 151) tsplit(Wv2, HH, HH, g_Wv2hi, g_Wv2lo, HP, ts);
            else               tsplit(Wv3, HH, 1,  g_Wv3hi, g_Wv3lo, HP, ts);
        }
    }
    gridbar(bar);

    // v0 L1 (A = x split)
    if (cta < 144)
        mma_gemm<0, false, true>(alp, sbase, rb, cb,
            0, DD, 256, 256, g_Xhi, g_Xlo, g_Wv1hi, g_Wv1lo, HH, bv1,
            0, 0, 0, 0, g_Y1, HP, g_S1, g_Q1, 0, 0, 0, 0, 0, 0);
    gridbar(bar);
    // v0 L2
    if (cta < 144)
        mma_gemm<0, true, false>(alp, sbase, rb, cb,
            g_Y1, HP, 266, 272, 0, 0, g_Wv2hi, g_Wv2lo, HH, bv2,
            gv1, bev1, g_S1, g_Q1, g_Y2, HP, g_S2, g_Q2, 0, 0, 0, 0, 0, 0);
    gridbar(bar);
    // v0 L3 (N=1)
    if (cta < 16)
        mma_gemm<2, true, false>(alp, sbase, cta * 128, 0,
            g_Y2, HP, 266, 272, 0, 0, g_Wv3hi, g_Wv3lo, 1, bv3,
            gv2, bev2, g_S2, g_Q2, 0, 0, 0, 0, 0, 0, 0, 0, 0, 0);
    else if (cta == 100)
        for (int j = tid; j < HP; j += NT) { g_S1[j] = 0.f; g_Q1[j] = 0.f; }
    gridbar(bar);
    // v0 finalize
    {
        int r = cta * NT + tid;
        if (r < BB) {
            float invB = 1.f / (float)BB;
            float mu  = g_SC[0] * invB;
            float var = g_QC[0] * invB - mu * mu;
            float rstd = rsqrtf(var + EPSBN);
            V[r] = fmaxf(gv3[0] * (g_Yv3[r] - mu) * rstd + bev3[0], 0.f);
        }
        if (cta == 8)
            for (int j = tid; j < HP; j += NT) { g_S2[j] = 0.f; g_Q2[j] = 0.f; }
    }
    gridbar(bar);

    #pragma unroll 1
    for (int i = 0; i < SS; i++) {
        float h  = tg[i + 1] - tg[i];
        float cs = SIGMA_C * sqrtf(h);
        // L1: Xsplit -> Y1 + S1/Q1
        if (cta < 144)
            mma_gemm<0, false, true>(alp, sbase, rb, cb,
                0, DD, 256, 256, g_Xhi, g_Xlo,
                g_Wt1hi + (size_t)i * HH * DD, g_Wt1lo + (size_t)i * HH * DD, HH,
                b1 + (size_t)i * HH, 0, 0, 0, 0,
                g_Y1, HP, g_S1, g_Q1, 0, 0, 0, 0, 0, 0);
        else if (cta == 147)
            for (int j = tid; j < HP; j += NT) { g_S2[j] = 0.f; g_Q2[j] = 0.f; }
        gridbar(bar);
        // L2: BN(Y1) -> Y2 + S2/Q2
        if (cta < 144)
            mma_gemm<0, true, false>(alp, sbase, rb, cb,
                g_Y1, HP, 266, 272, 0, 0,
                g_Wt2hi + (size_t)i * HH * HP, g_Wt2lo + (size_t)i * HH * HP, HH,
                b2 + (size_t)i * HH, g1 + (size_t)i * HH, be1 + (size_t)i * HH, g_S1, g_Q1,
                g_Y2, HP, g_S2, g_Q2, 0, 0, 0, 0, 0, 0);
        gridbar(bar);
        // L3: BN(Y2) -> grad; fused SDE update + X split
        if (cta < 128)
            mma_gemm<1, true, false>(alp, sbase, rb, cb,
                g_Y2, HP, 266, 272, 0, 0,
                g_Wt3hi + (size_t)i * DD * HP, g_Wt3lo + (size_t)i * DD * HP, DD,
                b3 + (size_t)i * DD, g2 + (size_t)i * HH, be2 + (size_t)i * HH, g_S2, g_Q2,
                0, 0, 0, 0, h, cs, V, g_X, dW + (size_t)i * BB * DD, law + (size_t)i * DD);
        else if (cta == 144)
            for (int j = tid; j < HP; j += NT) { g_S1[j] = 0.f; g_Q1[j] = 0.f; }
        gridbar(bar);
    }

    if (tid == 0) {
        __threadfence();
        atomicAdd(&g_done, 1u);
        if (cta == 0) {
            while (*(volatile unsigned*)&g_done < NCTA) { }
            g_barctr = 0u;
            __threadfence();
            g_done = 0u;
        }
    }
}

// ---------------- host launcher ----------------
extern "C" void kernel_launch(void* const* d_in, const int* in_sizes, int n_in,
                              void* d_out, int out_size)
{
    cudaFuncSetAttribute((const void*)mega_kernel,
                         cudaFuncAttributeMaxDynamicSharedMemorySize, SMEM_DYN);
    mega_kernel<<<NCTA, NT, SMEM_DYN>>>(
        (const float*)d_in[0], (const float*)d_in[1], (const float*)d_in[2], (const float*)d_in[3],
        (const float*)d_in[4],  (const float*)d_in[5],  (const float*)d_in[6],  (const float*)d_in[7],
        (const float*)d_in[8],  (const float*)d_in[9],  (const float*)d_in[10], (const float*)d_in[11],
        (const float*)d_in[12], (const float*)d_in[13],
        (const float*)d_in[14], (const float*)d_in[15], (const float*)d_in[16], (const float*)d_in[17],
        (const float*)d_in[18], (const float*)d_in[19], (const float*)d_in[20], (const float*)d_in[21],
        (const float*)d_in[22], (const float*)d_in[23], (const float*)d_in[24], (const float*)d_in[25],
        (float*)d_out);
    (void)in_sizes; (void)n_in; (void)out_size;
}

// round 12
// speedup vs baseline: 3.5919x; 1.0929x over previous
#include <cuda_runtime.h>
#include <cuda_bf16.h>
#include <math.h>
#include <stdint.h>

#define NCTA 148
#define NT   512
#define BB   2048
#define DD   256
#define HH   266
#define HP   272
#define SS   50
#define EPSBN 1e-5f
#define SIGMA_C 0.3f
#define KC   64

// smem layout (bytes)
#define ABUF(b)  ((b) * 18432)          // A: 128 rows x 72 halfs (bf16, single)
#define BBUF(b)  (36864 + (b) * 9216)   // B: 32 rows x 72 halfs, hi+lo
#define BLO      4608
#define OF_SC    55296
#define OF_SH    56448
#define SMEM_DYN 57600

// ---------------- device scratch ----------------
__device__ float g_X[BB * DD];
__device__ __nv_bfloat16 g_Xhi[BB * DD];
__device__ float g_Y1[BB * HP];
__device__ float g_Y2[BB * HP];
__device__ float g_Yv3[BB];
__device__ __nv_bfloat16 g_Wt1hi[SS * HH * DD], g_Wt1lo[SS * HH * DD];
__device__ __nv_bfloat16 g_Wt2hi[SS * HH * HP], g_Wt2lo[SS * HH * HP];
__device__ __nv_bfloat16 g_Wt3hi[SS * DD * HP], g_Wt3lo[SS * DD * HP];
__device__ __nv_bfloat16 g_Wv1hi[HH * DD], g_Wv1lo[HH * DD];
__device__ __nv_bfloat16 g_Wv2hi[HH * HP], g_Wv2lo[HH * HP];
__device__ __nv_bfloat16 g_Wv3hi[HP],      g_Wv3lo[HP];
__device__ float g_S1[HP], g_Q1[HP], g_S2[HP], g_Q2[HP], g_SC[1], g_QC[1];
__device__ unsigned g_barctr, g_done;

// ---------------- PTX helpers ----------------
__device__ __forceinline__ uint32_t smem_u32(const void* p) {
    uint32_t a;
    asm("{ .reg .u64 t; cvta.to.shared.u64 t, %1; cvt.u32.u64 %0, t; }" : "=r"(a) : "l"(p));
    return a;
}
#define LDSM4(r, addr) \
    asm volatile("ldmatrix.sync.aligned.m8n8.x4.shared.b16 {%0,%1,%2,%3}, [%4];" \
        : "=r"((r)[0]), "=r"((r)[1]), "=r"((r)[2]), "=r"((r)[3]) : "r"(addr))
#define MMA16816(c, a, b0_, b1_) \
    asm volatile("mma.sync.aligned.m16n8k16.row.col.f32.bf16.bf16.f32 " \
        "{%0,%1,%2,%3}, {%4,%5,%6,%7}, {%8,%9}, {%0,%1,%2,%3};" \
        : "+f"((c)[0]), "+f"((c)[1]), "+f"((c)[2]), "+f"((c)[3]) \
        : "r"((a)[0]), "r"((a)[1]), "r"((a)[2]), "r"((a)[3]), "r"(b0_), "r"(b1_))
#define CP16(dst, src) \
    asm volatile("cp.async.ca.shared.global [%0], [%1], 16;" :: "r"(dst), "l"(src) : "memory")
#define CP_COMMIT() asm volatile("cp.async.commit_group;" ::: "memory")
#define CP_WAIT0()  asm volatile("cp.async.wait_group 0;" ::: "memory")

__device__ __forceinline__ void gridbar(unsigned& cnt) {
    __syncthreads();
    if (threadIdx.x == 0) {
        __threadfence();
        atomicAdd(&g_barctr, 1u);
        unsigned target = (++cnt) * NCTA;
        while (*(volatile unsigned*)&g_barctr < target) { }
        __threadfence();
    }
    __syncthreads();
}

// ---------------- transpose + split (weights keep hi+lo) ----------------
__device__ void tsplit(const float* __restrict__ src, int K, int N,
                       __nv_bfloat16* __restrict__ dh, __nv_bfloat16* __restrict__ dl,
                       int ldT, float (*ts)[33]) {
    int ktiles = (ldT + 31) >> 5, ntiles = (N + 31) >> 5;
    for (int t = 0; t < ktiles * ntiles; t++) {
        int kt = t / ntiles, nt = t - kt * ntiles;
        int k0 = kt << 5, n0 = nt << 5;
        __syncthreads();
        #pragma unroll
        for (int s2 = 0; s2 < 2; s2++) {
            int idx = s2 * NT + threadIdx.x;
            int r = idx >> 5, c = idx & 31;
            int k = k0 + r, n = n0 + c;
            ts[r][c] = (k < K && n < N) ? src[(size_t)k * N + n] : 0.f;
        }
        __syncthreads();
        #pragma unroll
        for (int s2 = 0; s2 < 2; s2++) {
            int idx = s2 * NT + threadIdx.x;
            int rr = idx >> 5, cc = idx & 31;
            int n = n0 + rr, k = k0 + cc;
            if (n < N && k < ldT) {
                float v = ts[cc][rr];
                __nv_bfloat16 hb = __float2bfloat16(v);
                dh[(size_t)n * ldT + k] = hb;
                dl[(size_t)n * ldT + k] = __float2bfloat16(v - __bfloat162float(hb));
            }
        }
    }
}

// ---------------- HMMA GEMM phase (128x32 tile, 16 warps, pipelined) --------
// A single bf16; B split hi/lo (2-term: A*Bhi + A*Blo)
// MODE 0: C fp32 + column stats. MODE 1: fused SDE X/V update + X-split. MODE 2: N=1 head.
template<int MODE, bool BN, bool ASPLIT>
__device__ __noinline__ void mma_gemm(char* alp, uint32_t sbase,
    int rowBase, int cb,
    const float* __restrict__ A, int ldA, int K, int Ksteps,
    const __nv_bfloat16* __restrict__ Ahs,
    const __nv_bfloat16* __restrict__ Bh, const __nv_bfloat16* __restrict__ Bl, int Nout,
    const float* __restrict__ bias,
    const float* __restrict__ bng, const float* __restrict__ bnb,
    const float* __restrict__ ssum, const float* __restrict__ ssq,
    float* __restrict__ C, int ldc, float* osum, float* osq,
    float hstep, float cstep, float* __restrict__ V,
    float* __restrict__ X, const float* __restrict__ dWi, const float* __restrict__ lawi)
{
    const int tid = threadIdx.x;
    const int lane = tid & 31;
    const int warp = tid >> 5;
    const int mr = warp & 7;    // rows mr*16..+15
    const int nc = warp >> 3;   // cols nc*16..+15
    float* scK = (float*)(alp + OF_SC);
    float* shK = (float*)(alp + OF_SH);

    if (BN) {
        const float invB = 1.f / (float)BB;
        for (int k = tid; k < HP; k += NT) {
            if (k < K) {
                float mu  = ssum[k] * invB;
                float var = ssq[k] * invB - mu * mu;
                float rstd = rsqrtf(var + EPSBN);
                float sc = bng[k] * rstd;
                scK[k] = sc; shK[k] = bnb[k] - mu * sc;
            } else { scK[k] = 0.f; shK[k] = 0.f; }
        }
        __syncthreads();
    }

    const int nch = (Ksteps + KC - 1) / KC;
    float fa[16];

    auto ldAreg = [&](int ch) {
        const int k0 = ch * KC;
        #pragma unroll
        for (int it = 0; it < 2; it++) {
            int idx = it * NT + tid;
            int row = idx >> 3, kg = idx & 7;
            int gk = k0 + kg * 8;
            if (gk < Ksteps) {
                const float* ap = A + (size_t)(rowBase + row) * ldA + gk;
                float4 v0 = *(const float4*)ap;
                float4 v1 = *(const float4*)(ap + 4);
                fa[it*8+0] = v0.x; fa[it*8+1] = v0.y; fa[it*8+2] = v0.z; fa[it*8+3] = v0.w;
                fa[it*8+4] = v1.x; fa[it*8+5] = v1.y; fa[it*8+6] = v1.z; fa[it*8+7] = v1.w;
            } else {
                #pragma unroll
                for (int e = 0; e < 8; e++) fa[it*8+e] = 0.f;
            }
        }
    };
    auto stA = [&](int ch, int buf) {
        const int k0 = ch * KC;
        #pragma unroll
        for (int it = 0; it < 2; it++) {
            int idx = it * NT + tid;
            int row = idx >> 3, kg = idx & 7;
            int gk = k0 + kg * 8;
            union { __nv_bfloat16 h[8]; uint4 u; } th;
            if (gk < Ksteps) {
                #pragma unroll
                for (int e = 0; e < 8; e++) {
                    float v = fa[it*8+e];
                    if (BN) v = fmaxf(fmaf(v, scK[gk + e], shK[gk + e]), 0.f);
                    th.h[e] = __float2bfloat16(v);
                }
            } else th.u = make_uint4(0, 0, 0, 0);
            uint32_t off = (uint32_t)(row * 72 + kg * 8) * 2u;
            *(uint4*)(alp + ABUF(buf) + off) = th.u;
        }
    };
    auto cpA = [&](int ch, int buf) {   // ASPLIT: bf16 A direct (K=256 exact)
        const int k0 = ch * KC;
        #pragma unroll
        for (int it = 0; it < 2; it++) {
            int idx = it * NT + tid;
            int row = idx >> 3, kg = idx & 7;
            int gk = k0 + kg * 8;
            uint32_t off = (uint32_t)(row * 72 + kg * 8) * 2u;
            CP16(sbase + ABUF(buf) + off, Ahs + (size_t)(rowBase + row) * ldA + gk);
        }
    };
    auto cpB = [&](int ch, int buf) {
        if (tid < 256) {
            const int k0 = ch * KC;
            int row = tid >> 3, kg = tid & 7;
            int gk = k0 + kg * 8;
            int n = cb + row;
            uint32_t off = (uint32_t)(row * 72 + kg * 8) * 2u;
            uint32_t d0 = sbase + BBUF(buf) + off;
            if (gk < Ksteps && n < Nout) {
                CP16(d0, Bh + (size_t)n * Ksteps + gk);
                CP16(d0 + BLO, Bl + (size_t)n * Ksteps + gk);
            } else {
                uint4 z = make_uint4(0, 0, 0, 0);
                *(uint4*)(alp + BBUF(buf) + off) = z;
                *(uint4*)(alp + BBUF(buf) + BLO + off) = z;
            }
        }
    };

    float acc[2][4] = {};
    uint32_t ahf[2][4], bhf[2][4], blf[2][4];
    const uint32_t aoOff = 2u * (uint32_t)((mr * 16 + (lane & 15)) * 72 + ((lane >> 4) << 3));
    const uint32_t boOff = 2u * (uint32_t)((nc * 16 + (lane & 7) + ((lane >> 3) & 1) * 8) * 72
                                           + ((lane >> 4) << 3));

    // prologue
    if (ASPLIT) { cpA(0, 0); cpB(0, 0); CP_COMMIT(); }
    else        { ldAreg(0); cpB(0, 0); CP_COMMIT(); stA(0, 0); }
    CP_WAIT0();
    __syncthreads();

    for (int ch = 0; ch < nch; ch++) {
        const int buf = ch & 1;
        const bool more = (ch + 1 < nch);
        if (more) {
            if (ASPLIT) cpA(ch + 1, buf ^ 1);
            else        ldAreg(ch + 1);
            cpB(ch + 1, buf ^ 1); CP_COMMIT();
        }

        int ns = (Ksteps - ch * KC) >> 4; if (ns > KC / 16) ns = KC / 16;
        uint32_t ao = sbase + ABUF(buf) + aoOff;
        uint32_t bo = sbase + BBUF(buf) + boOff;
        LDSM4(ahf[0], ao); LDSM4(bhf[0], bo); LDSM4(blf[0], bo + BLO);
        for (int kk = 0; kk < ns; kk++) {
            const int p = kk & 1;
            if (kk + 1 < ns) {
                uint32_t a2 = ao + (kk + 1) * 32, b2 = bo + (kk + 1) * 32;
                LDSM4(ahf[p ^ 1], a2); LDSM4(bhf[p ^ 1], b2); LDSM4(blf[p ^ 1], b2 + BLO);
            }
            #pragma unroll
            for (int t = 0; t < 2; t++) {
                MMA16816(acc[t], ahf[p], bhf[p][t], bhf[p][t + 2]);
                MMA16816(acc[t], ahf[p], blf[p][t], blf[p][t + 2]);
            }
        }

        if (more && !ASPLIT) stA(ch + 1, buf ^ 1);
        CP_WAIT0();
        __syncthreads();
    }

    // ---- fragments -> Cs [128][36] (aliases A buffers) ----
    float* Cs = (float*)alp;
    {
        int r0 = mr * 16 + (lane >> 2);
        #pragma unroll
        for (int t = 0; t < 2; t++) {
            int cl = nc * 16 + t * 8 + (lane & 3) * 2;
            Cs[r0 * 36 + cl]           = acc[t][0];
            Cs[r0 * 36 + cl + 1]       = acc[t][1];
            Cs[(r0 + 8) * 36 + cl]     = acc[t][2];
            Cs[(r0 + 8) * 36 + cl + 1] = acc[t][3];
        }
    }
    __syncthreads();

    if (MODE == 0) {
        #pragma unroll
        for (int it = 0; it < 8; it++) {
            int idx = it * NT + tid;
            int row = idx >> 5, col = idx & 31;
            int gn = cb + col;
            float v = 0.f;
            if (gn < Nout) {
                v = Cs[row * 36 + col] + bias[gn];
                C[(size_t)(rowBase + row) * ldc + gn] = v;
            }
            Cs[row * 36 + col] = v;
        }
        __syncthreads();
        float* red2 = (float*)(alp + 20480);
        {
            int col = tid & 31, seg = tid >> 5;
            float s = 0.f, q = 0.f;
            #pragma unroll
            for (int r8 = 0; r8 < 8; r8++) {
                float v = Cs[(seg * 8 + r8) * 36 + col];
                s += v; q += v * v;
            }
            red2[seg * 32 + col] = s;
            red2[512 + seg * 32 + col] = q;
        }
        __syncthreads();
        if (tid < 32) {
            float s = 0.f, q = 0.f;
            #pragma unroll
            for (int g = 0; g < 16; g++) { s += red2[g * 32 + tid]; q += red2[512 + g * 32 + tid]; }
            int gn = cb + tid;
            if (gn < Nout) { atomicAdd(&osum[gn], s); atomicAdd(&osq[gn], q); }
        }
        __syncthreads();
    } else if (MODE == 1) {
        int row = tid >> 2, quad = tid & 3;
        size_t rbo = (size_t)(rowBase + row) * DD + cb + quad * 8;
        float p1 = 0.f, p2 = 0.f, p3 = 0.f;
        float xr[8];
        #pragma unroll
        for (int j4 = 0; j4 < 2; j4++) {
            int cl = quad * 8 + j4 * 4;
            int gc = cb + cl;
            float4 bj = *(const float4*)(bias + gc);
            float4 xv = *(const float4*)(X + rbo + j4 * 4);
            float4 dv = *(const float4*)(dWi + rbo + j4 * 4);
            float4 lw = *(const float4*)(lawi + gc);
            float q0 = Cs[row * 36 + cl]     + bj.x;
            float q1 = Cs[row * 36 + cl + 1] + bj.y;
            float q2 = Cs[row * 36 + cl + 2] + bj.z;
            float q3 = Cs[row * 36 + cl + 3] + bj.w;
            float n0 = cstep * dv.x, n1 = cstep * dv.y;
            float n2 = cstep * dv.z, n3 = cstep * dv.w;
            float d0 = xv.x - lw.x, d1 = xv.y - lw.y;
            float d2 = xv.z - lw.z, d3 = xv.w - lw.w;
            p1 += d0 * d0 + d1 * d1 + d2 * d2 + d3 * d3;
            p2 += q0 * q0 + q1 * q1 + q2 * q2 + q3 * q3;
            p3 += q0 * n0 + q1 * n1 + q2 * n2 + q3 * n3;
            float4 xo;
            xo.x = xv.x - q0 * hstep + n0;
            xo.y = xv.y - q1 * hstep + n1;
            xo.z = xv.z - q2 * hstep + n2;
            xo.w = xv.w - q3 * hstep + n3;
            *(float4*)(X + rbo + j4 * 4) = xo;
            xr[j4*4+0] = xo.x; xr[j4*4+1] = xo.y; xr[j4*4+2] = xo.z; xr[j4*4+3] = xo.w;
        }
        {
            union { __nv_bfloat16 h[8]; uint4 u; } th;
            #pragma unroll
            for (int e = 0; e < 8; e++) th.h[e] = __float2bfloat16(xr[e]);
            *(uint4*)(g_Xhi + rbo) = th.u;
        }
        float t = -0.5f * hstep * (p1 + p2) + p3;
        t += __shfl_down_sync(0xffffffffu, t, 1);
        t += __shfl_down_sync(0xffffffffu, t, 2);
        if ((lane & 3) == 0) atomicAdd(&V[rowBase + row], t);
        __syncthreads();
    } else {
        if (tid < 128) {
            float v = Cs[tid * 36] + bias[0];
            g_Yv3[rowBase + tid] = v;
            float s = v, q = v * v;
            #pragma unroll
            for (int o = 16; o > 0; o >>= 1) {
                s += __shfl_down_sync(0xffffffffu, s, o);
                q += __shfl_down_sync(0xffffffffu, q, o);
            }
            if ((tid & 31) == 0) { atomicAdd(&g_SC[0], s); atomicAdd(&g_QC[0], q); }
        }
        __syncthreads();
    }
}

// ---------------- single persistent kernel ----------------
extern "C" __global__ void __launch_bounds__(NT, 1)
mega_kernel(const float* __restrict__ x, const float* __restrict__ dW,
            const float* __restrict__ law, const float* __restrict__ tg,
            const float* __restrict__ W1, const float* __restrict__ b1,
            const float* __restrict__ g1, const float* __restrict__ be1,
            const float* __restrict__ W2, const float* __restrict__ b2,
            const float* __restrict__ g2, const float* __restrict__ be2,
            const float* __restrict__ W3, const float* __restrict__ b3,
            const float* __restrict__ Wv1, const float* __restrict__ bv1,
            const float* __restrict__ gv1, const float* __restrict__ bev1,
            const float* __restrict__ Wv2, const float* __restrict__ bv2,
            const float* __restrict__ gv2, const float* __restrict__ bev2,
            const float* __restrict__ Wv3, const float* __restrict__ bv3,
            const float* __restrict__ gv3, const float* __restrict__ bev3,
            float* __restrict__ V)
{
    extern __shared__ char dsm[];
    const int cta = blockIdx.x;
    const int tid = threadIdx.x;
    char* alp = dsm;
    uint32_t sbase = smem_u32(dsm);
    unsigned bar = 0;
    const int rb = (cta & 15) * 128;
    const int cb = (cta >> 4) * 32;

    if (cta == 0) {
        for (int j = tid; j < HP; j += NT) { g_S1[j] = 0.f; g_Q1[j] = 0.f; g_S2[j] = 0.f; g_Q2[j] = 0.f; }
        if (tid == 0) { g_SC[0] = 0.f; g_QC[0] = 0.f; }
    }
    {   // copy X and convert to bf16
        for (int idx = cta * NT + tid; idx < BB * DD / 4; idx += NCTA * NT)
            ((float4*)g_X)[idx] = ((const float4*)x)[idx];
        int idx8 = cta * NT + tid;
        if (idx8 < BB * DD / 8) {
            const float* xp = x + idx8 * 8;
            union { __nv_bfloat16 h[8]; uint4 u; } th;
            #pragma unroll
            for (int e = 0; e < 8; e++) th.h[e] = __float2bfloat16(xp[e]);
            *(uint4*)(g_Xhi + (size_t)idx8 * 8) = th.u;
        }
    }
    {
        float (*ts)[33] = (float (*)[33])alp;
        for (int m = cta; m < 153; m += NCTA) {
            if (m < 50)
                tsplit(W1 + (size_t)m * DD * HH, DD, HH,
                       g_Wt1hi + (size_t)m * HH * DD, g_Wt1lo + (size_t)m * HH * DD, DD, ts);
            else if (m < 100)
                tsplit(W2 + (size_t)(m - 50) * HH * HH, HH, HH,
                       g_Wt2hi + (size_t)(m - 50) * HH * HP, g_Wt2lo + (size_t)(m - 50) * HH * HP, HP, ts);
            else if (m < 150)
                tsplit(W3 + (size_t)(m - 100) * HH * DD, HH, DD,
                       g_Wt3hi + (size_t)(m - 100) * DD * HP, g_Wt3lo + (size_t)(m - 100) * DD * HP, HP, ts);
            else if (m == 150) tsplit(Wv1, DD, HH, g_Wv1hi, g_Wv1lo, DD, ts);
            else if (m == 151) tsplit(Wv2, HH, HH, g_Wv2hi, g_Wv2lo, HP, ts);
            else               tsplit(Wv3, HH, 1,  g_Wv3hi, g_Wv3lo, HP, ts);
        }
    }
    gridbar(bar);

    // v0 L1
    if (cta < 144)
        mma_gemm<0, false, true>(alp, sbase, rb, cb,
            0, DD, 256, 256, g_Xhi, g_Wv1hi, g_Wv1lo, HH, bv1,
            0, 0, 0, 0, g_Y1, HP, g_S1, g_Q1, 0, 0, 0, 0, 0, 0);
    gridbar(bar);
    // v0 L2
    if (cta < 144)
        mma_gemm<0, true, false>(alp, sbase, rb, cb,
            g_Y1, HP, 266, 272, 0, g_Wv2hi, g_Wv2lo, HH, bv2,
            gv1, bev1, g_S1, g_Q1, g_Y2, HP, g_S2, g_Q2, 0, 0, 0, 0, 0, 0);
    gridbar(bar);
    // v0 L3 (N=1)
    if (cta < 16)
        mma_gemm<2, true, false>(alp, sbase, cta * 128, 0,
            g_Y2, HP, 266, 272, 0, g_Wv3hi, g_Wv3lo, 1, bv3,
            gv2, bev2, g_S2, g_Q2, 0, 0, 0, 0, 0, 0, 0, 0, 0, 0);
    else if (cta == 100)
        for (int j = tid; j < HP; j += NT) { g_S1[j] = 0.f; g_Q1[j] = 0.f; }
    gridbar(bar);
    // v0 finalize
    {
        int r = cta * NT + tid;
        if (r < BB) {
            float invB = 1.f / (float)BB;
            float mu  = g_SC[0] * invB;
            float var = g_QC[0] * invB - mu * mu;
            float rstd = rsqrtf(var + EPSBN);
            V[r] = fmaxf(gv3[0] * (g_Yv3[r] - mu) * rstd + bev3[0], 0.f);
        }
        if (cta == 8)
            for (int j = tid; j < HP; j += NT) { g_S2[j] = 0.f; g_Q2[j] = 0.f; }
    }
    gridbar(bar);

    #pragma unroll 1
    for (int i = 0; i < SS; i++) {
        float h  = tg[i + 1] - tg[i];
        float cs = SIGMA_C * sqrtf(h);
        // L1: Xbf16 -> Y1 + S1/Q1
        if (cta < 144)
            mma_gemm<0, false, true>(alp, sbase, rb, cb,
                0, DD, 256, 256, g_Xhi,
                g_Wt1hi + (size_t)i * HH * DD, g_Wt1lo + (size_t)i * HH * DD, HH,
                b1 + (size_t)i * HH, 0, 0, 0, 0,
                g_Y1, HP, g_S1, g_Q1, 0, 0, 0, 0, 0, 0);
        else if (cta == 147)
            for (int j = tid; j < HP; j += NT) { g_S2[j] = 0.f; g_Q2[j] = 0.f; }
        gridbar(bar);
        // L2: BN(Y1) -> Y2 + S2/Q2
        if (cta < 144)
            mma_gemm<0, true, false>(alp, sbase, rb, cb,
                g_Y1, HP, 266, 272, 0,
                g_Wt2hi + (size_t)i * HH * HP, g_Wt2lo + (size_t)i * HH * HP, HH,
                b2 + (size_t)i * HH, g1 + (size_t)i * HH, be1 + (size_t)i * HH, g_S1, g_Q1,
                g_Y2, HP, g_S2, g_Q2, 0, 0, 0, 0, 0, 0);
        gridbar(bar);
        // L3: BN(Y2) -> grad; fused SDE update + X bf16
        if (cta < 128)
            mma_gemm<1, true, false>(alp, sbase, rb, cb,
                g_Y2, HP, 266, 272, 0,
                g_Wt3hi + (size_t)i * DD * HP, g_Wt3lo + (size_t)i * DD * HP, DD,
                b3 + (size_t)i * DD, g2 + (size_t)i * HH, be2 + (size_t)i * HH, g_S2, g_Q2,
                0, 0, 0, 0, h, cs, V, g_X, dW + (size_t)i * BB * DD, law + (size_t)i * DD);
        else if (cta == 144)
            for (int j = tid; j < HP; j += NT) { g_S1[j] = 0.f; g_Q1[j] = 0.f; }
        gridbar(bar);
    }

    if (tid == 0) {
        __threadfence();
        atomicAdd(&g_done, 1u);
        if (cta == 0) {
            while (*(volatile unsigned*)&g_done < NCTA) { }
            g_barctr = 0u;
            __threadfence();
            g_done = 0u;
        }
    }
}

// ---------------- host launcher ----------------
extern "C" void kernel_launch(void* const* d_in, const int* in_sizes, int n_in,
                              void* d_out, int out_size)
{
    cudaFuncSetAttribute((const void*)mega_kernel,
                         cudaFuncAttributeMaxDynamicSharedMemorySize, SMEM_DYN);
    mega_kernel<<<NCTA, NT, SMEM_DYN>>>(
        (const float*)d_in[0], (const float*)d_in[1], (const float*)d_in[2], (const float*)d_in[3],
        (const float*)d_in[4],  (const float*)d_in[5],  (const float*)d_in[6],  (const float*)d_in[7],
        (const float*)d_in[8],  (const float*)d_in[9],  (const float*)d_in[10], (const float*)d_in[11],
        (const float*)d_in[12], (const float*)d_in[13],
        (const float*)d_in[14], (const float*)d_in[15], (const float*)d_in[16], (const float*)d_in[17],
        (const float*)d_in[18], (const float*)d_in[19], (const float*)d_in[20], (const float*)d_in[21],
        (const float*)d_in[22], (const float*)d_in[23], (const float*)d_in[24], (const float*)d_in[25],
        (float*)d_out);
    (void)in_sizes; (void)n_in; (void)out_size;
}

// round 13
// speedup vs baseline: 3.6900x; 1.0273x over previous
#include <cuda_runtime.h>
#include <cuda_bf16.h>
#include <math.h>
#include <stdint.h>

#define NCTA 148
#define NT   512
#define BB   2048
#define DD   256
#define HH   266
#define HP   272
#define SS   50
#define EPSBN 1e-5f
#define SIGMA_C 0.3f
#define KC   96

// smem layout (bytes); row stride 104 halfs (208B)
#define ABUF(b)  ((b) * 26624)          // A: 128 rows x 104 halfs (bf16)
#define BBUF(b)  (53248 + (b) * 13312)  // B: 32 rows x 104 halfs, hi+lo
#define BLO      6656
#define OF_SC    79872
#define OF_SH    81024
#define SMEM_DYN 82176

// ---------------- device scratch ----------------
__device__ float g_X[BB * DD];
__device__ __nv_bfloat16 g_Xhi[BB * DD];
__device__ float g_Y1[BB * HP];
__device__ float g_Y2[BB * HP];
__device__ float g_Yv3[BB];
__device__ __nv_bfloat16 g_Wt1hi[SS * HH * DD], g_Wt1lo[SS * HH * DD];
__device__ __nv_bfloat16 g_Wt2hi[SS * HH * HP], g_Wt2lo[SS * HH * HP];
__device__ __nv_bfloat16 g_Wt3hi[SS * DD * HP], g_Wt3lo[SS * DD * HP];
__device__ __nv_bfloat16 g_Wv1hi[HH * DD], g_Wv1lo[HH * DD];
__device__ __nv_bfloat16 g_Wv2hi[HH * HP], g_Wv2lo[HH * HP];
__device__ __nv_bfloat16 g_Wv3hi[HP],      g_Wv3lo[HP];
__device__ float g_S1[HP], g_Q1[HP], g_S2[HP], g_Q2[HP], g_SC[1], g_QC[1];
__device__ unsigned g_barctr, g_done;

// ---------------- PTX helpers ----------------
__device__ __forceinline__ uint32_t smem_u32(const void* p) {
    uint32_t a;
    asm("{ .reg .u64 t; cvta.to.shared.u64 t, %1; cvt.u32.u64 %0, t; }" : "=r"(a) : "l"(p));
    return a;
}
#define LDSM4(r, addr) \
    asm volatile("ldmatrix.sync.aligned.m8n8.x4.shared.b16 {%0,%1,%2,%3}, [%4];" \
        : "=r"((r)[0]), "=r"((r)[1]), "=r"((r)[2]), "=r"((r)[3]) : "r"(addr))
#define MMA16816(c, a, b0_, b1_) \
    asm volatile("mma.sync.aligned.m16n8k16.row.col.f32.bf16.bf16.f32 " \
        "{%0,%1,%2,%3}, {%4,%5,%6,%7}, {%8,%9}, {%0,%1,%2,%3};" \
        : "+f"((c)[0]), "+f"((c)[1]), "+f"((c)[2]), "+f"((c)[3]) \
        : "r"((a)[0]), "r"((a)[1]), "r"((a)[2]), "r"((a)[3]), "r"(b0_), "r"(b1_))
#define CP16(dst, src) \
    asm volatile("cp.async.ca.shared.global [%0], [%1], 16;" :: "r"(dst), "l"(src) : "memory")
#define CP_COMMIT() asm volatile("cp.async.commit_group;" ::: "memory")
#define CP_WAIT0()  asm volatile("cp.async.wait_group 0;" ::: "memory")

__device__ __forceinline__ void gridbar(unsigned& cnt) {
    __syncthreads();
    if (threadIdx.x == 0) {
        __threadfence();
        atomicAdd(&g_barctr, 1u);
        unsigned target = (++cnt) * NCTA;
        while (*(volatile unsigned*)&g_barctr < target) { }
        __threadfence();
    }
    __syncthreads();
}

// ---------------- transpose + split (weights keep hi+lo) ----------------
__device__ void tsplit(const float* __restrict__ src, int K, int N,
                       __nv_bfloat16* __restrict__ dh, __nv_bfloat16* __restrict__ dl,
                       int ldT, float (*ts)[33]) {
    int ktiles = (ldT + 31) >> 5, ntiles = (N + 31) >> 5;
    for (int t = 0; t < ktiles * ntiles; t++) {
        int kt = t / ntiles, nt = t - kt * ntiles;
        int k0 = kt << 5, n0 = nt << 5;
        __syncthreads();
        #pragma unroll
        for (int s2 = 0; s2 < 2; s2++) {
            int idx = s2 * NT + threadIdx.x;
            int r = idx >> 5, c = idx & 31;
            int k = k0 + r, n = n0 + c;
            ts[r][c] = (k < K && n < N) ? src[(size_t)k * N + n] : 0.f;
        }
        __syncthreads();
        #pragma unroll
        for (int s2 = 0; s2 < 2; s2++) {
            int idx = s2 * NT + threadIdx.x;
            int rr = idx >> 5, cc = idx & 31;
            int n = n0 + rr, k = k0 + cc;
            if (n < N && k < ldT) {
                float v = ts[cc][rr];
                __nv_bfloat16 hb = __float2bfloat16(v);
                dh[(size_t)n * ldT + k] = hb;
                dl[(size_t)n * ldT + k] = __float2bfloat16(v - __bfloat162float(hb));
            }
        }
    }
}

// ---------------- HMMA GEMM phase (128x32 tile, 16 warps, pipelined) --------
// A single bf16; B split hi/lo (2-term). MODE 0: C + stats. MODE 1: SDE. MODE 2: N=1.
template<int MODE, bool BN, bool ASPLIT>
__device__ __noinline__ void mma_gemm(char* alp, uint32_t sbase,
    int rowBase, int cb,
    const float* __restrict__ A, int ldA, int K, int Ksteps,
    const __nv_bfloat16* __restrict__ Ahs,
    const __nv_bfloat16* __restrict__ Bh, const __nv_bfloat16* __restrict__ Bl, int Nout,
    const float* __restrict__ bias,
    const float* __restrict__ bng, const float* __restrict__ bnb,
    const float* __restrict__ ssum, const float* __restrict__ ssq,
    float* __restrict__ C, int ldc, float* osum, float* osq,
    float hstep, float cstep, float* __restrict__ V,
    float* __restrict__ X, const float* __restrict__ dWi, const float* __restrict__ lawi)
{
    const int tid = threadIdx.x;
    const int lane = tid & 31;
    const int warp = tid >> 5;
    const int mr = warp & 7;    // rows mr*16..+15
    const int nc = warp >> 3;   // cols nc*16..+15
    float* scK = (float*)(alp + OF_SC);
    float* shK = (float*)(alp + OF_SH);

    const int nch = (Ksteps + KC - 1) / KC;
    float fa[24];

    auto ldAreg = [&](int ch) {
        const int k0 = ch * KC;
        #pragma unroll
        for (int it = 0; it < 3; it++) {
            int idx = it * NT + tid;
            int row = idx / 12, kg = idx - row * 12;
            int gk = k0 + kg * 8;
            if (gk < Ksteps) {
                const float* ap = A + (size_t)(rowBase + row) * ldA + gk;
                float4 v0 = *(const float4*)ap;
                float4 v1 = *(const float4*)(ap + 4);
                fa[it*8+0] = v0.x; fa[it*8+1] = v0.y; fa[it*8+2] = v0.z; fa[it*8+3] = v0.w;
                fa[it*8+4] = v1.x; fa[it*8+5] = v1.y; fa[it*8+6] = v1.z; fa[it*8+7] = v1.w;
            } else {
                #pragma unroll
                for (int e = 0; e < 8; e++) fa[it*8+e] = 0.f;
            }
        }
    };
    auto stA = [&](int ch, int buf) {
        const int k0 = ch * KC;
        #pragma unroll
        for (int it = 0; it < 3; it++) {
            int idx = it * NT + tid;
            int row = idx / 12, kg = idx - row * 12;
            int gk = k0 + kg * 8;
            union { __nv_bfloat16 h[8]; uint4 u; } th;
            if (gk < Ksteps) {
                #pragma unroll
                for (int e = 0; e < 8; e++) {
                    float v = fa[it*8+e];
                    if (BN) v = fmaxf(fmaf(v, scK[gk + e], shK[gk + e]), 0.f);
                    th.h[e] = __float2bfloat16(v);
                }
            } else th.u = make_uint4(0, 0, 0, 0);
            uint32_t off = (uint32_t)(row * 104 + kg * 8) * 2u;
            *(uint4*)(alp + ABUF(buf) + off) = th.u;
        }
    };
    auto cpA = [&](int ch, int buf) {   // ASPLIT: bf16 A direct (Ksteps=256 exact)
        const int k0 = ch * KC;
        #pragma unroll
        for (int it = 0; it < 3; it++) {
            int idx = it * NT + tid;
            int row = idx / 12, kg = idx - row * 12;
            int gk = k0 + kg * 8;
            if (gk < Ksteps) {
                uint32_t off = (uint32_t)(row * 104 + kg * 8) * 2u;
                CP16(sbase + ABUF(buf) + off, Ahs + (size_t)(rowBase + row) * ldA + gk);
            }
        }
    };
    auto cpB = [&](int ch, int buf) {
        if (tid < 384) {
            const int k0 = ch * KC;
            int row = tid / 12, kg = tid - row * 12;
            int gk = k0 + kg * 8;
            int n = cb + row;
            uint32_t off = (uint32_t)(row * 104 + kg * 8) * 2u;
            uint32_t d0 = sbase + BBUF(buf) + off;
            if (gk < Ksteps && n < Nout) {
                CP16(d0, Bh + (size_t)n * Ksteps + gk);
                CP16(d0 + BLO, Bl + (size_t)n * Ksteps + gk);
            } else {
                uint4 z = make_uint4(0, 0, 0, 0);
                *(uint4*)(alp + BBUF(buf) + off) = z;
                *(uint4*)(alp + BBUF(buf) + BLO + off) = z;
            }
        }
    };

    float acc[2][4] = {};
    uint32_t ahf[2][4], bhf[2][4], blf[2][4];
    const uint32_t aoOff = 2u * (uint32_t)((mr * 16 + (lane & 15)) * 104 + ((lane >> 4) << 3));
    const uint32_t boOff = 2u * (uint32_t)((nc * 16 + (lane & 7) + ((lane >> 3) & 1) * 8) * 104
                                           + ((lane >> 4) << 3));

    // prologue: issue global loads first, BN table overlaps them
    if (ASPLIT) { cpA(0, 0); cpB(0, 0); CP_COMMIT(); }
    else        { ldAreg(0); cpB(0, 0); CP_COMMIT(); }
    if (BN) {
        const float invB = 1.f / (float)BB;
        for (int k = tid; k < HP; k += NT) {
            if (k < K) {
                float mu  = ssum[k] * invB;
                float var = ssq[k] * invB - mu * mu;
                float rstd = rsqrtf(var + EPSBN);
                float sc = bng[k] * rstd;
                scK[k] = sc; shK[k] = bnb[k] - mu * sc;
            } else { scK[k] = 0.f; shK[k] = 0.f; }
        }
    }
    __syncthreads();
    if (!ASPLIT) stA(0, 0);
    CP_WAIT0();
    __syncthreads();

    for (int ch = 0; ch < nch; ch++) {
        const int buf = ch & 1;
        const bool more = (ch + 1 < nch);
        if (more) {
            if (ASPLIT) cpA(ch + 1, buf ^ 1);
            else        ldAreg(ch + 1);
            cpB(ch + 1, buf ^ 1); CP_COMMIT();
        }

        int ns = (Ksteps - ch * KC) >> 4; if (ns > KC / 16) ns = KC / 16;
        uint32_t ao = sbase + ABUF(buf) + aoOff;
        uint32_t bo = sbase + BBUF(buf) + boOff;
        LDSM4(ahf[0], ao); LDSM4(bhf[0], bo); LDSM4(blf[0], bo + BLO);
        for (int kk = 0; kk < ns; kk++) {
            const int p = kk & 1;
            if (kk + 1 < ns) {
                uint32_t a2 = ao + (kk + 1) * 32, b2 = bo + (kk + 1) * 32;
                LDSM4(ahf[p ^ 1], a2); LDSM4(bhf[p ^ 1], b2); LDSM4(blf[p ^ 1], b2 + BLO);
            }
            #pragma unroll
            for (int t = 0; t < 2; t++) {
                MMA16816(acc[t], ahf[p], bhf[p][t], bhf[p][t + 2]);
                MMA16816(acc[t], ahf[p], blf[p][t], blf[p][t + 2]);
            }
        }

        if (more && !ASPLIT) stA(ch + 1, buf ^ 1);
        CP_WAIT0();
        __syncthreads();
    }

    // ---- fragments -> Cs [128][36] raw (aliases A buffers) ----
    float* Cs = (float*)alp;
    {
        int r0 = mr * 16 + (lane >> 2);
        #pragma unroll
        for (int t = 0; t < 2; t++) {
            int cl = nc * 16 + t * 8 + (lane & 3) * 2;
            Cs[r0 * 36 + cl]           = acc[t][0];
            Cs[r0 * 36 + cl + 1]       = acc[t][1];
            Cs[(r0 + 8) * 36 + cl]     = acc[t][2];
            Cs[(r0 + 8) * 36 + cl + 1] = acc[t][3];
        }
    }
    __syncthreads();

    if (MODE == 0) {
        float* red2 = (float*)(alp + 20480);
        // pass A: write C (biased); pass B: raw partial sums — one sync region
        #pragma unroll
        for (int it = 0; it < 8; it++) {
            int idx = it * NT + tid;
            int row = idx >> 5, col = idx & 31;
            int gn = cb + col;
            if (gn < Nout)
                C[(size_t)(rowBase + row) * ldc + gn] = Cs[row * 36 + col] + bias[gn];
        }
        {
            int col = tid & 31, seg = tid >> 5;
            float s = 0.f, q = 0.f;
            #pragma unroll
            for (int r8 = 0; r8 < 8; r8++) {
                float v = Cs[(seg * 8 + r8) * 36 + col];
                s += v; q += v * v;
            }
            red2[seg * 32 + col] = s;
            red2[512 + seg * 32 + col] = q;
        }
        __syncthreads();
        if (tid < 32) {
            float s = 0.f, q = 0.f;
            #pragma unroll
            for (int g = 0; g < 16; g++) { s += red2[g * 32 + tid]; q += red2[512 + g * 32 + tid]; }
            int gn = cb + tid;
            if (gn < Nout) {
                float b = bias[gn];
                atomicAdd(&osum[gn], s + 128.f * b);
                atomicAdd(&osq[gn], q + 2.f * b * s + 128.f * b * b);
            }
        }
        __syncthreads();
    } else if (MODE == 1) {
        int row = tid >> 2, quad = tid & 3;
        size_t rbo = (size_t)(rowBase + row) * DD + cb + quad * 8;
        float p1 = 0.f, p2 = 0.f, p3 = 0.f;
        float xr[8];
        #pragma unroll
        for (int j4 = 0; j4 < 2; j4++) {
            int cl = quad * 8 + j4 * 4;
            int gc = cb + cl;
            float4 bj = *(const float4*)(bias + gc);
            float4 xv = *(const float4*)(X + rbo + j4 * 4);
            float4 dv = *(const float4*)(dWi + rbo + j4 * 4);
            float4 lw = *(const float4*)(lawi + gc);
            float q0 = Cs[row * 36 + cl]     + bj.x;
            float q1 = Cs[row * 36 + cl + 1] + bj.y;
            float q2 = Cs[row * 36 + cl + 2] + bj.z;
            float q3 = Cs[row * 36 + cl + 3] + bj.w;
            float n0 = cstep * dv.x, n1 = cstep * dv.y;
            float n2 = cstep * dv.z, n3 = cstep * dv.w;
            float d0 = xv.x - lw.x, d1 = xv.y - lw.y;
            float d2 = xv.z - lw.z, d3 = xv.w - lw.w;
            p1 += d0 * d0 + d1 * d1 + d2 * d2 + d3 * d3;
            p2 += q0 * q0 + q1 * q1 + q2 * q2 + q3 * q3;
            p3 += q0 * n0 + q1 * n1 + q2 * n2 + q3 * n3;
            float4 xo;
            xo.x = xv.x - q0 * hstep + n0;
            xo.y = xv.y - q1 * hstep + n1;
            xo.z = xv.z - q2 * hstep + n2;
            xo.w = xv.w - q3 * hstep + n3;
            *(float4*)(X + rbo + j4 * 4) = xo;
            xr[j4*4+0] = xo.x; xr[j4*4+1] = xo.y; xr[j4*4+2] = xo.z; xr[j4*4+3] = xo.w;
        }
        {
            union { __nv_bfloat16 h[8]; uint4 u; } th;
            #pragma unroll
            for (int e = 0; e < 8; e++) th.h[e] = __float2bfloat16(xr[e]);
            *(uint4*)(g_Xhi + rbo) = th.u;
        }
        float t = -0.5f * hstep * (p1 + p2) + p3;
        t += __shfl_down_sync(0xffffffffu, t, 1);
        t += __shfl_down_sync(0xffffffffu, t, 2);
        if ((lane & 3) == 0) atomicAdd(&V[rowBase + row], t);
        __syncthreads();
    } else {
        if (tid < 128) {
            float v = Cs[tid * 36] + bias[0];
            g_Yv3[rowBase + tid] = v;
            float s = v, q = v * v;
            #pragma unroll
            for (int o = 16; o > 0; o >>= 1) {
                s += __shfl_down_sync(0xffffffffu, s, o);
                q += __shfl_down_sync(0xffffffffu, q, o);
            }
            if ((tid & 31) == 0) { atomicAdd(&g_SC[0], s); atomicAdd(&g_QC[0], q); }
        }
        __syncthreads();
    }
}

// ---------------- single persistent kernel ----------------
extern "C" __global__ void __launch_bounds__(NT, 1)
mega_kernel(const float* __restrict__ x, const float* __restrict__ dW,
            const float* __restrict__ law, const float* __restrict__ tg,
            const float* __restrict__ W1, const float* __restrict__ b1,
            const float* __restrict__ g1, const float* __restrict__ be1,
            const float* __restrict__ W2, const float* __restrict__ b2,
            const float* __restrict__ g2, const float* __restrict__ be2,
            const float* __restrict__ W3, const float* __restrict__ b3,
            const float* __restrict__ Wv1, const float* __restrict__ bv1,
            const float* __restrict__ gv1, const float* __restrict__ bev1,
            const float* __restrict__ Wv2, const float* __restrict__ bv2,
            const float* __restrict__ gv2, const float* __restrict__ bev2,
            const float* __restrict__ Wv3, const float* __restrict__ bv3,
            const float* __restrict__ gv3, const float* __restrict__ bev3,
            float* __restrict__ V)
{
    extern __shared__ char dsm[];
    const int cta = blockIdx.x;
    const int tid = threadIdx.x;
    char* alp = dsm;
    uint32_t sbase = smem_u32(dsm);
    unsigned bar = 0;
    const int rb = (cta & 15) * 128;
    const int cb = (cta >> 4) * 32;

    if (cta == 0) {
        for (int j = tid; j < HP; j += NT) { g_S1[j] = 0.f; g_Q1[j] = 0.f; g_S2[j] = 0.f; g_Q2[j] = 0.f; }
        if (tid == 0) { g_SC[0] = 0.f; g_QC[0] = 0.f; }
    }
    {   // copy X and convert to bf16
        for (int idx = cta * NT + tid; idx < BB * DD / 4; idx += NCTA * NT)
            ((float4*)g_X)[idx] = ((const float4*)x)[idx];
        int idx8 = cta * NT + tid;
        if (idx8 < BB * DD / 8) {
            const float* xp = x + idx8 * 8;
            union { __nv_bfloat16 h[8]; uint4 u; } th;
            #pragma unroll
            for (int e = 0; e < 8; e++) th.h[e] = __float2bfloat16(xp[e]);
            *(uint4*)(g_Xhi + (size_t)idx8 * 8) = th.u;
        }
    }
    {
        float (*ts)[33] = (float (*)[33])alp;
        for (int m = cta; m < 153; m += NCTA) {
            if (m < 50)
                tsplit(W1 + (size_t)m * DD * HH, DD, HH,
                       g_Wt1hi + (size_t)m * HH * DD, g_Wt1lo + (size_t)m * HH * DD, DD, ts);
            else if (m < 100)
                tsplit(W2 + (size_t)(m - 50) * HH * HH, HH, HH,
                       g_Wt2hi + (size_t)(m - 50) * HH * HP, g_Wt2lo + (size_t)(m - 50) * HH * HP, HP, ts);
            else if (m < 150)
                tsplit(W3 + (size_t)(m - 100) * HH * DD, HH, DD,
                       g_Wt3hi + (size_t)(m - 100) * DD * HP, g_Wt3lo + (size_t)(m - 100) * DD * HP, HP, ts);
            else if (m == 150) tsplit(Wv1, DD, HH, g_Wv1hi, g_Wv1lo, DD, ts);
            else if (m == 151) tsplit(Wv2, HH, HH, g_Wv2hi, g_Wv2lo, HP, ts);
            else               tsplit(Wv3, HH, 1,  g_Wv3hi, g_Wv3lo, HP, ts);
        }
    }
    gridbar(bar);

    // v0 L1
    if (cta < 144)
        mma_gemm<0, false, true>(alp, sbase, rb, cb,
            0, DD, 256, 256, g_Xhi, g_Wv1hi, g_Wv1lo, HH, bv1,
            0, 0, 0, 0, g_Y1, HP, g_S1, g_Q1, 0, 0, 0, 0, 0, 0);
    gridbar(bar);
    // v0 L2
    if (cta < 144)
        mma_gemm<0, true, false>(alp, sbase, rb, cb,
            g_Y1, HP, 266, 272, 0, g_Wv2hi, g_Wv2lo, HH, bv2,
            gv1, bev1, g_S1, g_Q1, g_Y2, HP, g_S2, g_Q2, 0, 0, 0, 0, 0, 0);
    gridbar(bar);
    // v0 L3 (N=1)
    if (cta < 16)
        mma_gemm<2, true, false>(alp, sbase, cta * 128, 0,
            g_Y2, HP, 266, 272, 0, g_Wv3hi, g_Wv3lo, 1, bv3,
            gv2, bev2, g_S2, g_Q2, 0, 0, 0, 0, 0, 0, 0, 0, 0, 0);
    else if (cta == 100)
        for (int j = tid; j < HP; j += NT) { g_S1[j] = 0.f; g_Q1[j] = 0.f; }
    gridbar(bar);
    // v0 finalize
    {
        int r = cta * NT + tid;
        if (r < BB) {
            float invB = 1.f / (float)BB;
            float mu  = g_SC[0] * invB;
            float var = g_QC[0] * invB - mu * mu;
            float rstd = rsqrtf(var + EPSBN);
            V[r] = fmaxf(gv3[0] * (g_Yv3[r] - mu) * rstd + bev3[0], 0.f);
        }
        if (cta == 8)
            for (int j = tid; j < HP; j += NT) { g_S2[j] = 0.f; g_Q2[j] = 0.f; }
    }
    gridbar(bar);

    #pragma unroll 1
    for (int i = 0; i < SS; i++) {
        float h  = tg[i + 1] - tg[i];
        float cs = SIGMA_C * sqrtf(h);
        // L1: Xbf16 -> Y1 + S1/Q1
        if (cta < 144)
            mma_gemm<0, false, true>(alp, sbase, rb, cb,
                0, DD, 256, 256, g_Xhi,
                g_Wt1hi + (size_t)i * HH * DD, g_Wt1lo + (size_t)i * HH * DD, HH,
                b1 + (size_t)i * HH, 0, 0, 0, 0,
                g_Y1, HP, g_S1, g_Q1, 0, 0, 0, 0, 0, 0);
        else if (cta == 147)
            for (int j = tid; j < HP; j += NT) { g_S2[j] = 0.f; g_Q2[j] = 0.f; }
        gridbar(bar);
        // L2: BN(Y1) -> Y2 + S2/Q2
        if (cta < 144)
            mma_gemm<0, true, false>(alp, sbase, rb, cb,
                g_Y1, HP, 266, 272, 0,
                g_Wt2hi + (size_t)i * HH * HP, g_Wt2lo + (size_t)i * HH * HP, HH,
                b2 + (size_t)i * HH, g1 + (size_t)i * HH, be1 + (size_t)i * HH, g_S1, g_Q1,
                g_Y2, HP, g_S2, g_Q2, 0, 0, 0, 0, 0, 0);
        gridbar(bar);
        // L3: BN(Y2) -> grad; fused SDE update + X bf16
        if (cta < 128)
            mma_gemm<1, true, false>(alp, sbase, rb, cb,
                g_Y2, HP, 266, 272, 0,
                g_Wt3hi + (size_t)i * DD * HP, g_Wt3lo + (size_t)i * DD * HP, DD,
                b3 + (size_t)i * DD, g2 + (size_t)i * HH, be2 + (size_t)i * HH, g_S2, g_Q2,
                0, 0, 0, 0, h, cs, V, g_X, dW + (size_t)i * BB * DD, law + (size_t)i * DD);
        else if (cta == 144)
            for (int j = tid; j < HP; j += NT) { g_S1[j] = 0.f; g_Q1[j] = 0.f; }
        gridbar(bar);
    }

    if (tid == 0) {
        __threadfence();
        atomicAdd(&g_done, 1u);
        if (cta == 0) {
            while (*(volatile unsigned*)&g_done < NCTA) { }
            g_barctr = 0u;
            __threadfence();
            g_done = 0u;
        }
    }
}

// ---------------- host launcher ----------------
extern "C" void kernel_launch(void* const* d_in, const int* in_sizes, int n_in,
                              void* d_out, int out_size)
{
    cudaFuncSetAttribute((const void*)mega_kernel,
                         cudaFuncAttributeMaxDynamicSharedMemorySize, SMEM_DYN);
    mega_kernel<<<NCTA, NT, SMEM_DYN>>>(
        (const float*)d_in[0], (const float*)d_in[1], (const float*)d_in[2], (const float*)d_in[3],
        (const float*)d_in[4],  (const float*)d_in[5],  (const float*)d_in[6],  (const float*)d_in[7],
        (const float*)d_in[8],  (const float*)d_in[9],  (const float*)d_in[10], (const float*)d_in[11],
        (const float*)d_in[12], (const float*)d_in[13],
        (const float*)d_in[14], (const float*)d_in[15], (const float*)d_in[16], (const float*)d_in[17],
        (const float*)d_in[18], (const float*)d_in[19], (const float*)d_in[20], (const float*)d_in[21],
        (const float*)d_in[22], (const float*)d_in[23], (const float*)d_in[24], (const float*)d_in[25],
        (float*)d_out);
    (void)in_sizes; (void)n_in; (void)out_size;
}